// round 1
// baseline (speedup 1.0000x reference)
#include <cuda_runtime.h>

#define Bx   8
#define Nn   200
#define Cc   32
#define OUTC 64
#define NN   (Nn*Nn)
#define ROWS (Bx*NN)   // 320000

// ---- static scratch (no allocations allowed) ----
__device__ float g_d0[Nn];
__device__ float g_d1[Nn];
__device__ float g_A[Nn*Nn];          // A[e*Nn+b] = L[b,e]  (L transposed)
__device__ float g_Wr[96*192];        // Wr[k1*32+c][k2*64+o]
__device__ float g_Y1[ROWS*Cc];       // 40.96 MB
__device__ float g_Y2[ROWS*Cc];       // 40.96 MB
__device__ float g_G[(size_t)ROWS*192]; // 245.76 MB : G[row][k2*64+o]
__device__ float g_H[(size_t)ROWS*OUTC]; // 81.92 MB

// ---------------------------------------------------------------------------
// degree sums (faithful to reference: zero diag, col-sums -> d0, row-sums -> d1)
__global__ void k_deg(const float* __restrict__ adj) {
    int i = threadIdx.x;
    if (i < Nn) {
        float cs = 0.f, rs = 0.f;
        for (int b = 0; b < Nn; b++) if (b != i) cs += adj[b*Nn + i];
        for (int e = 0; e < Nn; e++) if (e != i) rs += adj[i*Nn + e];
        g_d0[i] = (cs > 0.f) ? (1.0f / sqrtf(cs)) : 0.f;
        g_d1[i] = (rs > 0.f) ? (1.0f / sqrtf(rs)) : 0.f;
    }
}

// A[e][b] = L[b][e] = d0[b]*adj[b][e]*d1[e], diag zero
__global__ void k_buildA(const float* __restrict__ adj) {
    int idx = blockIdx.x * blockDim.x + threadIdx.x;
    if (idx < NN) {
        int e = idx / Nn, b = idx % Nn;
        float v = (b == e) ? 0.f : g_d0[b] * adj[b*Nn + e] * g_d1[e];
        g_A[e*Nn + b] = v;
    }
}

// rearranged weight: Wr[(k1*32+c)*192 + k2*64 + o] = W[o*288 + (k1*3+k2)*32 + c]
__global__ void k_wr(const float* __restrict__ w) {
    int idx = blockIdx.x * blockDim.x + threadIdx.x;
    if (idx < 96*192) {
        int row = idx / 192, col = idx % 192;
        int k1 = row / 32, c = row % 32;
        int k2 = col / 64, o = col % 64;
        g_Wr[idx] = w[o*288 + (k1*3 + k2)*32 + c];
    }
}

// ---------------------------------------------------------------------------
// left apply: Z[b] = alpha * A @ M[b] + beta * C[b]   (M viewed [200 x 6400])
// mode 0: Y1 = A@X ;  mode 1: Y2 = 2*A@Y1 - X
__global__ __launch_bounds__(256) void k_left(const float* __restrict__ X, int mode) {
    const float* M; const float* Cin = nullptr; float* Z; float alpha, beta = 0.f;
    if (mode == 0) { M = X;    Z = g_Y1; alpha = 1.f; }
    else           { M = g_Y1; Cin = X; Z = g_Y2; alpha = 2.f; beta = -1.f; }

    int bb = blockIdx.z;
    size_t base = (size_t)bb * Nn * 6400;
    const float* Mb = M + base;
    float* Zb = Z + base;
    const float* Cb = Cin ? Cin + base : nullptr;

    int row0 = blockIdx.y * 64;
    int col0 = blockIdx.x * 64;

    __shared__ float As[16][68];   // As[k][i]
    __shared__ float Bs[16][64];   // Bs[k][c]
    float acc[4][4] = {};
    int tid = threadIdx.x;
    int tx = tid & 15, ty = tid >> 4;

    for (int k0 = 0; k0 < Nn; k0 += 16) {
        #pragma unroll
        for (int l = 0; l < 4; l++) {
            int e = tid + l*256;
            int i = e >> 4, k = e & 15;
            int gr = row0 + i, gk = k0 + k;
            As[k][i] = (gr < Nn && gk < Nn) ? g_A[gr*Nn + gk] : 0.f;
        }
        #pragma unroll
        for (int l = 0; l < 4; l++) {
            int e = tid + l*256;
            int k = e >> 6, c = e & 63;
            int gp = k0 + k;
            Bs[k][c] = (gp < Nn) ? Mb[(size_t)gp*6400 + col0 + c] : 0.f;
        }
        __syncthreads();
        #pragma unroll
        for (int k = 0; k < 16; k++) {
            float a[4], b[4];
            *reinterpret_cast<float4*>(a) = *reinterpret_cast<const float4*>(&As[k][ty*4]);
            *reinterpret_cast<float4*>(b) = *reinterpret_cast<const float4*>(&Bs[k][tx*4]);
            #pragma unroll
            for (int ii = 0; ii < 4; ii++)
                #pragma unroll
                for (int jj = 0; jj < 4; jj++) acc[ii][jj] += a[ii]*b[jj];
        }
        __syncthreads();
    }
    #pragma unroll
    for (int ii = 0; ii < 4; ii++) {
        int gr = row0 + ty*4 + ii;
        if (gr < Nn) {
            #pragma unroll
            for (int jj = 0; jj < 4; jj++) {
                int gc = col0 + tx*4 + jj;
                size_t idx = (size_t)gr*6400 + gc;
                float v = alpha * acc[ii][jj];
                if (Cb) v += beta * Cb[idx];
                Zb[idx] = v;
            }
        }
    }
}

// ---------------------------------------------------------------------------
// channel mix: G[row][k2*64+o] = sum_{k1,c} srcs_{k1}[row][c] * Wr[k1*32+c][k2*64+o]
__global__ __launch_bounds__(256) void k_mix(const float* __restrict__ X) {
    int row0 = blockIdx.y * 64;
    int col0 = blockIdx.x * 64;   // blockIdx.x == k2

    __shared__ float As[32][68];  // As[c][r]
    __shared__ float Bs[32][64];  // Bs[c][o]
    float acc[4][4] = {};
    int tid = threadIdx.x, tx = tid & 15, ty = tid >> 4;

    const float* srcs[3] = { X, g_Y1, g_Y2 };
    for (int s = 0; s < 3; s++) {
        const float* src = srcs[s];
        #pragma unroll
        for (int l = 0; l < 8; l++) {
            int e = tid + l*256;
            int r = e >> 5, c = e & 31;
            As[c][r] = src[(size_t)(row0 + r)*32 + c];
        }
        #pragma unroll
        for (int l = 0; l < 8; l++) {
            int e = tid + l*256;
            int k = e >> 6, o = e & 63;
            Bs[k][o] = g_Wr[(s*32 + k)*192 + col0 + o];
        }
        __syncthreads();
        #pragma unroll
        for (int k = 0; k < 32; k++) {
            float a[4], b[4];
            *reinterpret_cast<float4*>(a) = *reinterpret_cast<const float4*>(&As[k][ty*4]);
            *reinterpret_cast<float4*>(b) = *reinterpret_cast<const float4*>(&Bs[k][tx*4]);
            #pragma unroll
            for (int ii = 0; ii < 4; ii++)
                #pragma unroll
                for (int jj = 0; jj < 4; jj++) acc[ii][jj] += a[ii]*b[jj];
        }
        __syncthreads();
    }
    #pragma unroll
    for (int ii = 0; ii < 4; ii++)
        #pragma unroll
        for (int jj = 0; jj < 4; jj++)
            g_G[(size_t)(row0 + ty*4 + ii)*192 + col0 + tx*4 + jj] = acc[ii][jj];
}

// ---------------------------------------------------------------------------
// H[bi][j][o] = G1[bi][j][o] + 2 * sum_q G2[bi][q][o] * A[q][j]
__global__ __launch_bounds__(256) void k_rightH() {
    int bi = blockIdx.x;            // 0..1599 = b*200+i
    int j0 = blockIdx.y * 64;
    __shared__ float As[16][68];    // As[k][j] = A[(q0+k)*Nn + j0+j]
    __shared__ float Gs[16][64];    // Gs[k][o]
    float acc[4][4] = {};
    int tid = threadIdx.x, tx = tid & 15, ty = tid >> 4;
    size_t gbase = (size_t)bi * 200 * 192;

    for (int q0 = 0; q0 < Nn; q0 += 16) {
        #pragma unroll
        for (int l = 0; l < 4; l++) {
            int e = tid + l*256;
            int k = e >> 6, j = e & 63;
            int gq = q0 + k, gj = j0 + j;
            As[k][j] = (gq < Nn && gj < Nn) ? g_A[gq*Nn + gj] : 0.f;
        }
        #pragma unroll
        for (int l = 0; l < 4; l++) {
            int e = tid + l*256;
            int k = e >> 6, o = e & 63;
            int gq = q0 + k;
            Gs[k][o] = (gq < Nn) ? g_G[gbase + (size_t)gq*192 + 128 + o] : 0.f;
        }
        __syncthreads();
        #pragma unroll
        for (int k = 0; k < 16; k++) {
            float a[4], b[4];
            *reinterpret_cast<float4*>(a) = *reinterpret_cast<const float4*>(&As[k][ty*4]);
            *reinterpret_cast<float4*>(b) = *reinterpret_cast<const float4*>(&Gs[k][tx*4]);
            #pragma unroll
            for (int ii = 0; ii < 4; ii++)
                #pragma unroll
                for (int jj = 0; jj < 4; jj++) acc[ii][jj] += a[ii]*b[jj];
        }
        __syncthreads();
    }
    #pragma unroll
    for (int ii = 0; ii < 4; ii++) {
        int gj = j0 + ty*4 + ii;
        if (gj < Nn) {
            #pragma unroll
            for (int jj = 0; jj < 4; jj++) {
                int o = tx*4 + jj;
                g_H[((size_t)bi*200 + gj)*64 + o] =
                    g_G[gbase + (size_t)gj*192 + 64 + o] + 2.f * acc[ii][jj];
            }
        }
    }
}

// out[bi][j][o] = bias[o] + G0[bi][j][o] - G2[bi][j][o] + sum_q H[bi][q][o]*A[q][j]
__global__ __launch_bounds__(256) void k_rightOut(const float* __restrict__ bias,
                                                  float* __restrict__ out) {
    int bi = blockIdx.x;
    int j0 = blockIdx.y * 64;
    __shared__ float As[16][68];
    __shared__ float Gs[16][64];
    float acc[4][4] = {};
    int tid = threadIdx.x, tx = tid & 15, ty = tid >> 4;
    size_t gbase = (size_t)bi * 200 * 192;
    size_t hbase = (size_t)bi * 200 * 64;

    for (int q0 = 0; q0 < Nn; q0 += 16) {
        #pragma unroll
        for (int l = 0; l < 4; l++) {
            int e = tid + l*256;
            int k = e >> 6, j = e & 63;
            int gq = q0 + k, gj = j0 + j;
            As[k][j] = (gq < Nn && gj < Nn) ? g_A[gq*Nn + gj] : 0.f;
        }
        #pragma unroll
        for (int l = 0; l < 4; l++) {
            int e = tid + l*256;
            int k = e >> 6, o = e & 63;
            int gq = q0 + k;
            Gs[k][o] = (gq < Nn) ? g_H[hbase + (size_t)gq*64 + o] : 0.f;
        }
        __syncthreads();
        #pragma unroll
        for (int k = 0; k < 16; k++) {
            float a[4], b[4];
            *reinterpret_cast<float4*>(a) = *reinterpret_cast<const float4*>(&As[k][ty*4]);
            *reinterpret_cast<float4*>(b) = *reinterpret_cast<const float4*>(&Gs[k][tx*4]);
            #pragma unroll
            for (int ii = 0; ii < 4; ii++)
                #pragma unroll
                for (int jj = 0; jj < 4; jj++) acc[ii][jj] += a[ii]*b[jj];
        }
        __syncthreads();
    }
    #pragma unroll
    for (int ii = 0; ii < 4; ii++) {
        int gj = j0 + ty*4 + ii;
        if (gj < Nn) {
            #pragma unroll
            for (int jj = 0; jj < 4; jj++) {
                int o = tx*4 + jj;
                out[((size_t)bi*200 + gj)*64 + o] =
                    bias[o] + g_G[gbase + (size_t)gj*192 + o]
                            - g_G[gbase + (size_t)gj*192 + 128 + o]
                            + acc[ii][jj];
            }
        }
    }
}

// ---------------------------------------------------------------------------
extern "C" void kernel_launch(void* const* d_in, const int* in_sizes, int n_in,
                              void* d_out, int out_size) {
    const float* x    = (const float*)d_in[0];   // [8,200,200,32]
    const float* adj  = (const float*)d_in[1];   // [200,200]
    const float* w    = (const float*)d_in[2];   // [64,288]
    const float* bias = (const float*)d_in[3];   // [64]
    float* out = (float*)d_out;                  // [8,200,200,64]

    k_deg<<<1, 256>>>(adj);
    k_buildA<<<(NN + 255)/256, 256>>>(adj);
    k_wr<<<(96*192 + 255)/256, 256>>>(w);

    dim3 gl(100, 4, Bx);                 // cols 6400/64, rows 200/64 ceil, batch
    k_left<<<gl, 256>>>(x, 0);           // Y1 = A @ X
    k_left<<<gl, 256>>>(x, 1);           // Y2 = 2*A@Y1 - X

    k_mix<<<dim3(3, ROWS/64), 256>>>(x); // G[row][192]

    dim3 gr(Bx*Nn, 4);                   // 1600 (b,i) batches x 4 j-tiles
    k_rightH<<<gr, 256>>>();             // H = G1 + 2*(G2 . A)
    k_rightOut<<<gr, 256>>>(bias, out);  // out = (G0-G2) + H.A + bias
}

// round 2
// speedup vs baseline: 1.6000x; 1.6000x over previous
#include <cuda_runtime.h>
#include <cuda_bf16.h>
#include <cstdint>

#define Nn   200
#define NP   256          // padded node dim
#define Bx   8
#define NCH  6400         // 200*32 flattened (j,c) for left GEMM
#define GW   192          // G row width (3 * 64)

typedef __nv_bfloat16 bf16;
typedef __nv_bfloat162 bf162;

// ---------------- static scratch ----------------
__device__ float g_d0[NP];
__device__ float g_d1[NP];
__device__ float g_Afp[NP*NP];      // A[e][b] = L[b,e], padded zeros
__device__ float g_Rtf[NP*NP];      // Rt[j][q] = L[j,q]
__device__ float g_R2f[NP*NP];      // 2 * Rt @ Rt
__device__ bf16  gA_h[NP*NP],  gA_l[NP*NP];
__device__ bf16  gRt_h[NP*NP], gRt_l[NP*NP];
__device__ bf16  gR2_h[NP*NP], gR2_l[NP*NP];
__device__ bf16  gX_h[Bx*NP*NCH],  gX_l[Bx*NP*NCH];    // padded [b][256][6400]
__device__ bf16  gY1_h[Bx*NP*NCH], gY1_l[Bx*NP*NCH];
__device__ bf16  gY2_h[Bx*NP*NCH], gY2_l[Bx*NP*NCH];
__device__ bf16  gW_h[128*GW], gW_l[128*GW];           // padded K rows 96->128
__device__ bf16  gG_h[(size_t)1600*NP*GW], gG_l[(size_t)1600*NP*GW];  // [bi][256][192]

// ---------------- small prep kernels ----------------
__global__ void k_deg(const float* __restrict__ adj) {
    int i = threadIdx.x;
    if (i < Nn) {
        float cs = 0.f, rs = 0.f;
        for (int b = 0; b < Nn; b++) if (b != i) cs += adj[b*Nn + i];
        for (int e = 0; e < Nn; e++) if (e != i) rs += adj[i*Nn + e];
        g_d0[i] = (cs > 0.f) ? rsqrtf(cs) : 0.f;
        g_d1[i] = (rs > 0.f) ? rsqrtf(rs) : 0.f;
    }
}

__global__ void k_buildA(const float* __restrict__ adj) {
    int idx = blockIdx.x * blockDim.x + threadIdx.x;
    if (idx < NP*NP) {
        int e = idx / NP, b = idx % NP;
        float v = 0.f;
        if (e < Nn && b < Nn && e != b) v = g_d0[b] * adj[b*Nn + e] * g_d1[e];
        g_Afp[e*NP + b] = v;     // A[e][b] = L[b,e]
        g_Rtf[b*NP + e] = v;     // Rt[b][e] = L[b,e]
    }
}

__global__ void k_R2() {   // R2 = 2 * Rt @ Rt, grid(16,16) block(16,16)
    __shared__ float a[16][17], b[16][17];
    int tx = threadIdx.x, ty = threadIdx.y;
    int j = blockIdx.y*16 + ty, q = blockIdx.x*16 + tx;
    float s = 0.f;
    for (int p0 = 0; p0 < NP; p0 += 16) {
        a[ty][tx] = g_Rtf[j*NP + p0 + tx];
        b[ty][tx] = g_Rtf[(p0+ty)*NP + q];
        __syncthreads();
        #pragma unroll
        for (int p = 0; p < 16; p++) s += a[ty][p]*b[p][tx];
        __syncthreads();
    }
    g_R2f[j*NP + q] = 2.f*s;
}

__global__ void k_splitmat(int which) {
    const float* s; bf16 *h, *l;
    if (which == 0)      { s = g_Afp; h = gA_h;  l = gA_l;  }
    else if (which == 1) { s = g_Rtf; h = gRt_h; l = gRt_l; }
    else                 { s = g_R2f; h = gR2_h; l = gR2_l; }
    int i = blockIdx.x * blockDim.x + threadIdx.x;
    if (i < NP*NP) {
        float v = s[i];
        bf16 hh = __float2bfloat16(v);
        h[i] = hh;
        l[i] = __float2bfloat16(v - __bfloat162float(hh));
    }
}

__global__ void k_splitX(const float* __restrict__ x) {
    size_t i = (size_t)blockIdx.x * blockDim.x + threadIdx.x;
    if (i < (size_t)Bx*NP*NCH) {
        int col = (int)(i % NCH);
        int r   = (int)((i / NCH) % NP);
        int b   = (int)(i / ((size_t)NP*NCH));
        float v = (r < Nn) ? x[((size_t)b*Nn + r)*NCH + col] : 0.f;
        bf16 hh = __float2bfloat16(v);
        gX_h[i] = hh;
        gX_l[i] = __float2bfloat16(v - __bfloat162float(hh));
    }
}

__global__ void k_buildW(const float* __restrict__ w) {
    int i = blockIdx.x * blockDim.x + threadIdx.x;
    if (i < 128*GW) {
        int row = i / GW, col = i % GW;
        float v = 0.f;
        if (row < 96) {
            int k1 = row / 32, c = row % 32;
            int k2 = col / 64, o = col % 64;
            v = w[o*288 + (k1*3 + k2)*32 + c];
        }
        bf16 hh = __float2bfloat16(v);
        gW_h[i] = hh;
        gW_l[i] = __float2bfloat16(v - __bfloat162float(hh));
    }
}

// ---------------- mma helpers ----------------
static __device__ __forceinline__ unsigned sptr(const void* p) {
    return (unsigned)__cvta_generic_to_shared(p);
}

static __device__ __forceinline__ void mma_bf16(float* c, const unsigned* a, const unsigned* b) {
    asm volatile("mma.sync.aligned.m16n8k16.row.col.f32.bf16.bf16.f32 "
        "{%0,%1,%2,%3},{%4,%5,%6,%7},{%8,%9},{%0,%1,%2,%3};\n"
        : "+f"(c[0]), "+f"(c[1]), "+f"(c[2]), "+f"(c[3])
        : "r"(a[0]), "r"(a[1]), "r"(a[2]), "r"(a[3]), "r"(b[0]), "r"(b[1]));
}

#define LDB2(bq, addr) asm volatile( \
    "ldmatrix.sync.aligned.m8n8.x2.trans.shared.b16 {%0,%1},[%2];" \
    : "=r"((bq)[0]), "=r"((bq)[1]) : "r"(addr))

#define SM_STRIDE 72

// 64x64 tile copy, src row-major with stride lda (all unguarded: padded bufs)
static __device__ __forceinline__ void cp_tile(bf16* dst, const bf16* src, int lda) {
    int tid = threadIdx.x;
    #pragma unroll
    for (int i = 0; i < 4; i++) {
        int u = tid + i*128, r = u >> 3, s = u & 7;
        *(uint4*)(dst + r*SM_STRIDE + s*8) = *(const uint4*)(src + (size_t)r*lda + s*8);
    }
}

// compute one 64(M)x64(N)x64(K) stage with 3-way split-bf16 accumulation
static __device__ __forceinline__ void mma_stage(float acc[2][4][4],
        const bf16* Ah, const bf16* Al, const bf16* Bh, const bf16* Bl) {
    int lane = threadIdx.x & 31, warp = threadIdx.x >> 5;
    int m0 = (warp >> 1) * 32, n0 = (warp & 1) * 32;
    int g = lane >> 2, tig = lane & 3;
    #pragma unroll
    for (int kk = 0; kk < 4; kk++) {
        int kb = kk*16;
        unsigned aH[2][4], aL[2][4], bH[4][2], bL[4][2];
        #pragma unroll
        for (int mt = 0; mt < 2; mt++) {
            int r = m0 + mt*16 + g;
            const bf16* p = Ah + r*SM_STRIDE + kb + tig*2;
            aH[mt][0] = *(const unsigned*)p;
            aH[mt][1] = *(const unsigned*)(p + 8*SM_STRIDE);
            aH[mt][2] = *(const unsigned*)(p + 8);
            aH[mt][3] = *(const unsigned*)(p + 8*SM_STRIDE + 8);
            const bf16* q = Al + r*SM_STRIDE + kb + tig*2;
            aL[mt][0] = *(const unsigned*)q;
            aL[mt][1] = *(const unsigned*)(q + 8*SM_STRIDE);
            aL[mt][2] = *(const unsigned*)(q + 8);
            aL[mt][3] = *(const unsigned*)(q + 8*SM_STRIDE + 8);
        }
        int rr = kb + (lane & 15);
        #pragma unroll
        for (int nt = 0; nt < 4; nt++) {
            unsigned adh = sptr(Bh + rr*SM_STRIDE + n0 + nt*8);
            unsigned adl = sptr(Bl + rr*SM_STRIDE + n0 + nt*8);
            LDB2(bH[nt], adh);
            LDB2(bL[nt], adl);
        }
        #pragma unroll
        for (int mt = 0; mt < 2; mt++)
            #pragma unroll
            for (int nt = 0; nt < 4; nt++) {
                mma_bf16(acc[mt][nt], aH[mt], bH[nt]);
                mma_bf16(acc[mt][nt], aH[mt], bL[nt]);
                mma_bf16(acc[mt][nt], aL[mt], bH[nt]);
            }
    }
}

// ---------------- GEMM kernels ----------------
// left: Y1 = A@X (mode0) ; Y2 = 2*A@Y1 - X (mode1). M=node(256) N=6400 K=256.
__global__ __launch_bounds__(128) void k_left_mma(int mode, const float* __restrict__ xf32) {
    __shared__ bf16 Ah[64*SM_STRIDE], Al[64*SM_STRIDE], Bh[64*SM_STRIDE], Bl[64*SM_STRIDE];
    int n0 = blockIdx.x*64, e0 = blockIdx.y*64, b = blockIdx.z;
    const bf16* Bsh = mode ? gY1_h : gX_h;
    const bf16* Bsl = mode ? gY1_l : gX_l;
    bf16* Oh = mode ? gY2_h : gY1_h;
    bf16* Ol = mode ? gY2_l : gY1_l;
    float acc[2][4][4];
    #pragma unroll
    for (int i = 0; i < 2; i++) for (int j2 = 0; j2 < 4; j2++) for (int r = 0; r < 4; r++) acc[i][j2][r] = 0.f;

    for (int k0 = 0; k0 < NP; k0 += 64) {
        cp_tile(Ah, gA_h + e0*NP + k0, NP);
        cp_tile(Al, gA_l + e0*NP + k0, NP);
        cp_tile(Bh, Bsh + ((size_t)b*NP + k0)*NCH + n0, NCH);
        cp_tile(Bl, Bsl + ((size_t)b*NP + k0)*NCH + n0, NCH);
        __syncthreads();
        mma_stage(acc, Ah, Al, Bh, Bl);
        __syncthreads();
    }
    int lane = threadIdx.x & 31, warp = threadIdx.x >> 5;
    int g = lane >> 2, tig = lane & 3;
    int mw = (warp >> 1)*32, nw = (warp & 1)*32;
    #pragma unroll
    for (int mt = 0; mt < 2; mt++)
        #pragma unroll
        for (int nt = 0; nt < 4; nt++) {
            int col = n0 + nw + nt*8 + tig*2;
            #pragma unroll
            for (int rh = 0; rh < 2; rh++) {
                int row = e0 + mw + mt*16 + g + rh*8;
                float v0 = acc[mt][nt][rh*2+0], v1 = acc[mt][nt][rh*2+1];
                if (mode) {
                    if (row < Nn) {
                        const float* xp = xf32 + ((size_t)b*Nn + row)*NCH + col;
                        v0 = 2.f*v0 - xp[0];
                        v1 = 2.f*v1 - xp[1];
                    } else { v0 = 0.f; v1 = 0.f; }
                }
                bf16 h0 = __float2bfloat16(v0), h1 = __float2bfloat16(v1);
                bf16 l0 = __float2bfloat16(v0 - __bfloat162float(h0));
                bf16 l1 = __float2bfloat16(v1 - __bfloat162float(h1));
                size_t di = ((size_t)b*NP + row)*NCH + col;
                bf162 ph; ph.x = h0; ph.y = h1;
                bf162 pl; pl.x = l0; pl.y = l1;
                *(bf162*)(Oh + di) = ph;
                *(bf162*)(Ol + di) = pl;
            }
        }
}

// mix A-operand loader: rows are padded (bi,q) rows, channels [X|Y1|Y2]
static __device__ __forceinline__ void cp_tileS(bf16* dst, const bf16* Xs,
        const bf16* Y1s, const bf16* Y2s, int pr0, int k0) {
    int tid = threadIdx.x;
    #pragma unroll
    for (int i = 0; i < 4; i++) {
        int u = tid + i*128, r = u >> 3, s = u & 7;
        int pr = pr0 + r, bi = pr >> 8, q = pr & 255;
        int c = k0 + s*8;
        uint4 v = make_uint4(0u, 0u, 0u, 0u);
        if (q < Nn && c < 96) {
            int b = bi / Nn, ii = bi % Nn;
            size_t base = ((size_t)b*NP + ii)*NCH + q*32;
            const bf16* sp;
            if (c < 32)      sp = Xs  + base + c;
            else if (c < 64) sp = Y1s + base + (c - 32);
            else             sp = Y2s + base + (c - 64);
            v = *(const uint4*)sp;
        }
        *(uint4*)(dst + r*SM_STRIDE + s*8) = v;
    }
}

// mix: G[pr][192] = S[pr][96] @ Wr[96][192]. grid(3, 6400)
__global__ __launch_bounds__(128) void k_mix_mma() {
    __shared__ bf16 Ah[64*SM_STRIDE], Al[64*SM_STRIDE], Bh[64*SM_STRIDE], Bl[64*SM_STRIDE];
    int n0 = blockIdx.x*64, pr0 = blockIdx.y*64;
    float acc[2][4][4];
    #pragma unroll
    for (int i = 0; i < 2; i++) for (int j2 = 0; j2 < 4; j2++) for (int r = 0; r < 4; r++) acc[i][j2][r] = 0.f;

    for (int k0 = 0; k0 < 128; k0 += 64) {
        cp_tileS(Ah, gX_h, gY1_h, gY2_h, pr0, k0);
        cp_tileS(Al, gX_l, gY1_l, gY2_l, pr0, k0);
        cp_tile(Bh, gW_h + k0*GW + n0, GW);
        cp_tile(Bl, gW_l + k0*GW + n0, GW);
        __syncthreads();
        mma_stage(acc, Ah, Al, Bh, Bl);
        __syncthreads();
    }
    int lane = threadIdx.x & 31, warp = threadIdx.x >> 5;
    int g = lane >> 2, tig = lane & 3;
    int mw = (warp >> 1)*32, nw = (warp & 1)*32;
    #pragma unroll
    for (int mt = 0; mt < 2; mt++)
        #pragma unroll
        for (int nt = 0; nt < 4; nt++) {
            int col = n0 + nw + nt*8 + tig*2;
            #pragma unroll
            for (int rh = 0; rh < 2; rh++) {
                int row = pr0 + mw + mt*16 + g + rh*8;
                float v0 = acc[mt][nt][rh*2+0], v1 = acc[mt][nt][rh*2+1];
                bf16 h0 = __float2bfloat16(v0), h1 = __float2bfloat16(v1);
                bf16 l0 = __float2bfloat16(v0 - __bfloat162float(h0));
                bf16 l1 = __float2bfloat16(v1 - __bfloat162float(h1));
                size_t di = (size_t)row*GW + col;
                bf162 ph; ph.x = h0; ph.y = h1;
                bf162 pl; pl.x = l0; pl.y = l1;
                *(bf162*)(gG_h + di) = ph;
                *(bf162*)(gG_l + di) = pl;
            }
        }
}

// right: out[bi][j][o] = bias + G0 - G2 + Rt@G1 + (2Rt^2)@G2. grid(4, 1600)
__global__ __launch_bounds__(128) void k_right_mma(const float* __restrict__ bias,
                                                   float* __restrict__ out) {
    __shared__ bf16 Ah[64*SM_STRIDE], Al[64*SM_STRIDE], Bh[64*SM_STRIDE], Bl[64*SM_STRIDE];
    int j0 = blockIdx.x*64, bi = blockIdx.y;
    float acc[2][4][4];
    #pragma unroll
    for (int i = 0; i < 2; i++) for (int j2 = 0; j2 < 4; j2++) for (int r = 0; r < 4; r++) acc[i][j2][r] = 0.f;

    #pragma unroll
    for (int ph = 0; ph < 2; ph++) {
        const bf16* Rh = ph ? gR2_h : gRt_h;
        const bf16* Rl = ph ? gR2_l : gRt_l;
        int coff = ph ? 128 : 64;
        for (int k0 = 0; k0 < NP; k0 += 64) {
            cp_tile(Ah, Rh + j0*NP + k0, NP);
            cp_tile(Al, Rl + j0*NP + k0, NP);
            cp_tile(Bh, gG_h + ((size_t)bi*NP + k0)*GW + coff, GW);
            cp_tile(Bl, gG_l + ((size_t)bi*NP + k0)*GW + coff, GW);
            __syncthreads();
            mma_stage(acc, Ah, Al, Bh, Bl);
            __syncthreads();
        }
    }
    int lane = threadIdx.x & 31, warp = threadIdx.x >> 5;
    int g = lane >> 2, tig = lane & 3;
    int mw = (warp >> 1)*32, nw = (warp & 1)*32;
    #pragma unroll
    for (int mt = 0; mt < 2; mt++)
        #pragma unroll
        for (int nt = 0; nt < 4; nt++) {
            int o = nw + nt*8 + tig*2;
            #pragma unroll
            for (int rh = 0; rh < 2; rh++) {
                int j = j0 + mw + mt*16 + g + rh*8;
                if (j < Nn) {
                    size_t grow = ((size_t)bi*NP + j)*GW;
                    float v0 = acc[mt][nt][rh*2+0], v1 = acc[mt][nt][rh*2+1];
                    float g0a = __bfloat162float(gG_h[grow + o])     + __bfloat162float(gG_l[grow + o]);
                    float g0b = __bfloat162float(gG_h[grow + o + 1]) + __bfloat162float(gG_l[grow + o + 1]);
                    float g2a = __bfloat162float(gG_h[grow + 128 + o])     + __bfloat162float(gG_l[grow + 128 + o]);
                    float g2b = __bfloat162float(gG_h[grow + 128 + o + 1]) + __bfloat162float(gG_l[grow + 128 + o + 1]);
                    size_t oi = ((size_t)bi*Nn + j)*64 + o;
                    out[oi]     = bias[o]     + g0a - g2a + v0;
                    out[oi + 1] = bias[o + 1] + g0b - g2b + v1;
                }
            }
        }
}

// ---------------------------------------------------------------------------
extern "C" void kernel_launch(void* const* d_in, const int* in_sizes, int n_in,
                              void* d_out, int out_size) {
    const float* x    = (const float*)d_in[0];   // [8,200,200,32]
    const float* adj  = (const float*)d_in[1];   // [200,200]
    const float* w    = (const float*)d_in[2];   // [64,288]
    const float* bias = (const float*)d_in[3];   // [64]
    float* out = (float*)d_out;                  // [8,200,200,64]

    k_deg<<<1, 256>>>(adj);
    k_buildA<<<(NP*NP + 255)/256, 256>>>(adj);
    k_R2<<<dim3(16, 16), dim3(16, 16)>>>();
    k_splitmat<<<(NP*NP + 255)/256, 256>>>(0);
    k_splitmat<<<(NP*NP + 255)/256, 256>>>(1);
    k_splitmat<<<(NP*NP + 255)/256, 256>>>(2);
    k_splitX<<<(int)(((size_t)Bx*NP*NCH + 255)/256), 256>>>(x);
    k_buildW<<<(128*GW + 255)/256, 256>>>(w);

    dim3 gl(NCH/64, NP/64, Bx);          // (100, 4, 8)
    k_left_mma<<<gl, 128>>>(0, x);       // Y1 = A @ X
    k_left_mma<<<gl, 128>>>(1, x);       // Y2 = 2*A@Y1 - X

    k_mix_mma<<<dim3(3, (1600*NP)/64), 128>>>();       // (3, 6400)

    k_right_mma<<<dim3(NP/64, 1600), 128>>>(bias, out); // (4, 1600)
}

// round 5
// speedup vs baseline: 2.0890x; 1.3056x over previous
#include <cuda_runtime.h>
#include <cuda_bf16.h>
#include <cstdint>

#define Nn   200
#define NP   256
#define Bx   8
#define NCH  6400
#define GW   192

typedef __nv_bfloat16 bf16;
typedef __nv_bfloat162 bf162;

// ---------------- static scratch ----------------
__device__ float g_d0[NP];
__device__ float g_d1[NP];
__device__ float g_Afp[NP*NP];
__device__ float g_Rtf[NP*NP];
__device__ float g_R2f[NP*NP];
__device__ bf16  gA_h[NP*NP],  gA_l[NP*NP];
__device__ bf16  gRt_h[NP*NP], gRt_l[NP*NP];
__device__ bf16  gR2_h[NP*NP], gR2_l[NP*NP];
__device__ bf16  gX_h[(size_t)Bx*NP*NCH],  gX_l[(size_t)Bx*NP*NCH];
__device__ bf16  gY1_h[(size_t)Bx*NP*NCH], gY1_l[(size_t)Bx*NP*NCH];
__device__ bf16  gY2_h[(size_t)Bx*NP*NCH], gY2_l[(size_t)Bx*NP*NCH];
__device__ bf16  gW_h[128*GW], gW_l[128*GW];            // [k=128][n=192]
__device__ bf16  gG_h[(size_t)1600*NP*GW], gG_l[(size_t)1600*NP*GW];

// ---------------- prep kernels ----------------
__global__ void k_deg(const float* __restrict__ adj) {
    int i = threadIdx.x;
    if (i < Nn) {
        float cs = 0.f, rs = 0.f;
        for (int b = 0; b < Nn; b++) if (b != i) cs += adj[b*Nn + i];
        for (int e = 0; e < Nn; e++) if (e != i) rs += adj[i*Nn + e];
        g_d0[i] = (cs > 0.f) ? rsqrtf(cs) : 0.f;
        g_d1[i] = (rs > 0.f) ? rsqrtf(rs) : 0.f;
    }
}
__global__ void k_buildA(const float* __restrict__ adj) {
    int idx = blockIdx.x * blockDim.x + threadIdx.x;
    if (idx < NP*NP) {
        int e = idx / NP, b = idx % NP;
        float v = 0.f;
        if (e < Nn && b < Nn && e != b) v = g_d0[b] * adj[b*Nn + e] * g_d1[e];
        g_Afp[e*NP + b] = v;
        g_Rtf[b*NP + e] = v;
    }
}
__global__ void k_R2() {
    __shared__ float a[16][17], b[16][17];
    int tx = threadIdx.x, ty = threadIdx.y;
    int j = blockIdx.y*16 + ty, q = blockIdx.x*16 + tx;
    float s = 0.f;
    for (int p0 = 0; p0 < NP; p0 += 16) {
        a[ty][tx] = g_Rtf[j*NP + p0 + tx];
        b[ty][tx] = g_Rtf[(p0+ty)*NP + q];
        __syncthreads();
        #pragma unroll
        for (int p = 0; p < 16; p++) s += a[ty][p]*b[p][tx];
        __syncthreads();
    }
    g_R2f[j*NP + q] = 2.f*s;
}
__global__ void k_splitmat(int which) {
    const float* s; bf16 *h, *l;
    if (which == 0)      { s = g_Afp; h = gA_h;  l = gA_l;  }
    else if (which == 1) { s = g_Rtf; h = gRt_h; l = gRt_l; }
    else                 { s = g_R2f; h = gR2_h; l = gR2_l; }
    int i = blockIdx.x * blockDim.x + threadIdx.x;
    if (i < NP*NP) {
        float v = s[i];
        bf16 hh = __float2bfloat16(v);
        h[i] = hh;
        l[i] = __float2bfloat16(v - __bfloat162float(hh));
    }
}
__global__ void k_splitX(const float* __restrict__ x) {
    size_t i = (size_t)blockIdx.x * blockDim.x + threadIdx.x;
    if (i < (size_t)Bx*NP*NCH) {
        int col = (int)(i % NCH);
        int r   = (int)((i / NCH) % NP);
        int b   = (int)(i / ((size_t)NP*NCH));
        float v = (r < Nn) ? x[((size_t)b*Nn + r)*NCH + col] : 0.f;
        bf16 hh = __float2bfloat16(v);
        gX_h[i] = hh;
        gX_l[i] = __float2bfloat16(v - __bfloat162float(hh));
    }
}
__global__ void k_buildW(const float* __restrict__ w) {
    int i = blockIdx.x * blockDim.x + threadIdx.x;
    if (i < 128*GW) {
        int k = i / GW, n = i % GW;
        float v = 0.f;
        if (k < 96) {
            int k1 = k / 32, c = k & 31;
            int k2 = n / 64, o = n & 63;
            v = w[o*288 + (k1*3 + k2)*32 + c];
        }
        bf16 hh = __float2bfloat16(v);
        gW_h[i] = hh;
        gW_l[i] = __float2bfloat16(v - __bfloat162float(hh));
    }
}

// ---------------- mma/async helpers ----------------
static __device__ __forceinline__ unsigned sptr(const void* p) {
    return (unsigned)__cvta_generic_to_shared(p);
}
static __device__ __forceinline__ void mma_bf16(float* c, const unsigned* a, const unsigned* b) {
    asm volatile("mma.sync.aligned.m16n8k16.row.col.f32.bf16.bf16.f32 "
        "{%0,%1,%2,%3},{%4,%5,%6,%7},{%8,%9},{%0,%1,%2,%3};\n"
        : "+f"(c[0]), "+f"(c[1]), "+f"(c[2]), "+f"(c[3])
        : "r"(a[0]), "r"(a[1]), "r"(a[2]), "r"(a[3]), "r"(b[0]), "r"(b[1]));
}
#define LDB2(bq, addr) asm volatile( \
    "ldmatrix.sync.aligned.m8n8.x2.trans.shared.b16 {%0,%1},[%2];" \
    : "=r"((bq)[0]), "=r"((bq)[1]) : "r"(addr))

#define SM_STRIDE 72
#define TILE_B    (64*SM_STRIDE*2)   // 9216 bytes per 64x64 bf16 tile

#define CPA(dst, src, sz) asm volatile( \
    "cp.async.cg.shared.global [%0], [%1], 16, %2;" :: "r"(dst), "l"(src), "r"(sz))
#define CPA_COMMIT() asm volatile("cp.async.commit_group;")
template<int N>
static __device__ __forceinline__ void cpa_wait() {
    asm volatile("cp.async.wait_group %0;" :: "n"(N));
}

// async copy 64x64 bf16 tile, src stride lda elements (unguarded, padded bufs)
static __device__ __forceinline__ void cpa64(unsigned dst, const bf16* src, long lda) {
    int tid = threadIdx.x;
    #pragma unroll
    for (int i = 0; i < 4; i++) {
        int u = tid + i*128, r = u >> 3, s = u & 7;
        CPA(dst + r*(SM_STRIDE*2) + s*16, src + (long)r*lda + s*8, 16);
    }
}

// 64(M)x64(N) x (KSN*16) K with 3-pass split-bf16
template<int KSN>
static __device__ __forceinline__ void mma_stage(float acc[2][4][4],
        const bf16* Ah, const bf16* Al, const bf16* Bh, const bf16* Bl) {
    int lane = threadIdx.x & 31, warp = threadIdx.x >> 5;
    int m0 = (warp >> 1) * 32, n0 = (warp & 1) * 32;
    int g = lane >> 2, tig = lane & 3;
    #pragma unroll
    for (int kk = 0; kk < KSN; kk++) {
        int kb = kk*16;
        unsigned aH[2][4], aL[2][4], bH[4][2], bL[4][2];
        #pragma unroll
        for (int mt = 0; mt < 2; mt++) {
            int r = m0 + mt*16 + g;
            const bf16* p = Ah + r*SM_STRIDE + kb + tig*2;
            aH[mt][0] = *(const unsigned*)p;
            aH[mt][1] = *(const unsigned*)(p + 8*SM_STRIDE);
            aH[mt][2] = *(const unsigned*)(p + 8);
            aH[mt][3] = *(const unsigned*)(p + 8*SM_STRIDE + 8);
            const bf16* q = Al + r*SM_STRIDE + kb + tig*2;
            aL[mt][0] = *(const unsigned*)q;
            aL[mt][1] = *(const unsigned*)(q + 8*SM_STRIDE);
            aL[mt][2] = *(const unsigned*)(q + 8);
            aL[mt][3] = *(const unsigned*)(q + 8*SM_STRIDE + 8);
        }
        int rr = kb + (lane & 15);
        #pragma unroll
        for (int nt = 0; nt < 4; nt++) {
            LDB2(bH[nt], sptr(Bh + rr*SM_STRIDE + n0 + nt*8));
            LDB2(bL[nt], sptr(Bl + rr*SM_STRIDE + n0 + nt*8));
        }
        #pragma unroll
        for (int mt = 0; mt < 2; mt++)
            #pragma unroll
            for (int nt = 0; nt < 4; nt++) {
                mma_bf16(acc[mt][nt], aH[mt], bH[nt]);
                mma_bf16(acc[mt][nt], aH[mt], bL[nt]);
                mma_bf16(acc[mt][nt], aL[mt], bH[nt]);
            }
    }
}

// ---------------- left: Y1 = A@X (mode0) ; Y2 = 2*A@Y1 - X (mode1) ----------
// grid (100, 4, 8), 128 threads. 2-stage cp.async pipeline, K chunks {4,4,4,1}.
__global__ __launch_bounds__(128) void k_left_mma(int mode, const float* __restrict__ xf32) {
    extern __shared__ __align__(128) char smem[];
    unsigned sb = sptr(smem);
    int n0 = blockIdx.x*64, e0 = blockIdx.y*64, b = blockIdx.z;
    const bf16* Bhs = mode ? gY1_h : gX_h;
    const bf16* Bls = mode ? gY1_l : gX_l;
    bf16* Oh = mode ? gY2_h : gY1_h;
    bf16* Ol = mode ? gY2_l : gY1_l;

    float acc[2][4][4];
    #pragma unroll
    for (int i = 0; i < 2; i++) for (int j = 0; j < 4; j++) for (int r = 0; r < 4; r++) acc[i][j][r] = 0.f;

    auto load_chunk = [&](int c, int st) {
        unsigned base = sb + st*(4*TILE_B);
        cpa64(base,            gA_h + (size_t)e0*NP + c*64, NP);
        cpa64(base + TILE_B,   gA_l + (size_t)e0*NP + c*64, NP);
        cpa64(base + 2*TILE_B, Bhs + ((size_t)b*NP + c*64)*NCH + n0, NCH);
        cpa64(base + 3*TILE_B, Bls + ((size_t)b*NP + c*64)*NCH + n0, NCH);
        CPA_COMMIT();
    };

    load_chunk(0, 0);
    #pragma unroll
    for (int c = 0; c < 4; c++) {
        if (c < 3) { load_chunk(c+1, (c+1)&1); cpa_wait<1>(); }
        else       cpa_wait<0>();
        __syncthreads();
        const char* base = smem + (c&1)*(4*TILE_B);
        const bf16* Ah = (const bf16*)base;
        const bf16* Al = (const bf16*)(base + TILE_B);
        const bf16* Bh = (const bf16*)(base + 2*TILE_B);
        const bf16* Bl = (const bf16*)(base + 3*TILE_B);
        if (c == 3) mma_stage<1>(acc, Ah, Al, Bh, Bl);
        else        mma_stage<4>(acc, Ah, Al, Bh, Bl);
        __syncthreads();
    }

    int lane = threadIdx.x & 31, warp = threadIdx.x >> 5;
    int g = lane >> 2, tig = lane & 3;
    int mw = (warp >> 1)*32, nw = (warp & 1)*32;
    #pragma unroll
    for (int mt = 0; mt < 2; mt++)
        #pragma unroll
        for (int nt = 0; nt < 4; nt++) {
            int col = n0 + nw + nt*8 + tig*2;
            #pragma unroll
            for (int rh = 0; rh < 2; rh++) {
                int row = e0 + mw + mt*16 + g + rh*8;
                float v0 = acc[mt][nt][rh*2+0], v1 = acc[mt][nt][rh*2+1];
                if (mode) {
                    if (row < Nn) {
                        const float* xp = xf32 + ((size_t)b*Nn + row)*NCH + col;
                        v0 = 2.f*v0 - xp[0];
                        v1 = 2.f*v1 - xp[1];
                    } else { v0 = 0.f; v1 = 0.f; }
                }
                bf16 h0 = __float2bfloat16(v0), h1 = __float2bfloat16(v1);
                bf16 l0 = __float2bfloat16(v0 - __bfloat162float(h0));
                bf16 l1 = __float2bfloat16(v1 - __bfloat162float(h1));
                size_t di = ((size_t)b*NP + row)*NCH + col;
                bf162 ph; ph.x = h0; ph.y = h1;
                bf162 pl; pl.x = l0; pl.y = l1;
                *(bf162*)(Oh + di) = ph;
                *(bf162*)(Ol + di) = pl;
            }
        }
}

// ---------------- mix: G[pr][192] = S[pr][96] @ W[96][192] -------------------
// grid (3, 6400), 128 threads. K chunks {4,2} k16-steps. All loads async upfront.
__global__ __launch_bounds__(128) void k_mix_mma() {
    extern __shared__ __align__(128) char smem[];
    unsigned sb = sptr(smem);
    int n0 = blockIdx.x*64, pr0 = blockIdx.y*64;
    int bi = pr0 >> 8, q0 = pr0 & 255;
    int bb = bi / Nn, ii = bi % Nn;
    size_t abase = ((size_t)(bb*NP + ii))*NCH;
    int tid = threadIdx.x;

    // layout: A tiles: [c][hl] 4*TILE_B ; B tiles: [c][hl] 4*TILE_B
    #pragma unroll
    for (int c = 0; c < 2; c++) {
        unsigned da = sb + c*(2*TILE_B);
        #pragma unroll
        for (int i = 0; i < 4; i++) {
            int u = tid + i*128, r = u >> 3, s = u & 7;
            int q = q0 + r;
            int ch = c*64 + s*8;
            int sz = (q < Nn && ch < 96) ? 16 : 0;
            int qc = (q < Nn) ? q : 0;
            const bf16 *ph, *pl;
            if (ch < 32)      { ph = gX_h  + abase + qc*32 + ch;      pl = gX_l  + abase + qc*32 + ch; }
            else if (ch < 64) { ph = gY1_h + abase + qc*32 + ch - 32; pl = gY1_l + abase + qc*32 + ch - 32; }
            else              { int cc = (ch < 96) ? ch - 64 : 0;
                                ph = gY2_h + abase + qc*32 + cc;      pl = gY2_l + abase + qc*32 + cc; }
            unsigned o = r*(SM_STRIDE*2) + s*16;
            CPA(da + o, ph, sz);
            CPA(da + TILE_B + o, pl, sz);
        }
        unsigned db = sb + 4*TILE_B + c*(2*TILE_B);
        cpa64(db,          gW_h + (size_t)(c*64)*GW + n0, GW);
        cpa64(db + TILE_B, gW_l + (size_t)(c*64)*GW + n0, GW);
    }
    CPA_COMMIT();
    cpa_wait<0>();
    __syncthreads();

    float acc[2][4][4];
    #pragma unroll
    for (int i = 0; i < 2; i++) for (int j = 0; j < 4; j++) for (int r = 0; r < 4; r++) acc[i][j][r] = 0.f;

    #pragma unroll
    for (int c = 0; c < 2; c++) {
        const char* ab = smem + c*(2*TILE_B);
        const char* bb2 = smem + 4*TILE_B + c*(2*TILE_B);
        const bf16* Ah = (const bf16*)ab;
        const bf16* Al = (const bf16*)(ab + TILE_B);
        const bf16* Bh = (const bf16*)bb2;
        const bf16* Bl = (const bf16*)(bb2 + TILE_B);
        if (c == 0) mma_stage<4>(acc, Ah, Al, Bh, Bl);
        else        mma_stage<2>(acc, Ah, Al, Bh, Bl);
    }

    int lane = threadIdx.x & 31, warp = threadIdx.x >> 5;
    int g = lane >> 2, tig = lane & 3;
    int mw = (warp >> 1)*32, nw = (warp & 1)*32;
    #pragma unroll
    for (int mt = 0; mt < 2; mt++)
        #pragma unroll
        for (int nt = 0; nt < 4; nt++) {
            int col = n0 + nw + nt*8 + tig*2;
            #pragma unroll
            for (int rh = 0; rh < 2; rh++) {
                int row = pr0 + mw + mt*16 + g + rh*8;
                float v0 = acc[mt][nt][rh*2+0], v1 = acc[mt][nt][rh*2+1];
                bf16 h0 = __float2bfloat16(v0), h1 = __float2bfloat16(v1);
                bf16 l0 = __float2bfloat16(v0 - __bfloat162float(h0));
                bf16 l1 = __float2bfloat16(v1 - __bfloat162float(h1));
                size_t di = (size_t)row*GW + col;
                bf162 ph; ph.x = h0; ph.y = h1;
                bf162 pl; pl.x = l0; pl.y = l1;
                *(bf162*)(gG_h + di) = ph;
                *(bf162*)(gG_l + di) = pl;
            }
        }
}

// ---------------- right: out = bias + G0 - G2 + Rt@G1 + R2@G2 ----------------
// grid (4, 1600), 128 threads. 8 chunks (2 phases x 4), ks {4,4,4,1} each phase.
__global__ __launch_bounds__(128) void k_right_mma(const float* __restrict__ bias,
                                                   float* __restrict__ out) {
    extern __shared__ __align__(128) char smem[];
    unsigned sb = sptr(smem);
    int j0 = blockIdx.x*64, bi = blockIdx.y;

    float acc[2][4][4];
    #pragma unroll
    for (int i = 0; i < 2; i++) for (int j = 0; j < 4; j++) for (int r = 0; r < 4; r++) acc[i][j][r] = 0.f;

    auto load_chunk = [&](int c, int st) {
        int phase = c >> 2, kq0 = (c & 3)*64;
        const bf16* Ah = phase ? gR2_h : gRt_h;
        const bf16* Al = phase ? gR2_l : gRt_l;
        int coff = phase ? 128 : 64;
        unsigned base = sb + st*(4*TILE_B);
        cpa64(base,            Ah + (size_t)j0*NP + kq0, NP);
        cpa64(base + TILE_B,   Al + (size_t)j0*NP + kq0, NP);
        cpa64(base + 2*TILE_B, gG_h + ((size_t)bi*NP + kq0)*GW + coff, GW);
        cpa64(base + 3*TILE_B, gG_l + ((size_t)bi*NP + kq0)*GW + coff, GW);
        CPA_COMMIT();
    };

    load_chunk(0, 0);
    #pragma unroll
    for (int c = 0; c < 8; c++) {
        if (c < 7) { load_chunk(c+1, (c+1)&1); cpa_wait<1>(); }
        else       cpa_wait<0>();
        __syncthreads();
        const char* base = smem + (c&1)*(4*TILE_B);
        const bf16* Ah = (const bf16*)base;
        const bf16* Al = (const bf16*)(base + TILE_B);
        const bf16* Bh = (const bf16*)(base + 2*TILE_B);
        const bf16* Bl = (const bf16*)(base + 3*TILE_B);
        if ((c & 3) == 3) mma_stage<1>(acc, Ah, Al, Bh, Bl);
        else              mma_stage<4>(acc, Ah, Al, Bh, Bl);
        __syncthreads();
    }

    int lane = threadIdx.x & 31, warp = threadIdx.x >> 5;
    int g = lane >> 2, tig = lane & 3;
    int mw = (warp >> 1)*32, nw = (warp & 1)*32;
    #pragma unroll
    for (int mt = 0; mt < 2; mt++)
        #pragma unroll
        for (int nt = 0; nt < 4; nt++) {
            int o = nw + nt*8 + tig*2;
            #pragma unroll
            for (int rh = 0; rh < 2; rh++) {
                int j = j0 + mw + mt*16 + g + rh*8;
                if (j < Nn) {
                    size_t grow = ((size_t)bi*NP + j)*GW;
                    float v0 = acc[mt][nt][rh*2+0], v1 = acc[mt][nt][rh*2+1];
                    float g0a = __bfloat162float(gG_h[grow + o])     + __bfloat162float(gG_l[grow + o]);
                    float g0b = __bfloat162float(gG_h[grow + o + 1]) + __bfloat162float(gG_l[grow + o + 1]);
                    float g2a = __bfloat162float(gG_h[grow + 128 + o])     + __bfloat162float(gG_l[grow + 128 + o]);
                    float g2b = __bfloat162float(gG_h[grow + 128 + o + 1]) + __bfloat162float(gG_l[grow + 128 + o + 1]);
                    size_t oi = ((size_t)bi*Nn + j)*64 + o;
                    out[oi]     = bias[o]     + g0a - g2a + v0;
                    out[oi + 1] = bias[o + 1] + g0b - g2b + v1;
                }
            }
        }
}

#define LEFT_SMEM  (8*TILE_B)   // 73728
#define MIX_SMEM   (8*TILE_B)   // 73728
#define RIGHT_SMEM (8*TILE_B)   // 73728

// ---------------------------------------------------------------------------
extern "C" void kernel_launch(void* const* d_in, const int* in_sizes, int n_in,
                              void* d_out, int out_size) {
    const float* x    = (const float*)d_in[0];
    const float* adj  = (const float*)d_in[1];
    const float* w    = (const float*)d_in[2];
    const float* bias = (const float*)d_in[3];
    float* out = (float*)d_out;

    cudaFuncSetAttribute(k_left_mma,  cudaFuncAttributeMaxDynamicSharedMemorySize, LEFT_SMEM);
    cudaFuncSetAttribute(k_mix_mma,   cudaFuncAttributeMaxDynamicSharedMemorySize, MIX_SMEM);
    cudaFuncSetAttribute(k_right_mma, cudaFuncAttributeMaxDynamicSharedMemorySize, RIGHT_SMEM);

    k_deg<<<1, 256>>>(adj);
    k_buildA<<<(NP*NP + 255)/256, 256>>>(adj);
    k_R2<<<dim3(16, 16), dim3(16, 16)>>>();
    k_splitmat<<<(NP*NP + 255)/256, 256>>>(0);
    k_splitmat<<<(NP*NP + 255)/256, 256>>>(1);
    k_splitmat<<<(NP*NP + 255)/256, 256>>>(2);
    k_splitX<<<(int)(((size_t)Bx*NP*NCH + 255)/256), 256>>>(x);
    k_buildW<<<(128*GW + 255)/256, 256>>>(w);

    dim3 gl(NCH/64, NP/64, Bx);                       // (100, 4, 8)
    k_left_mma<<<gl, 128, LEFT_SMEM>>>(0, x);         // Y1 = A @ X
    k_left_mma<<<gl, 128, LEFT_SMEM>>>(1, x);         // Y2 = 2*A@Y1 - X

    k_mix_mma<<<dim3(3, (1600*NP)/64), 128, MIX_SMEM>>>();   // (3, 6400)

    k_right_mma<<<dim3(NP/64, 1600), 128, RIGHT_SMEM>>>(bias, out);
}

// round 6
// speedup vs baseline: 2.1124x; 1.0112x over previous
#include <cuda_runtime.h>
#include <cuda_bf16.h>
#include <cstdint>

#define Nn   200
#define NP   256
#define Bx   8
#define NCH  6400
#define GW   192

typedef __nv_bfloat16 bf16;
typedef __nv_bfloat162 bf162;

// ---------------- static scratch ----------------
__device__ float g_d0[NP];
__device__ float g_d1[NP];
__device__ float g_Afp[NP*NP];
__device__ float g_Rtf[NP*NP];
__device__ float g_R2f[NP*NP];
__device__ bf16  gA_h[NP*NP],  gA_l[NP*NP];
__device__ bf16  gRt_h[NP*NP], gRt_l[NP*NP];
__device__ bf16  gR2_h[NP*NP], gR2_l[NP*NP];
__device__ bf16  gX_h[(size_t)Bx*NP*NCH],  gX_l[(size_t)Bx*NP*NCH];
__device__ bf16  gY1_h[(size_t)Bx*NP*NCH], gY1_l[(size_t)Bx*NP*NCH];
__device__ bf16  gY2_h[(size_t)Bx*NP*NCH], gY2_l[(size_t)Bx*NP*NCH];
__device__ bf16  gW_h[128*GW], gW_l[128*GW];            // [k=128][n=192]

// ---------------- prep kernels ----------------
__global__ void k_deg(const float* __restrict__ adj) {
    int i = threadIdx.x;
    if (i < Nn) {
        float cs = 0.f, rs = 0.f;
        for (int b = 0; b < Nn; b++) if (b != i) cs += adj[b*Nn + i];
        for (int e = 0; e < Nn; e++) if (e != i) rs += adj[i*Nn + e];
        g_d0[i] = (cs > 0.f) ? rsqrtf(cs) : 0.f;
        g_d1[i] = (rs > 0.f) ? rsqrtf(rs) : 0.f;
    }
}
__global__ void k_buildA(const float* __restrict__ adj) {
    int idx = blockIdx.x * blockDim.x + threadIdx.x;
    if (idx < NP*NP) {
        int e = idx / NP, b = idx % NP;
        float v = 0.f;
        if (e < Nn && b < Nn && e != b) v = g_d0[b] * adj[b*Nn + e] * g_d1[e];
        g_Afp[e*NP + b] = v;
        g_Rtf[b*NP + e] = v;
    }
}
__global__ void k_R2() {
    __shared__ float a[16][17], b[16][17];
    int tx = threadIdx.x, ty = threadIdx.y;
    int j = blockIdx.y*16 + ty, q = blockIdx.x*16 + tx;
    float s = 0.f;
    for (int p0 = 0; p0 < NP; p0 += 16) {
        a[ty][tx] = g_Rtf[j*NP + p0 + tx];
        b[ty][tx] = g_Rtf[(p0+ty)*NP + q];
        __syncthreads();
        #pragma unroll
        for (int p = 0; p < 16; p++) s += a[ty][p]*b[p][tx];
        __syncthreads();
    }
    g_R2f[j*NP + q] = 2.f*s;
}
__global__ void k_splitmat(int which) {
    const float* s; bf16 *h, *l;
    if (which == 0)      { s = g_Afp; h = gA_h;  l = gA_l;  }
    else if (which == 1) { s = g_Rtf; h = gRt_h; l = gRt_l; }
    else                 { s = g_R2f; h = gR2_h; l = gR2_l; }
    int i = blockIdx.x * blockDim.x + threadIdx.x;
    if (i < NP*NP) {
        float v = s[i];
        bf16 hh = __float2bfloat16(v);
        h[i] = hh;
        l[i] = __float2bfloat16(v - __bfloat162float(hh));
    }
}
__global__ void k_splitX(const float* __restrict__ x) {
    size_t i = (size_t)blockIdx.x * blockDim.x + threadIdx.x;
    if (i < (size_t)Bx*NP*NCH) {
        int col = (int)(i % NCH);
        int r   = (int)((i / NCH) % NP);
        int b   = (int)(i / ((size_t)NP*NCH));
        float v = (r < Nn) ? x[((size_t)b*Nn + r)*NCH + col] : 0.f;
        bf16 hh = __float2bfloat16(v);
        gX_h[i] = hh;
        gX_l[i] = __float2bfloat16(v - __bfloat162float(hh));
    }
}
__global__ void k_buildW(const float* __restrict__ w) {
    int i = blockIdx.x * blockDim.x + threadIdx.x;
    if (i < 128*GW) {
        int k = i / GW, n = i % GW;
        float v = 0.f;
        if (k < 96) {
            int k1 = k / 32, c = k & 31;
            int k2 = n / 64, o = n & 63;
            v = w[o*288 + (k1*3 + k2)*32 + c];
        }
        bf16 hh = __float2bfloat16(v);
        gW_h[i] = hh;
        gW_l[i] = __float2bfloat16(v - __bfloat162float(hh));
    }
}

// ---------------- mma/async helpers ----------------
static __device__ __forceinline__ unsigned sptr(const void* p) {
    return (unsigned)__cvta_generic_to_shared(p);
}
static __device__ __forceinline__ void mma_bf16(float* c, const unsigned* a, const unsigned* b) {
    asm volatile("mma.sync.aligned.m16n8k16.row.col.f32.bf16.bf16.f32 "
        "{%0,%1,%2,%3},{%4,%5,%6,%7},{%8,%9},{%0,%1,%2,%3};\n"
        : "+f"(c[0]), "+f"(c[1]), "+f"(c[2]), "+f"(c[3])
        : "r"(a[0]), "r"(a[1]), "r"(a[2]), "r"(a[3]), "r"(b[0]), "r"(b[1]));
}
#define LDB2(bq, addr) asm volatile( \
    "ldmatrix.sync.aligned.m8n8.x2.trans.shared.b16 {%0,%1},[%2];" \
    : "=r"((bq)[0]), "=r"((bq)[1]) : "r"(addr))

#define SM_STRIDE 72
#define TILE_B    (64*SM_STRIDE*2)   // 9216 bytes per 64x64 bf16 tile

#define CPA(dst, src, sz) asm volatile( \
    "cp.async.cg.shared.global [%0], [%1], 16, %2;" :: "r"(dst), "l"(src), "r"(sz))
#define CPA_COMMIT() asm volatile("cp.async.commit_group;")
template<int N>
static __device__ __forceinline__ void cpa_wait() {
    asm volatile("cp.async.wait_group %0;" :: "n"(N));
}

// async copy 64x64 bf16 tile, src stride lda elements (unguarded, padded bufs)
static __device__ __forceinline__ void cpa64(unsigned dst, const bf16* src, long lda) {
    int tid = threadIdx.x;
    #pragma unroll
    for (int i = 0; i < 4; i++) {
        int u = tid + i*128, r = u >> 3, s = u & 7;
        CPA(dst + r*(SM_STRIDE*2) + s*16, src + (long)r*lda + s*8, 16);
    }
}

// 64(M)x64(N) x (KSN*16) K with 3-pass split-bf16; A stride AS, B stride BS (elems)
template<int KSN, int AS, int BS>
static __device__ __forceinline__ void mma_stageG(float acc[2][4][4],
        const bf16* Ah, const bf16* Al, const bf16* Bh, const bf16* Bl) {
    int lane = threadIdx.x & 31, warp = threadIdx.x >> 5;
    int m0 = (warp >> 1) * 32, n0 = (warp & 1) * 32;
    int g = lane >> 2, tig = lane & 3;
    #pragma unroll
    for (int kk = 0; kk < KSN; kk++) {
        int kb = kk*16;
        unsigned aH[2][4], aL[2][4], bH[4][2], bL[4][2];
        #pragma unroll
        for (int mt = 0; mt < 2; mt++) {
            int r = m0 + mt*16 + g;
            const bf16* p = Ah + r*AS + kb + tig*2;
            aH[mt][0] = *(const unsigned*)p;
            aH[mt][1] = *(const unsigned*)(p + 8*AS);
            aH[mt][2] = *(const unsigned*)(p + 8);
            aH[mt][3] = *(const unsigned*)(p + 8*AS + 8);
            const bf16* q = Al + r*AS + kb + tig*2;
            aL[mt][0] = *(const unsigned*)q;
            aL[mt][1] = *(const unsigned*)(q + 8*AS);
            aL[mt][2] = *(const unsigned*)(q + 8);
            aL[mt][3] = *(const unsigned*)(q + 8*AS + 8);
        }
        int rr = kb + (lane & 15);
        #pragma unroll
        for (int nt = 0; nt < 4; nt++) {
            LDB2(bH[nt], sptr(Bh + rr*BS + n0 + nt*8));
            LDB2(bL[nt], sptr(Bl + rr*BS + n0 + nt*8));
        }
        #pragma unroll
        for (int mt = 0; mt < 2; mt++)
            #pragma unroll
            for (int nt = 0; nt < 4; nt++) {
                mma_bf16(acc[mt][nt], aH[mt], bH[nt]);
                mma_bf16(acc[mt][nt], aH[mt], bL[nt]);
                mma_bf16(acc[mt][nt], aL[mt], bH[nt]);
            }
    }
}

// ---------------- left: Y1 = A@X (mode0) ; Y2 = 2*A@Y1 - X (mode1) ----------
__global__ __launch_bounds__(128) void k_left_mma(int mode, const float* __restrict__ xf32) {
    extern __shared__ __align__(128) char smem[];
    unsigned sb = sptr(smem);
    int n0 = blockIdx.x*64, e0 = blockIdx.y*64, b = blockIdx.z;
    const bf16* Bhs = mode ? gY1_h : gX_h;
    const bf16* Bls = mode ? gY1_l : gX_l;
    bf16* Oh = mode ? gY2_h : gY1_h;
    bf16* Ol = mode ? gY2_l : gY1_l;

    float acc[2][4][4];
    #pragma unroll
    for (int i = 0; i < 2; i++) for (int j = 0; j < 4; j++) for (int r = 0; r < 4; r++) acc[i][j][r] = 0.f;

    auto load_chunk = [&](int c, int st) {
        unsigned base = sb + st*(4*TILE_B);
        cpa64(base,            gA_h + (size_t)e0*NP + c*64, NP);
        cpa64(base + TILE_B,   gA_l + (size_t)e0*NP + c*64, NP);
        cpa64(base + 2*TILE_B, Bhs + ((size_t)b*NP + c*64)*NCH + n0, NCH);
        cpa64(base + 3*TILE_B, Bls + ((size_t)b*NP + c*64)*NCH + n0, NCH);
        CPA_COMMIT();
    };

    load_chunk(0, 0);
    #pragma unroll
    for (int c = 0; c < 4; c++) {
        if (c < 3) { load_chunk(c+1, (c+1)&1); cpa_wait<1>(); }
        else       cpa_wait<0>();
        __syncthreads();
        const char* base = smem + (c&1)*(4*TILE_B);
        const bf16* Ah = (const bf16*)base;
        const bf16* Al = (const bf16*)(base + TILE_B);
        const bf16* Bh = (const bf16*)(base + 2*TILE_B);
        const bf16* Bl = (const bf16*)(base + 3*TILE_B);
        if (c == 3) mma_stageG<1,SM_STRIDE,SM_STRIDE>(acc, Ah, Al, Bh, Bl);
        else        mma_stageG<4,SM_STRIDE,SM_STRIDE>(acc, Ah, Al, Bh, Bl);
        __syncthreads();
    }

    int lane = threadIdx.x & 31, warp = threadIdx.x >> 5;
    int g = lane >> 2, tig = lane & 3;
    int mw = (warp >> 1)*32, nw = (warp & 1)*32;
    #pragma unroll
    for (int mt = 0; mt < 2; mt++)
        #pragma unroll
        for (int nt = 0; nt < 4; nt++) {
            int col = n0 + nw + nt*8 + tig*2;
            #pragma unroll
            for (int rh = 0; rh < 2; rh++) {
                int row = e0 + mw + mt*16 + g + rh*8;
                float v0 = acc[mt][nt][rh*2+0], v1 = acc[mt][nt][rh*2+1];
                if (mode) {
                    if (row < Nn) {
                        const float* xp = xf32 + ((size_t)b*Nn + row)*NCH + col;
                        v0 = 2.f*v0 - xp[0];
                        v1 = 2.f*v1 - xp[1];
                    } else { v0 = 0.f; v1 = 0.f; }
                }
                bf16 h0 = __float2bfloat16(v0), h1 = __float2bfloat16(v1);
                bf16 l0 = __float2bfloat16(v0 - __bfloat162float(h0));
                bf16 l1 = __float2bfloat16(v1 - __bfloat162float(h1));
                size_t di = ((size_t)b*NP + row)*NCH + col;
                bf162 ph; ph.x = h0; ph.y = h1;
                bf162 pl; pl.x = l0; pl.y = l1;
                *(bf162*)(Oh + di) = ph;
                *(bf162*)(Ol + di) = pl;
            }
        }
}

// ---------------- fused mix+right ------------------------------------------
// grid(1600) = (b,i) pairs, 128 threads.
// Phase 1: G[208 x 192] = S[208 x 96] @ W[96 x 192]  (h/l split, G kept in smem)
// Phase 2: out[j][o] = bias[o] + G0[j][o] - G2[j][o] + Rt@G1 + R2@G2
#define GSTR     200                       // G smem row stride (elems)
#define OFF_GH   0
#define OFF_GL   83200                     // 208*200*2
#define OFF_POOL 166400
#define OFF_SH   (OFF_POOL)
#define OFF_SL   (OFF_POOL + 13312)        // 64*104*2
#define OFF_WH   (OFF_POOL + 26624)
#define OFF_WL   (OFF_POOL + 40448)        // 96*72*2
#define FUSED_SMEM (OFF_POOL + 54272)      // 220672

__global__ __launch_bounds__(128) void k_fused(const float* __restrict__ bias,
                                               float* __restrict__ out) {
    extern __shared__ __align__(128) char smem[];
    unsigned sb = sptr(smem);
    int bi = blockIdx.x;
    int bb = bi / Nn, ii = bi % Nn;
    size_t abase = ((size_t)(bb*NP + ii))*NCH;
    int tid = threadIdx.x;
    int lane = tid & 31, warp = tid >> 5;
    int g = lane >> 2, tig = lane & 3;
    int mw = (warp >> 1)*32, nw = (warp & 1)*32;

    bf16* Ghp = (bf16*)(smem + OFF_GH);
    bf16* Glp = (bf16*)(smem + OFF_GL);

    // ---- phase 1: build G in smem ----
    for (int qc = 0; qc < 4; qc++) {
        int q0 = qc*64;
        // S tile (64 rows x 96 ch) h/l
        #pragma unroll
        for (int i = 0; i < 6; i++) {
            int u = tid + i*128;
            int r = u / 12, s = u % 12;
            int q = q0 + r;
            int seg = s >> 2, cc = (s & 3)*8;
            int sz = (q < Nn) ? 16 : 0;
            int qq = (q < Nn) ? q : 0;
            size_t off = abase + (size_t)qq*32 + cc;
            const bf16 *ph, *pl;
            if (seg == 0)      { ph = gX_h  + off; pl = gX_l  + off; }
            else if (seg == 1) { ph = gY1_h + off; pl = gY1_l + off; }
            else               { ph = gY2_h + off; pl = gY2_l + off; }
            unsigned d = r*208 + s*16;
            CPA(sb + OFF_SH + d, ph, sz);
            CPA(sb + OFF_SL + d, pl, sz);
        }
        for (int nt3 = 0; nt3 < 3; nt3++) {
            int n0g = nt3*64;
            // W tile (96 k-rows x 64 n-cols) h/l
            #pragma unroll
            for (int i = 0; i < 6; i++) {
                int u = tid + i*128;
                int r = u >> 3, s = u & 7;
                unsigned d = r*144 + s*16;
                CPA(sb + OFF_WH + d, gW_h + (size_t)r*GW + n0g + s*8, 16);
                CPA(sb + OFF_WL + d, gW_l + (size_t)r*GW + n0g + s*8, 16);
            }
            CPA_COMMIT();
            cpa_wait<0>();
            __syncthreads();

            float acc[2][4][4];
            #pragma unroll
            for (int i = 0; i < 2; i++) for (int j = 0; j < 4; j++) for (int r = 0; r < 4; r++) acc[i][j][r] = 0.f;
            mma_stageG<6,104,SM_STRIDE>(acc,
                (const bf16*)(smem + OFF_SH), (const bf16*)(smem + OFF_SL),
                (const bf16*)(smem + OFF_WH), (const bf16*)(smem + OFF_WL));

            // store acc -> G smem (h/l)
            #pragma unroll
            for (int mt = 0; mt < 2; mt++)
                #pragma unroll
                for (int nt = 0; nt < 4; nt++) {
                    int col = n0g + nw + nt*8 + tig*2;
                    #pragma unroll
                    for (int rh = 0; rh < 2; rh++) {
                        int row = q0 + mw + mt*16 + g + rh*8;
                        if (row < 208) {
                            float v0 = acc[mt][nt][rh*2+0], v1 = acc[mt][nt][rh*2+1];
                            bf16 h0 = __float2bfloat16(v0), h1 = __float2bfloat16(v1);
                            bf16 l0 = __float2bfloat16(v0 - __bfloat162float(h0));
                            bf16 l1 = __float2bfloat16(v1 - __bfloat162float(h1));
                            bf162 ph; ph.x = h0; ph.y = h1;
                            bf162 pl; pl.x = l0; pl.y = l1;
                            *(bf162*)(Ghp + row*GSTR + col) = ph;
                            *(bf162*)(Glp + row*GSTR + col) = pl;
                        }
                    }
                }
            __syncthreads();
        }
    }

    // ---- phase 2: right contraction, B = G smem ----
    auto loadA = [&](int c, int st) {
        int phse = c >> 2, kq0 = (c & 3)*64;
        const bf16* Ah = phse ? gR2_h : gRt_h;
        const bf16* Al = phse ? gR2_l : gRt_l;
        unsigned base = sb + OFF_POOL + st*(2*TILE_B);
        cpa64(base,          Ah + (size_t)(blockIdx.y /*unused*/ * 0) + (size_t)(0), NP); // placeholder removed below
    };
    (void)loadA;

    for (int jt = 0; jt < 4; jt++) {
        int j0 = jt*64;
        float acc[2][4][4];
        #pragma unroll
        for (int i = 0; i < 2; i++) for (int j = 0; j < 4; j++) for (int r = 0; r < 4; r++) acc[i][j][r] = 0.f;

        auto load_chunk = [&](int c, int st) {
            int phse = c >> 2, kq0 = (c & 3)*64;
            const bf16* Ah = phse ? gR2_h : gRt_h;
            const bf16* Al = phse ? gR2_l : gRt_l;
            unsigned base = sb + OFF_POOL + st*(2*TILE_B);
            cpa64(base,          Ah + (size_t)j0*NP + kq0, NP);
            cpa64(base + TILE_B, Al + (size_t)j0*NP + kq0, NP);
            CPA_COMMIT();
        };

        load_chunk(0, 0);
        #pragma unroll
        for (int c = 0; c < 8; c++) {
            if (c < 7) { load_chunk(c+1, (c+1)&1); cpa_wait<1>(); }
            else       cpa_wait<0>();
            __syncthreads();
            int phse = c >> 2, kc = c & 3;
            const char* ab = smem + OFF_POOL + (c&1)*(2*TILE_B);
            const bf16* Ah = (const bf16*)ab;
            const bf16* Al = (const bf16*)(ab + TILE_B);
            int coff = phse ? 128 : 64;
            const bf16* Bh = Ghp + kc*64*GSTR + coff;
            const bf16* Bl = Glp + kc*64*GSTR + coff;
            if (kc == 3) mma_stageG<1,SM_STRIDE,GSTR>(acc, Ah, Al, Bh, Bl);
            else         mma_stageG<4,SM_STRIDE,GSTR>(acc, Ah, Al, Bh, Bl);
            __syncthreads();
        }

        // epilogue
        #pragma unroll
        for (int mt = 0; mt < 2; mt++)
            #pragma unroll
            for (int nt = 0; nt < 4; nt++) {
                int o = nw + nt*8 + tig*2;
                #pragma unroll
                for (int rh = 0; rh < 2; rh++) {
                    int j = j0 + mw + mt*16 + g + rh*8;
                    if (j < Nn) {
                        float v0 = acc[mt][nt][rh*2+0], v1 = acc[mt][nt][rh*2+1];
                        int gr = j*GSTR;
                        float g0a = __bfloat162float(Ghp[gr + o])       + __bfloat162float(Glp[gr + o]);
                        float g0b = __bfloat162float(Ghp[gr + o + 1])   + __bfloat162float(Glp[gr + o + 1]);
                        float g2a = __bfloat162float(Ghp[gr + 128 + o]) + __bfloat162float(Glp[gr + 128 + o]);
                        float g2b = __bfloat162float(Ghp[gr + 128 + o + 1]) + __bfloat162float(Glp[gr + 128 + o + 1]);
                        size_t oi = ((size_t)bi*Nn + j)*64 + o;
                        out[oi]     = bias[o]     + g0a - g2a + v0;
                        out[oi + 1] = bias[o + 1] + g0b - g2b + v1;
                    }
                }
            }
    }
}

#define LEFT_SMEM  (8*TILE_B)   // 73728

// ---------------------------------------------------------------------------
extern "C" void kernel_launch(void* const* d_in, const int* in_sizes, int n_in,
                              void* d_out, int out_size) {
    const float* x    = (const float*)d_in[0];
    const float* adj  = (const float*)d_in[1];
    const float* w    = (const float*)d_in[2];
    const float* bias = (const float*)d_in[3];
    float* out = (float*)d_out;

    cudaFuncSetAttribute(k_left_mma, cudaFuncAttributeMaxDynamicSharedMemorySize, LEFT_SMEM);
    cudaFuncSetAttribute(k_fused,    cudaFuncAttributeMaxDynamicSharedMemorySize, FUSED_SMEM);

    k_deg<<<1, 256>>>(adj);
    k_buildA<<<(NP*NP + 255)/256, 256>>>(adj);
    k_R2<<<dim3(16, 16), dim3(16, 16)>>>();
    k_splitmat<<<(NP*NP + 255)/256, 256>>>(0);
    k_splitmat<<<(NP*NP + 255)/256, 256>>>(1);
    k_splitmat<<<(NP*NP + 255)/256, 256>>>(2);
    k_splitX<<<(int)(((size_t)Bx*NP*NCH + 255)/256), 256>>>(x);
    k_buildW<<<(128*GW + 255)/256, 256>>>(w);

    dim3 gl(NCH/64, NP/64, Bx);                       // (100, 4, 8)
    k_left_mma<<<gl, 128, LEFT_SMEM>>>(0, x);         // Y1 = A @ X
    k_left_mma<<<gl, 128, LEFT_SMEM>>>(1, x);         // Y2 = 2*A@Y1 - X

    k_fused<<<1600, 128, FUSED_SMEM>>>(bias, out);    // mix + right fused
}

// round 7
// speedup vs baseline: 2.2692x; 1.0742x over previous
#include <cuda_runtime.h>
#include <cuda_bf16.h>
#include <cstdint>

#define Nn   200
#define NP   256
#define Bx   8
#define NCH  6400
#define GW   192

typedef __nv_bfloat16 bf16;
typedef __nv_bfloat162 bf162;

// ---------------- static scratch ----------------
__device__ float g_d0[NP];
__device__ float g_d1[NP];
__device__ float g_Afp[NP*NP];
__device__ float g_Rtf[NP*NP];
__device__ float g_R2f[NP*NP];
__device__ bf16  gA_h[NP*NP],  gA_l[NP*NP];
__device__ bf16  gRt_h[NP*NP], gRt_l[NP*NP];
__device__ bf16  gR2_h[NP*NP], gR2_l[NP*NP];
__device__ bf16  gX_h[(size_t)Bx*NP*NCH],  gX_l[(size_t)Bx*NP*NCH];
__device__ bf16  gY1_h[(size_t)Bx*NP*NCH], gY1_l[(size_t)Bx*NP*NCH];
__device__ bf16  gY2_h[(size_t)Bx*NP*NCH], gY2_l[(size_t)Bx*NP*NCH];
__device__ bf16  gW_h[128*GW], gW_l[128*GW];            // [k=128][n=192]

// ---------------- prep kernels ----------------
__global__ void k_deg(const float* __restrict__ adj) {
    int i = threadIdx.x;
    if (i < Nn) {
        float cs = 0.f, rs = 0.f;
        for (int b = 0; b < Nn; b++) if (b != i) cs += adj[b*Nn + i];
        for (int e = 0; e < Nn; e++) if (e != i) rs += adj[i*Nn + e];
        g_d0[i] = (cs > 0.f) ? rsqrtf(cs) : 0.f;
        g_d1[i] = (rs > 0.f) ? rsqrtf(rs) : 0.f;
    }
}
__global__ void k_buildA(const float* __restrict__ adj) {
    int idx = blockIdx.x * blockDim.x + threadIdx.x;
    if (idx < NP*NP) {
        int e = idx / NP, b = idx % NP;
        float v = 0.f;
        if (e < Nn && b < Nn && e != b) v = g_d0[b] * adj[b*Nn + e] * g_d1[e];
        g_Afp[e*NP + b] = v;
        g_Rtf[b*NP + e] = v;
    }
}
__global__ void k_R2() {
    __shared__ float a[16][17], b[16][17];
    int tx = threadIdx.x, ty = threadIdx.y;
    int j = blockIdx.y*16 + ty, q = blockIdx.x*16 + tx;
    float s = 0.f;
    for (int p0 = 0; p0 < NP; p0 += 16) {
        a[ty][tx] = g_Rtf[j*NP + p0 + tx];
        b[ty][tx] = g_Rtf[(p0+ty)*NP + q];
        __syncthreads();
        #pragma unroll
        for (int p = 0; p < 16; p++) s += a[ty][p]*b[p][tx];
        __syncthreads();
    }
    g_R2f[j*NP + q] = 2.f*s;
}
// consolidated: splitmat x3 | splitX | buildW  (fewer launches -> ncu hits main kernels)
__global__ void k_prepsplit(const float* __restrict__ x, const float* __restrict__ w) {
    int b = blockIdx.x;
    int tid = threadIdx.x;
    if (b < 768) {
        int which = b / 256;
        const float* s; bf16 *h, *l;
        if (which == 0)      { s = g_Afp; h = gA_h;  l = gA_l;  }
        else if (which == 1) { s = g_Rtf; h = gRt_h; l = gRt_l; }
        else                 { s = g_R2f; h = gR2_h; l = gR2_l; }
        int i = (b % 256)*256 + tid;
        float v = s[i];
        bf16 hh = __float2bfloat16(v);
        h[i] = hh;
        l[i] = __float2bfloat16(v - __bfloat162float(hh));
    } else if (b < 768 + 51200) {
        size_t i = (size_t)(b - 768)*256 + tid;
        int col = (int)(i % NCH);
        int r   = (int)((i / NCH) % NP);
        int bb  = (int)(i / ((size_t)NP*NCH));
        float v = (r < Nn) ? x[((size_t)bb*Nn + r)*NCH + col] : 0.f;
        bf16 hh = __float2bfloat16(v);
        gX_h[i] = hh;
        gX_l[i] = __float2bfloat16(v - __bfloat162float(hh));
    } else {
        int i = (b - 768 - 51200)*256 + tid;
        int k = i / GW, n = i % GW;
        float v = 0.f;
        if (k < 96) {
            int k1 = k / 32, c = k & 31;
            int k2 = n / 64, o = n & 63;
            v = w[o*288 + (k1*3 + k2)*32 + c];
        }
        bf16 hh = __float2bfloat16(v);
        gW_h[i] = hh;
        gW_l[i] = __float2bfloat16(v - __bfloat162float(hh));
    }
}

// ---------------- mma/async helpers ----------------
static __device__ __forceinline__ unsigned sptr(const void* p) {
    return (unsigned)__cvta_generic_to_shared(p);
}
static __device__ __forceinline__ void mma_bf16(float* c, const unsigned* a, const unsigned* b) {
    asm volatile("mma.sync.aligned.m16n8k16.row.col.f32.bf16.bf16.f32 "
        "{%0,%1,%2,%3},{%4,%5,%6,%7},{%8,%9},{%0,%1,%2,%3};\n"
        : "+f"(c[0]), "+f"(c[1]), "+f"(c[2]), "+f"(c[3])
        : "r"(a[0]), "r"(a[1]), "r"(a[2]), "r"(a[3]), "r"(b[0]), "r"(b[1]));
}
static __device__ __forceinline__ void mma_bf16_k8(float* c, const unsigned* a, unsigned b) {
    asm volatile("mma.sync.aligned.m16n8k8.row.col.f32.bf16.bf16.f32 "
        "{%0,%1,%2,%3},{%4,%5},{%6},{%0,%1,%2,%3};\n"
        : "+f"(c[0]), "+f"(c[1]), "+f"(c[2]), "+f"(c[3])
        : "r"(a[0]), "r"(a[1]), "r"(b));
}
#define LDB2(bq, addr) asm volatile( \
    "ldmatrix.sync.aligned.m8n8.x2.trans.shared.b16 {%0,%1},[%2];" \
    : "=r"((bq)[0]), "=r"((bq)[1]) : "r"(addr))
#define LDB1(b, addr) asm volatile( \
    "ldmatrix.sync.aligned.m8n8.x1.trans.shared.b16 {%0},[%1];" \
    : "=r"(b) : "r"(addr))

#define SM_STRIDE 72
#define TILE_B    (64*SM_STRIDE*2)   // 9216

#define CPA(dst, src, sz) asm volatile( \
    "cp.async.cg.shared.global [%0], [%1], 16, %2;" :: "r"(dst), "l"(src), "r"(sz))
#define CPA8(dst, src) asm volatile( \
    "cp.async.ca.shared.global [%0], [%1], 8;" :: "r"(dst), "l"(src))
#define CPA_COMMIT() asm volatile("cp.async.commit_group;")
template<int N>
static __device__ __forceinline__ void cpa_wait() {
    asm volatile("cp.async.wait_group %0;" :: "n"(N));
}

// async copy 64x64 bf16 tile (128 threads)
static __device__ __forceinline__ void cpa64(unsigned dst, const bf16* src, long lda) {
    int tid = threadIdx.x;
    #pragma unroll
    for (int i = 0; i < 4; i++) {
        int u = tid + i*128, r = u >> 3, s = u & 7;
        CPA(dst + r*(SM_STRIDE*2) + s*16, src + (long)r*lda + s*8, 16);
    }
}

// 64(M)x64(N)x(KSN*16), 3-pass split; explicit warp quadrant (wm0, wn0)
template<int KSN, int AS, int BS>
static __device__ __forceinline__ void mma_stageG(float acc[2][4][4],
        const bf16* Ah, const bf16* Al, const bf16* Bh, const bf16* Bl,
        int wm0, int wn0) {
    int lane = threadIdx.x & 31;
    int g = lane >> 2, tig = lane & 3;
    #pragma unroll
    for (int kk = 0; kk < KSN; kk++) {
        int kb = kk*16;
        unsigned aH[2][4], aL[2][4], bH[4][2], bL[4][2];
        #pragma unroll
        for (int mt = 0; mt < 2; mt++) {
            int r = wm0 + mt*16 + g;
            const bf16* p = Ah + r*AS + kb + tig*2;
            aH[mt][0] = *(const unsigned*)p;
            aH[mt][1] = *(const unsigned*)(p + 8*AS);
            aH[mt][2] = *(const unsigned*)(p + 8);
            aH[mt][3] = *(const unsigned*)(p + 8*AS + 8);
            const bf16* q = Al + r*AS + kb + tig*2;
            aL[mt][0] = *(const unsigned*)q;
            aL[mt][1] = *(const unsigned*)(q + 8*AS);
            aL[mt][2] = *(const unsigned*)(q + 8);
            aL[mt][3] = *(const unsigned*)(q + 8*AS + 8);
        }
        int rr = kb + (lane & 15);
        #pragma unroll
        for (int nt = 0; nt < 4; nt++) {
            LDB2(bH[nt], sptr(Bh + rr*BS + wn0 + nt*8));
            LDB2(bL[nt], sptr(Bl + rr*BS + wn0 + nt*8));
        }
        #pragma unroll
        for (int mt = 0; mt < 2; mt++)
            #pragma unroll
            for (int nt = 0; nt < 4; nt++) {
                mma_bf16(acc[mt][nt], aH[mt], bH[nt]);
                mma_bf16(acc[mt][nt], aH[mt], bL[nt]);
                mma_bf16(acc[mt][nt], aL[mt], bH[nt]);
            }
    }
}

// single k8 step (3-pass)
template<int AS, int BS>
static __device__ __forceinline__ void mma_k8stage(float acc[2][4][4],
        const bf16* Ah, const bf16* Al, const bf16* Bh, const bf16* Bl,
        int wm0, int wn0) {
    int lane = threadIdx.x & 31;
    int g = lane >> 2, tig = lane & 3;
    unsigned aH[2][2], aL[2][2], bH[4], bL[4];
    #pragma unroll
    for (int mt = 0; mt < 2; mt++) {
        int r = wm0 + mt*16 + g;
        aH[mt][0] = *(const unsigned*)(Ah + r*AS + tig*2);
        aH[mt][1] = *(const unsigned*)(Ah + (r+8)*AS + tig*2);
        aL[mt][0] = *(const unsigned*)(Al + r*AS + tig*2);
        aL[mt][1] = *(const unsigned*)(Al + (r+8)*AS + tig*2);
    }
    int rr = lane & 7;
    #pragma unroll
    for (int nt = 0; nt < 4; nt++) {
        LDB1(bH[nt], sptr(Bh + rr*BS + wn0 + nt*8));
        LDB1(bL[nt], sptr(Bl + rr*BS + wn0 + nt*8));
    }
    #pragma unroll
    for (int mt = 0; mt < 2; mt++)
        #pragma unroll
        for (int nt = 0; nt < 4; nt++) {
            mma_bf16_k8(acc[mt][nt], aH[mt], bH[nt]);
            mma_bf16_k8(acc[mt][nt], aH[mt], bL[nt]);
            mma_bf16_k8(acc[mt][nt], aL[mt], bH[nt]);
        }
}

// ---------------- left: Y1 = A@X (mode0) ; Y2 = 2*A@Y1 - X (mode1) ----------
__global__ __launch_bounds__(128) void k_left_mma(int mode, const float* __restrict__ xf32) {
    extern __shared__ __align__(128) char smem[];
    unsigned sb = sptr(smem);
    int n0 = blockIdx.x*64, e0 = blockIdx.y*64, b = blockIdx.z;
    const bf16* Bhs = mode ? gY1_h : gX_h;
    const bf16* Bls = mode ? gY1_l : gX_l;
    bf16* Oh = mode ? gY2_h : gY1_h;
    bf16* Ol = mode ? gY2_l : gY1_l;

    float acc[2][4][4];
    #pragma unroll
    for (int i = 0; i < 2; i++) for (int j = 0; j < 4; j++) for (int r = 0; r < 4; r++) acc[i][j][r] = 0.f;

    auto load_chunk = [&](int c, int st) {
        unsigned base = sb + st*(4*TILE_B);
        cpa64(base,            gA_h + (size_t)e0*NP + c*64, NP);
        cpa64(base + TILE_B,   gA_l + (size_t)e0*NP + c*64, NP);
        cpa64(base + 2*TILE_B, Bhs + ((size_t)b*NP + c*64)*NCH + n0, NCH);
        cpa64(base + 3*TILE_B, Bls + ((size_t)b*NP + c*64)*NCH + n0, NCH);
        CPA_COMMIT();
    };

    int warp = threadIdx.x >> 5;
    int wm0 = (warp >> 1)*32, wn0 = (warp & 1)*32;

    load_chunk(0, 0);
    #pragma unroll
    for (int c = 0; c < 4; c++) {
        if (c < 3) { load_chunk(c+1, (c+1)&1); cpa_wait<1>(); }
        else       cpa_wait<0>();
        __syncthreads();
        const char* base = smem + (c&1)*(4*TILE_B);
        const bf16* Ah = (const bf16*)base;
        const bf16* Al = (const bf16*)(base + TILE_B);
        const bf16* Bh = (const bf16*)(base + 2*TILE_B);
        const bf16* Bl = (const bf16*)(base + 3*TILE_B);
        if (c == 3) mma_stageG<1,SM_STRIDE,SM_STRIDE>(acc, Ah, Al, Bh, Bl, wm0, wn0);
        else        mma_stageG<4,SM_STRIDE,SM_STRIDE>(acc, Ah, Al, Bh, Bl, wm0, wn0);
        __syncthreads();
    }

    int lane = threadIdx.x & 31;
    int g = lane >> 2, tig = lane & 3;
    #pragma unroll
    for (int mt = 0; mt < 2; mt++)
        #pragma unroll
        for (int nt = 0; nt < 4; nt++) {
            int col = n0 + wn0 + nt*8 + tig*2;
            #pragma unroll
            for (int rh = 0; rh < 2; rh++) {
                int row = e0 + wm0 + mt*16 + g + rh*8;
                float v0 = acc[mt][nt][rh*2+0], v1 = acc[mt][nt][rh*2+1];
                if (mode) {
                    if (row < Nn) {
                        const float* xp = xf32 + ((size_t)b*Nn + row)*NCH + col;
                        v0 = 2.f*v0 - xp[0];
                        v1 = 2.f*v1 - xp[1];
                    } else { v0 = 0.f; v1 = 0.f; }
                }
                bf16 h0 = __float2bfloat16(v0), h1 = __float2bfloat16(v1);
                bf16 l0 = __float2bfloat16(v0 - __bfloat162float(h0));
                bf16 l1 = __float2bfloat16(v1 - __bfloat162float(h1));
                size_t di = ((size_t)b*NP + row)*NCH + col;
                bf162 ph; ph.x = h0; ph.y = h1;
                bf162 pl; pl.x = l0; pl.y = l1;
                *(bf162*)(Oh + di) = ph;
                *(bf162*)(Ol + di) = pl;
            }
        }
}

// ---------------- fused mix+right, 256 threads ------------------------------
// G smem: 200 rows x stride 200 (h + l). Phase 1: two 64-row q-chunks in
// parallel (warp-groups). Phase 2: 128x64 j-tiles, A double-buffered.
#define GSTR     200
#define OFF_GH   0
#define OFF_GL   80000
#define OFF_POOL 160000
// phase1 pool
#define P1_S(t,hl)  (OFF_POOL + (t)*26624 + (hl)*13312)   // 64 x 104 bf16
#define P1_W(hl)    (OFF_POOL + 53248 + (hl)*6912)        // 48 x 72 bf16
// phase2 pool
#define ASTR        68
#define P2_A(st,hl) (OFF_POOL + (st)*34816 + (hl)*17408)  // 128 x 68 bf16
#define FUSED_SMEM  229632

__global__ __launch_bounds__(256) void k_fused(const float* __restrict__ bias,
                                               float* __restrict__ out) {
    extern __shared__ __align__(128) char smem[];
    unsigned sb = sptr(smem);
    int bi = blockIdx.x;
    int bb = bi / Nn, ii = bi % Nn;
    size_t abase = ((size_t)(bb*NP + ii))*NCH;
    int tid = threadIdx.x;
    int lane = tid & 31, warp = tid >> 5;
    int g = lane >> 2, tig = lane & 3;

    bf16* Ghp = (bf16*)(smem + OFF_GH);
    bf16* Glp = (bf16*)(smem + OFF_GL);

    // ---- phase 1 ----
    int g2 = warp >> 2;             // warp-group 0/1
    int wl = warp & 3;              // group-local warp
    int p1m0 = (wl >> 1)*32, p1n0 = (wl & 1)*32;

    for (int qp = 0; qp < 2; qp++) {
        int q0 = qp*128;
        // load both S tiles (2 x 64 rows x 96 ch), h/l
        #pragma unroll
        for (int i = 0; i < 6; i++) {
            int u = tid + i*256;
            int t = u / 768, rem = u % 768;
            int r = rem / 12, s = rem % 12;
            int q = q0 + t*64 + r;
            int seg = s >> 2, cc = (s & 3)*8;
            int sz = (q < Nn) ? 16 : 0;
            int qq = (q < Nn) ? q : 0;
            size_t off = abase + (size_t)qq*32 + cc;
            const bf16 *ph, *pl;
            if (seg == 0)      { ph = gX_h  + off; pl = gX_l  + off; }
            else if (seg == 1) { ph = gY1_h + off; pl = gY1_l + off; }
            else               { ph = gY2_h + off; pl = gY2_l + off; }
            unsigned d = r*208 + s*16;
            CPA(sb + P1_S(t,0) + d, ph, sz);
            CPA(sb + P1_S(t,1) + d, pl, sz);
        }
        CPA_COMMIT();
        cpa_wait<0>();
        __syncthreads();

        const bf16* Sh = (const bf16*)(smem + P1_S(g2,0));
        const bf16* Sl = (const bf16*)(smem + P1_S(g2,1));

        for (int nt3 = 0; nt3 < 3; nt3++) {
            int n0g = nt3*64;
            float acc[2][4][4];
            #pragma unroll
            for (int i = 0; i < 2; i++) for (int j = 0; j < 4; j++) for (int r = 0; r < 4; r++) acc[i][j][r] = 0.f;

            #pragma unroll
            for (int half = 0; half < 2; half++) {
                // load W 48k x 64n (h/l)
                #pragma unroll
                for (int i = 0; i < 3; i++) {
                    int u = tid + i*256;
                    int hl = u / 384, rem = u % 384;
                    int r = rem >> 3, s = rem & 7;
                    const bf16* wsrc = (hl ? gW_l : gW_h) + (size_t)(half*48 + r)*GW + n0g + s*8;
                    CPA(sb + P1_W(hl) + r*144 + s*16, wsrc, 16);
                }
                CPA_COMMIT();
                cpa_wait<0>();
                __syncthreads();
                mma_stageG<3,104,SM_STRIDE>(acc, Sh + half*48, Sl + half*48,
                    (const bf16*)(smem + P1_W(0)), (const bf16*)(smem + P1_W(1)),
                    p1m0, p1n0);
                __syncthreads();
            }
            // store acc -> G (rows q0 + g2*64 + ...)
            #pragma unroll
            for (int mt = 0; mt < 2; mt++)
                #pragma unroll
                for (int nt = 0; nt < 4; nt++) {
                    int col = n0g + p1n0 + nt*8 + tig*2;
                    #pragma unroll
                    for (int rh = 0; rh < 2; rh++) {
                        int row = q0 + g2*64 + p1m0 + mt*16 + g + rh*8;
                        if (row < Nn) {
                            float v0 = acc[mt][nt][rh*2+0], v1 = acc[mt][nt][rh*2+1];
                            bf16 h0 = __float2bfloat16(v0), h1 = __float2bfloat16(v1);
                            bf16 l0 = __float2bfloat16(v0 - __bfloat162float(h0));
                            bf16 l1 = __float2bfloat16(v1 - __bfloat162float(h1));
                            bf162 ph; ph.x = h0; ph.y = h1;
                            bf162 pl; pl.x = l0; pl.y = l1;
                            *(bf162*)(Ghp + row*GSTR + col) = ph;
                            *(bf162*)(Glp + row*GSTR + col) = pl;
                        }
                    }
                }
        }
        __syncthreads();
    }

    // ---- phase 2 ----
    int mw = (warp >> 1)*32, nw = (warp & 1)*32;

    for (int jt = 0; jt < 2; jt++) {
        int j0 = jt*128;
        float acc[2][4][4];
        #pragma unroll
        for (int i = 0; i < 2; i++) for (int j = 0; j < 4; j++) for (int r = 0; r < 4; r++) acc[i][j][r] = 0.f;

        auto load_chunk = [&](int c, int st) {
            int phse = c >> 2, kq0 = (c & 3)*64;
            const bf16* Ahs = phse ? gR2_h : gRt_h;
            const bf16* Als = phse ? gR2_l : gRt_l;
            // 128 rows x 64 cols, 8B copies (stride 136B)
            #pragma unroll
            for (int i = 0; i < 16; i++) {
                int u = tid + i*256;
                int hl = u >> 11, rem = u & 2047;
                int r = rem >> 4, s = rem & 15;
                const bf16* src = (hl ? Als : Ahs) + (size_t)(j0 + r)*NP + kq0 + s*4;
                CPA8(sb + P2_A(st,hl) + r*136 + s*8, src);
            }
            CPA_COMMIT();
        };

        load_chunk(0, 0);
        #pragma unroll
        for (int c = 0; c < 8; c++) {
            if (c < 7) { load_chunk(c+1, (c+1)&1); cpa_wait<1>(); }
            else       cpa_wait<0>();
            __syncthreads();
            int phse = c >> 2, kc = c & 3;
            const bf16* Ah = (const bf16*)(smem + P2_A(c&1,0));
            const bf16* Al = (const bf16*)(smem + P2_A(c&1,1));
            int coff = phse ? 128 : 64;
            const bf16* Bh = Ghp + kc*64*GSTR + coff;
            const bf16* Bl = Glp + kc*64*GSTR + coff;
            if (kc == 3) mma_k8stage<ASTR,GSTR>(acc, Ah, Al, Bh, Bl, mw, nw);
            else         mma_stageG<4,ASTR,GSTR>(acc, Ah, Al, Bh, Bl, mw, nw);
            __syncthreads();
        }

        // epilogue
        #pragma unroll
        for (int mt = 0; mt < 2; mt++)
            #pragma unroll
            for (int nt = 0; nt < 4; nt++) {
                int o = nw + nt*8 + tig*2;
                #pragma unroll
                for (int rh = 0; rh < 2; rh++) {
                    int j = j0 + mw + mt*16 + g + rh*8;
                    if (j < Nn) {
                        float v0 = acc[mt][nt][rh*2+0], v1 = acc[mt][nt][rh*2+1];
                        int gr = j*GSTR;
                        float g0a = __bfloat162float(Ghp[gr + o])       + __bfloat162float(Glp[gr + o]);
                        float g0b = __bfloat162float(Ghp[gr + o + 1])   + __bfloat162float(Glp[gr + o + 1]);
                        float g2a = __bfloat162float(Ghp[gr + 128 + o]) + __bfloat162float(Glp[gr + 128 + o]);
                        float g2b = __bfloat162float(Ghp[gr + 128 + o + 1]) + __bfloat162float(Glp[gr + 128 + o + 1]);
                        size_t oi = ((size_t)bi*Nn + j)*64 + o;
                        out[oi]     = bias[o]     + g0a - g2a + v0;
                        out[oi + 1] = bias[o + 1] + g0b - g2b + v1;
                    }
                }
            }
    }
}

#define LEFT_SMEM  (8*TILE_B)   // 73728

// ---------------------------------------------------------------------------
extern "C" void kernel_launch(void* const* d_in, const int* in_sizes, int n_in,
                              void* d_out, int out_size) {
    const float* x    = (const float*)d_in[0];
    const float* adj  = (const float*)d_in[1];
    const float* w    = (const float*)d_in[2];
    const float* bias = (const float*)d_in[3];
    float* out = (float*)d_out;

    cudaFuncSetAttribute(k_left_mma, cudaFuncAttributeMaxDynamicSharedMemorySize, LEFT_SMEM);
    cudaFuncSetAttribute(k_fused,    cudaFuncAttributeMaxDynamicSharedMemorySize, FUSED_SMEM);

    k_deg<<<1, 256>>>(adj);                                   // launch 0
    k_buildA<<<(NP*NP + 255)/256, 256>>>(adj);                // launch 1
    k_R2<<<dim3(16, 16), dim3(16, 16)>>>();                   // launch 2
    k_prepsplit<<<768 + 51200 + 96, 256>>>(x, w);             // launch 3

    dim3 gl(NCH/64, NP/64, Bx);                               // (100, 4, 8)
    k_left_mma<<<gl, 128, LEFT_SMEM>>>(0, x);                 // launch 4
    k_left_mma<<<gl, 128, LEFT_SMEM>>>(1, x);                 // launch 5 <- ncu
    k_fused<<<1600, 256, FUSED_SMEM>>>(bias, out);            // launch 6
}

// round 8
// speedup vs baseline: 2.3486x; 1.0350x over previous
#include <cuda_runtime.h>
#include <cuda_bf16.h>
#include <cstdint>

#define Nn   200
#define NP   256
#define Bx   8
#define NCH  6400
#define GW   192

typedef __nv_bfloat16 bf16;
typedef __nv_bfloat162 bf162;

// ---------------- static scratch ----------------
__device__ float g_d0[NP];
__device__ float g_d1[NP];
__device__ float g_Afp[NP*NP];
__device__ float g_Rtf[NP*NP];
__device__ float g_R2f[NP*NP];
__device__ bf16  gA_h[NP*NP],  gA_l[NP*NP];
__device__ bf16  gRt_h[NP*NP], gRt_l[NP*NP];
__device__ bf16  gR2_h[NP*NP], gR2_l[NP*NP];
__device__ bf16  gX_h[(size_t)Bx*NP*NCH],  gX_l[(size_t)Bx*NP*NCH];
__device__ bf16  gY1_h[(size_t)Bx*NP*NCH], gY1_l[(size_t)Bx*NP*NCH];
__device__ bf16  gY2_h[(size_t)Bx*NP*NCH], gY2_l[(size_t)Bx*NP*NCH];
__device__ bf16  gW_h[128*GW], gW_l[128*GW];            // [k=128][n=192]

// ---------------- prep kernels ----------------
__global__ void k_deg(const float* __restrict__ adj) {
    int i = threadIdx.x;
    if (i < Nn) {
        float cs = 0.f, rs = 0.f;
        for (int b = 0; b < Nn; b++) if (b != i) cs += adj[b*Nn + i];
        for (int e = 0; e < Nn; e++) if (e != i) rs += adj[i*Nn + e];
        g_d0[i] = (cs > 0.f) ? rsqrtf(cs) : 0.f;
        g_d1[i] = (rs > 0.f) ? rsqrtf(rs) : 0.f;
    }
}
__global__ void k_buildA(const float* __restrict__ adj) {
    int idx = blockIdx.x * blockDim.x + threadIdx.x;
    if (idx < NP*NP) {
        int e = idx / NP, b = idx % NP;
        float v = 0.f;
        if (e < Nn && b < Nn && e != b) v = g_d0[b] * adj[b*Nn + e] * g_d1[e];
        g_Afp[e*NP + b] = v;
        g_Rtf[b*NP + e] = v;
    }
}
__global__ void k_R2() {
    __shared__ float a[16][17], b[16][17];
    int tx = threadIdx.x, ty = threadIdx.y;
    int j = blockIdx.y*16 + ty, q = blockIdx.x*16 + tx;
    float s = 0.f;
    for (int p0 = 0; p0 < NP; p0 += 16) {
        a[ty][tx] = g_Rtf[j*NP + p0 + tx];
        b[ty][tx] = g_Rtf[(p0+ty)*NP + q];
        __syncthreads();
        #pragma unroll
        for (int p = 0; p < 16; p++) s += a[ty][p]*b[p][tx];
        __syncthreads();
    }
    g_R2f[j*NP + q] = 2.f*s;
}
__global__ void k_prepsplit(const float* __restrict__ x, const float* __restrict__ w) {
    int b = blockIdx.x;
    int tid = threadIdx.x;
    if (b < 768) {
        int which = b / 256;
        const float* s; bf16 *h, *l;
        if (which == 0)      { s = g_Afp; h = gA_h;  l = gA_l;  }
        else if (which == 1) { s = g_Rtf; h = gRt_h; l = gRt_l; }
        else                 { s = g_R2f; h = gR2_h; l = gR2_l; }
        int i = (b % 256)*256 + tid;
        float v = s[i];
        bf16 hh = __float2bfloat16(v);
        h[i] = hh;
        l[i] = __float2bfloat16(v - __bfloat162float(hh));
    } else if (b < 768 + 51200) {
        size_t i = (size_t)(b - 768)*256 + tid;
        int col = (int)(i % NCH);
        int r   = (int)((i / NCH) % NP);
        int bb  = (int)(i / ((size_t)NP*NCH));
        float v = (r < Nn) ? x[((size_t)bb*Nn + r)*NCH + col] : 0.f;
        bf16 hh = __float2bfloat16(v);
        gX_h[i] = hh;
        gX_l[i] = __float2bfloat16(v - __bfloat162float(hh));
    } else {
        int i = (b - 768 - 51200)*256 + tid;
        int k = i / GW, n = i % GW;
        float v = 0.f;
        if (k < 96) {
            int k1 = k / 32, c = k & 31;
            int k2 = n / 64, o = n & 63;
            v = w[o*288 + (k1*3 + k2)*32 + c];
        }
        bf16 hh = __float2bfloat16(v);
        gW_h[i] = hh;
        gW_l[i] = __float2bfloat16(v - __bfloat162float(hh));
    }
}

// ---------------- mma/async helpers ----------------
static __device__ __forceinline__ unsigned sptr(const void* p) {
    return (unsigned)__cvta_generic_to_shared(p);
}
static __device__ __forceinline__ void mma_bf16(float* c, const unsigned* a, const unsigned* b) {
    asm volatile("mma.sync.aligned.m16n8k16.row.col.f32.bf16.bf16.f32 "
        "{%0,%1,%2,%3},{%4,%5,%6,%7},{%8,%9},{%0,%1,%2,%3};\n"
        : "+f"(c[0]), "+f"(c[1]), "+f"(c[2]), "+f"(c[3])
        : "r"(a[0]), "r"(a[1]), "r"(a[2]), "r"(a[3]), "r"(b[0]), "r"(b[1]));
}
static __device__ __forceinline__ void mma_bf16_k8(float* c, const unsigned* a, unsigned b) {
    asm volatile("mma.sync.aligned.m16n8k8.row.col.f32.bf16.bf16.f32 "
        "{%0,%1,%2,%3},{%4,%5},{%6},{%0,%1,%2,%3};\n"
        : "+f"(c[0]), "+f"(c[1]), "+f"(c[2]), "+f"(c[3])
        : "r"(a[0]), "r"(a[1]), "r"(b));
}
#define LDB2(bq, addr) asm volatile( \
    "ldmatrix.sync.aligned.m8n8.x2.trans.shared.b16 {%0,%1},[%2];" \
    : "=r"((bq)[0]), "=r"((bq)[1]) : "r"(addr))
#define LDB1(b, addr) asm volatile( \
    "ldmatrix.sync.aligned.m8n8.x1.trans.shared.b16 {%0},[%1];" \
    : "=r"(b) : "r"(addr))
#define LDA4(aq, addr) asm volatile( \
    "ldmatrix.sync.aligned.m8n8.x4.shared.b16 {%0,%1,%2,%3},[%4];" \
    : "=r"((aq)[0]), "=r"((aq)[1]), "=r"((aq)[2]), "=r"((aq)[3]) : "r"(addr))
#define LDA2(aq, addr) asm volatile( \
    "ldmatrix.sync.aligned.m8n8.x2.shared.b16 {%0,%1},[%2];" \
    : "=r"((aq)[0]), "=r"((aq)[1]) : "r"(addr))

#define SM_STRIDE 72

#define CPA(dst, src, sz) asm volatile( \
    "cp.async.cg.shared.global [%0], [%1], 16, %2;" :: "r"(dst), "l"(src), "r"(sz))
#define CPA_COMMIT() asm volatile("cp.async.commit_group;")
template<int N>
static __device__ __forceinline__ void cpa_wait() {
    asm volatile("cp.async.wait_group %0;" :: "n"(N));
}

// MTx16(M) x 64(N) x KSN*16(K), 3-pass split; A via ldmatrix.x4 (AS elems, 16B-aligned rows)
template<int MT, int KSN, int AS, int BS>
static __device__ __forceinline__ void mma_stageG(float (*acc)[4][4],
        const bf16* Ah, const bf16* Al, const bf16* Bh, const bf16* Bl,
        int wm0, int wn0) {
    int lane = threadIdx.x & 31;
    int arow = lane & 15;
    int acol = (lane >> 4) * 8;
    #pragma unroll
    for (int kk = 0; kk < KSN; kk++) {
        int kb = kk*16;
        unsigned aH[MT][4], aL[MT][4], bH[4][2], bL[4][2];
        #pragma unroll
        for (int mt = 0; mt < MT; mt++) {
            int r = wm0 + mt*16 + arow;
            LDA4(aH[mt], sptr(Ah + r*AS + kb + acol));
            LDA4(aL[mt], sptr(Al + r*AS + kb + acol));
        }
        int rr = kb + (lane & 15);
        #pragma unroll
        for (int nt = 0; nt < 4; nt++) {
            LDB2(bH[nt], sptr(Bh + rr*BS + wn0 + nt*8));
            LDB2(bL[nt], sptr(Bl + rr*BS + wn0 + nt*8));
        }
        #pragma unroll
        for (int mt = 0; mt < MT; mt++)
            #pragma unroll
            for (int nt = 0; nt < 4; nt++) {
                mma_bf16(acc[mt][nt], aH[mt], bH[nt]);
                mma_bf16(acc[mt][nt], aH[mt], bL[nt]);
                mma_bf16(acc[mt][nt], aL[mt], bH[nt]);
            }
    }
}

// single k8 step (3-pass)
template<int MT, int AS, int BS>
static __device__ __forceinline__ void mma_k8stage(float (*acc)[4][4],
        const bf16* Ah, const bf16* Al, const bf16* Bh, const bf16* Bl,
        int wm0, int wn0) {
    int lane = threadIdx.x & 31;
    int arow = lane & 15;
    unsigned aH[MT][2], aL[MT][2], bH[4], bL[4];
    #pragma unroll
    for (int mt = 0; mt < MT; mt++) {
        int r = wm0 + mt*16 + arow;
        LDA2(aH[mt], sptr(Ah + r*AS));
        LDA2(aL[mt], sptr(Al + r*AS));
    }
    int rr = lane & 7;
    #pragma unroll
    for (int nt = 0; nt < 4; nt++) {
        LDB1(bH[nt], sptr(Bh + rr*BS + wn0 + nt*8));
        LDB1(bL[nt], sptr(Bl + rr*BS + wn0 + nt*8));
    }
    #pragma unroll
    for (int mt = 0; mt < MT; mt++)
        #pragma unroll
        for (int nt = 0; nt < 4; nt++) {
            mma_bf16_k8(acc[mt][nt], aH[mt], bH[nt]);
            mma_bf16_k8(acc[mt][nt], aH[mt], bL[nt]);
            mma_bf16_k8(acc[mt][nt], aL[mt], bH[nt]);
        }
}

// ---------------- left: Y1 = A@X (mode0) ; Y2 = 2*A@Y1 - X (mode1) ----------
// grid (100, 2, 8), 256 threads, 128(M)x64(N) tile, double-buffered K chunks.
#define LA_B  (128*SM_STRIDE*2)      // 18432
#define LB_B  (64*SM_STRIDE*2)       // 9216
#define LCH   (2*LA_B + 2*LB_B)      // 55296 per chunk buffer
#define LEFT_SMEM (2*LCH)            // 110592

__global__ __launch_bounds__(256) void k_left_mma(int mode, const float* __restrict__ xf32) {
    extern __shared__ __align__(128) char smem[];
    unsigned sb = sptr(smem);
    int n0 = blockIdx.x*64, e0 = blockIdx.y*128, b = blockIdx.z;
    const bf16* Bhs = mode ? gY1_h : gX_h;
    const bf16* Bls = mode ? gY1_l : gX_l;
    bf16* Oh = mode ? gY2_h : gY1_h;
    bf16* Ol = mode ? gY2_l : gY1_l;
    int tid = threadIdx.x;

    float acc[2][4][4];
    #pragma unroll
    for (int i = 0; i < 2; i++) for (int j = 0; j < 4; j++) for (int r = 0; r < 4; r++) acc[i][j][r] = 0.f;

    auto load_chunk = [&](int c, int st) {
        unsigned base = sb + st*LCH;
        // A: 128 x 64 (h then l)
        #pragma unroll
        for (int i = 0; i < 4; i++) {
            int u = tid + i*256, r = u >> 3, s = u & 7;
            CPA(base + r*(SM_STRIDE*2) + s*16,          gA_h + (size_t)(e0 + r)*NP + c*64 + s*8, 16);
            CPA(base + LA_B + r*(SM_STRIDE*2) + s*16,   gA_l + (size_t)(e0 + r)*NP + c*64 + s*8, 16);
        }
        // B: 64 x 64 (h then l)
        #pragma unroll
        for (int i = 0; i < 2; i++) {
            int u = tid + i*256, r = u >> 3, s = u & 7;
            CPA(base + 2*LA_B + r*(SM_STRIDE*2) + s*16,        Bhs + ((size_t)b*NP + c*64 + r)*NCH + n0 + s*8, 16);
            CPA(base + 2*LA_B + LB_B + r*(SM_STRIDE*2) + s*16, Bls + ((size_t)b*NP + c*64 + r)*NCH + n0 + s*8, 16);
        }
        CPA_COMMIT();
    };

    int warp = tid >> 5;
    int wm0 = (warp >> 1)*32, wn0 = (warp & 1)*32;

    load_chunk(0, 0);
    #pragma unroll
    for (int c = 0; c < 4; c++) {
        if (c < 3) { load_chunk(c+1, (c+1)&1); cpa_wait<1>(); }
        else       cpa_wait<0>();
        __syncthreads();
        const char* base = smem + (c&1)*LCH;
        const bf16* Ah = (const bf16*)base;
        const bf16* Al = (const bf16*)(base + LA_B);
        const bf16* Bh = (const bf16*)(base + 2*LA_B);
        const bf16* Bl = (const bf16*)(base + 2*LA_B + LB_B);
        if (c == 3) mma_stageG<2,1,SM_STRIDE,SM_STRIDE>(acc, Ah, Al, Bh, Bl, wm0, wn0);
        else        mma_stageG<2,4,SM_STRIDE,SM_STRIDE>(acc, Ah, Al, Bh, Bl, wm0, wn0);
        __syncthreads();
    }

    int lane = tid & 31;
    int g = lane >> 2, tig = lane & 3;
    #pragma unroll
    for (int mt = 0; mt < 2; mt++)
        #pragma unroll
        for (int nt = 0; nt < 4; nt++) {
            int col = n0 + wn0 + nt*8 + tig*2;
            #pragma unroll
            for (int rh = 0; rh < 2; rh++) {
                int row = e0 + wm0 + mt*16 + g + rh*8;
                float v0 = acc[mt][nt][rh*2+0], v1 = acc[mt][nt][rh*2+1];
                if (mode) {
                    if (row < Nn) {
                        const float* xp = xf32 + ((size_t)b*Nn + row)*NCH + col;
                        v0 = 2.f*v0 - xp[0];
                        v1 = 2.f*v1 - xp[1];
                    } else { v0 = 0.f; v1 = 0.f; }
                }
                bf16 h0 = __float2bfloat16(v0), h1 = __float2bfloat16(v1);
                bf16 l0 = __float2bfloat16(v0 - __bfloat162float(h0));
                bf16 l1 = __float2bfloat16(v1 - __bfloat162float(h1));
                size_t di = ((size_t)b*NP + row)*NCH + col;
                bf162 ph; ph.x = h0; ph.y = h1;
                bf162 pl; pl.x = l0; pl.y = l1;
                *(bf162*)(Oh + di) = ph;
                *(bf162*)(Ol + di) = pl;
            }
        }
}

// ---------------- fused mix+right, 256 threads ------------------------------
#define GSTR     200
#define OFF_GH   0
#define OFF_GL   80000
#define OFF_POOL 160000
// phase1 pool
#define P1_S(t,hl)  (OFF_POOL + (t)*26624 + (hl)*13312)   // 64 x 104 bf16
#define P1_W(hl)    (OFF_POOL + 53248 + (hl)*6912)        // 48 x 72 bf16
// phase2 pool (64-row A tiles, stride 72)
#define P2_AB       (64*SM_STRIDE*2)                      // 9216
#define P2_A(st,hl) (OFF_POOL + (st)*(2*P2_AB) + (hl)*P2_AB)
#define FUSED_SMEM  227072

__global__ __launch_bounds__(256) void k_fused(const float* __restrict__ bias,
                                               float* __restrict__ out) {
    extern __shared__ __align__(128) char smem[];
    unsigned sb = sptr(smem);
    int bi = blockIdx.x;
    int bb = bi / Nn, ii = bi % Nn;
    size_t abase = ((size_t)(bb*NP + ii))*NCH;
    int tid = threadIdx.x;
    int lane = tid & 31, warp = tid >> 5;
    int g = lane >> 2, tig = lane & 3;

    bf16* Ghp = (bf16*)(smem + OFF_GH);
    bf16* Glp = (bf16*)(smem + OFF_GL);

    // ---- phase 1 ----
    int g2 = warp >> 2;
    int wl = warp & 3;
    int p1m0 = (wl >> 1)*32, p1n0 = (wl & 1)*32;

    for (int qp = 0; qp < 2; qp++) {
        int q0 = qp*128;
        #pragma unroll
        for (int i = 0; i < 6; i++) {
            int u = tid + i*256;
            int t = u / 768, rem = u % 768;
            int r = rem / 12, s = rem % 12;
            int q = q0 + t*64 + r;
            int seg = s >> 2, cc = (s & 3)*8;
            int sz = (q < Nn) ? 16 : 0;
            int qq = (q < Nn) ? q : 0;
            size_t off = abase + (size_t)qq*32 + cc;
            const bf16 *ph, *pl;
            if (seg == 0)      { ph = gX_h  + off; pl = gX_l  + off; }
            else if (seg == 1) { ph = gY1_h + off; pl = gY1_l + off; }
            else               { ph = gY2_h + off; pl = gY2_l + off; }
            unsigned d = r*208 + s*16;
            CPA(sb + P1_S(t,0) + d, ph, sz);
            CPA(sb + P1_S(t,1) + d, pl, sz);
        }
        CPA_COMMIT();
        cpa_wait<0>();
        __syncthreads();

        const bf16* Sh = (const bf16*)(smem + P1_S(g2,0));
        const bf16* Sl = (const bf16*)(smem + P1_S(g2,1));

        for (int nt3 = 0; nt3 < 3; nt3++) {
            int n0g = nt3*64;
            float acc[2][4][4];
            #pragma unroll
            for (int i = 0; i < 2; i++) for (int j = 0; j < 4; j++) for (int r = 0; r < 4; r++) acc[i][j][r] = 0.f;

            #pragma unroll
            for (int half = 0; half < 2; half++) {
                #pragma unroll
                for (int i = 0; i < 3; i++) {
                    int u = tid + i*256;
                    int hl = u / 384, rem = u % 384;
                    int r = rem >> 3, s = rem & 7;
                    const bf16* wsrc = (hl ? gW_l : gW_h) + (size_t)(half*48 + r)*GW + n0g + s*8;
                    CPA(sb + P1_W(hl) + r*144 + s*16, wsrc, 16);
                }
                CPA_COMMIT();
                cpa_wait<0>();
                __syncthreads();
                mma_stageG<2,3,104,SM_STRIDE>(acc, Sh + half*48, Sl + half*48,
                    (const bf16*)(smem + P1_W(0)), (const bf16*)(smem + P1_W(1)),
                    p1m0, p1n0);
                __syncthreads();
            }
            #pragma unroll
            for (int mt = 0; mt < 2; mt++)
                #pragma unroll
                for (int nt = 0; nt < 4; nt++) {
                    int col = n0g + p1n0 + nt*8 + tig*2;
                    #pragma unroll
                    for (int rh = 0; rh < 2; rh++) {
                        int row = q0 + g2*64 + p1m0 + mt*16 + g + rh*8;
                        if (row < Nn) {
                            float v0 = acc[mt][nt][rh*2+0], v1 = acc[mt][nt][rh*2+1];
                            bf16 h0 = __float2bfloat16(v0), h1 = __float2bfloat16(v1);
                            bf16 l0 = __float2bfloat16(v0 - __bfloat162float(h0));
                            bf16 l1 = __float2bfloat16(v1 - __bfloat162float(h1));
                            bf162 ph; ph.x = h0; ph.y = h1;
                            bf162 pl; pl.x = l0; pl.y = l1;
                            *(bf162*)(Ghp + row*GSTR + col) = ph;
                            *(bf162*)(Glp + row*GSTR + col) = pl;
                        }
                    }
                }
        }
        __syncthreads();
    }

    // ---- phase 2: 64-row j-tiles, MT=1 warp mapping ----
    int mw = (warp >> 1)*16, nw = (warp & 1)*32;

    for (int jt = 0; jt < 4; jt++) {
        int j0 = jt*64;
        float acc[1][4][4];
        #pragma unroll
        for (int j = 0; j < 4; j++) for (int r = 0; r < 4; r++) acc[0][j][r] = 0.f;

        auto load_chunk = [&](int c, int st) {
            int phse = c >> 2, kq0 = (c & 3)*64;
            const bf16* Ahs = phse ? gR2_h : gRt_h;
            const bf16* Als = phse ? gR2_l : gRt_l;
            #pragma unroll
            for (int i = 0; i < 4; i++) {
                int u = tid + i*256;
                int hl = u >> 9, rem = u & 511;
                int r = rem >> 3, s = rem & 7;
                const bf16* src = (hl ? Als : Ahs) + (size_t)(j0 + r)*NP + kq0 + s*8;
                CPA(sb + P2_A(st,hl) + r*(SM_STRIDE*2) + s*16, src, 16);
            }
            CPA_COMMIT();
        };

        load_chunk(0, 0);
        #pragma unroll
        for (int c = 0; c < 8; c++) {
            if (c < 7) { load_chunk(c+1, (c+1)&1); cpa_wait<1>(); }
            else       cpa_wait<0>();
            __syncthreads();
            int phse = c >> 2, kc = c & 3;
            const bf16* Ah = (const bf16*)(smem + P2_A(c&1,0));
            const bf16* Al = (const bf16*)(smem + P2_A(c&1,1));
            int coff = phse ? 128 : 64;
            const bf16* Bh = Ghp + kc*64*GSTR + coff;
            const bf16* Bl = Glp + kc*64*GSTR + coff;
            if (kc == 3) mma_k8stage<1,SM_STRIDE,GSTR>(acc, Ah, Al, Bh, Bl, mw, nw);
            else         mma_stageG<1,4,SM_STRIDE,GSTR>(acc, Ah, Al, Bh, Bl, mw, nw);
            __syncthreads();
        }

        #pragma unroll
        for (int nt = 0; nt < 4; nt++) {
            int o = nw + nt*8 + tig*2;
            #pragma unroll
            for (int rh = 0; rh < 2; rh++) {
                int j = j0 + mw + g + rh*8;
                if (j < Nn) {
                    float v0 = acc[0][nt][rh*2+0], v1 = acc[0][nt][rh*2+1];
                    int gr = j*GSTR;
                    float g0a = __bfloat162float(Ghp[gr + o])       + __bfloat162float(Glp[gr + o]);
                    float g0b = __bfloat162float(Ghp[gr + o + 1])   + __bfloat162float(Glp[gr + o + 1]);
                    float g2a = __bfloat162float(Ghp[gr + 128 + o]) + __bfloat162float(Glp[gr + 128 + o]);
                    float g2b = __bfloat162float(Ghp[gr + 128 + o + 1]) + __bfloat162float(Glp[gr + 128 + o + 1]);
                    size_t oi = ((size_t)bi*Nn + j)*64 + o;
                    out[oi]     = bias[o]     + g0a - g2a + v0;
                    out[oi + 1] = bias[o + 1] + g0b - g2b + v1;
                }
            }
        }
    }
}

// ---------------------------------------------------------------------------
extern "C" void kernel_launch(void* const* d_in, const int* in_sizes, int n_in,
                              void* d_out, int out_size) {
    const float* x    = (const float*)d_in[0];
    const float* adj  = (const float*)d_in[1];
    const float* w    = (const float*)d_in[2];
    const float* bias = (const float*)d_in[3];
    float* out = (float*)d_out;

    cudaFuncSetAttribute(k_left_mma, cudaFuncAttributeMaxDynamicSharedMemorySize, LEFT_SMEM);
    cudaFuncSetAttribute(k_fused,    cudaFuncAttributeMaxDynamicSharedMemorySize, FUSED_SMEM);

    k_deg<<<1, 256>>>(adj);
    k_buildA<<<(NP*NP + 255)/256, 256>>>(adj);
    k_R2<<<dim3(16, 16), dim3(16, 16)>>>();
    k_prepsplit<<<768 + 51200 + 96, 256>>>(x, w);

    dim3 gl(NCH/64, 2, Bx);                               // (100, 2, 8)
    k_left_mma<<<gl, 256, LEFT_SMEM>>>(0, x);
    k_left_mma<<<gl, 256, LEFT_SMEM>>>(1, x);             // <- ncu launch 5
    k_fused<<<1600, 256, FUSED_SMEM>>>(bias, out);
}

// round 9
// speedup vs baseline: 2.4026x; 1.0230x over previous
#include <cuda_runtime.h>
#include <cuda_bf16.h>
#include <cstdint>

#define Nn   200
#define NP   256
#define Bx   8
#define NCH  6400
#define GW   192

typedef __nv_bfloat16 bf16;
typedef __nv_bfloat162 bf162;

// ---------------- static scratch ----------------
__device__ float g_d0[NP];
__device__ float g_d1[NP];
__device__ float g_Afp[NP*NP];
__device__ float g_Rtf[NP*NP];
__device__ float g_R2f[NP*NP];
__device__ bf16  gA_h[NP*NP],  gA_l[NP*NP];
__device__ bf16  gRt_h[NP*NP], gRt_l[NP*NP];
__device__ bf16  gR2_h[NP*NP], gR2_l[NP*NP];
__device__ bf16  gX_h[(size_t)Bx*NP*NCH],  gX_l[(size_t)Bx*NP*NCH];
__device__ bf16  gY1_h[(size_t)Bx*NP*NCH], gY1_l[(size_t)Bx*NP*NCH];
__device__ bf16  gY2_h[(size_t)Bx*NP*NCH], gY2_l[(size_t)Bx*NP*NCH];
__device__ bf16  gW_h[128*GW], gW_l[128*GW];            // [k=128][n=192]

// ---------------- prep kernels ----------------
__global__ void k_deg(const float* __restrict__ adj) {
    int i = threadIdx.x;
    if (i < Nn) {
        float cs = 0.f, rs = 0.f;
        for (int b = 0; b < Nn; b++) if (b != i) cs += adj[b*Nn + i];
        for (int e = 0; e < Nn; e++) if (e != i) rs += adj[i*Nn + e];
        g_d0[i] = (cs > 0.f) ? rsqrtf(cs) : 0.f;
        g_d1[i] = (rs > 0.f) ? rsqrtf(rs) : 0.f;
    }
}
__global__ void k_buildA(const float* __restrict__ adj) {
    int idx = blockIdx.x * blockDim.x + threadIdx.x;
    if (idx < NP*NP) {
        int e = idx / NP, b = idx % NP;
        float v = 0.f;
        if (e < Nn && b < Nn && e != b) v = g_d0[b] * adj[b*Nn + e] * g_d1[e];
        g_Afp[e*NP + b] = v;
        g_Rtf[b*NP + e] = v;
    }
}
__global__ void k_R2() {
    __shared__ float a[16][17], b[16][17];
    int tx = threadIdx.x, ty = threadIdx.y;
    int j = blockIdx.y*16 + ty, q = blockIdx.x*16 + tx;
    float s = 0.f;
    for (int p0 = 0; p0 < NP; p0 += 16) {
        a[ty][tx] = g_Rtf[j*NP + p0 + tx];
        b[ty][tx] = g_Rtf[(p0+ty)*NP + q];
        __syncthreads();
        #pragma unroll
        for (int p = 0; p < 16; p++) s += a[ty][p]*b[p][tx];
        __syncthreads();
    }
    g_R2f[j*NP + q] = 2.f*s;
}
__global__ void k_prepsplit(const float* __restrict__ x, const float* __restrict__ w) {
    int b = blockIdx.x;
    int tid = threadIdx.x;
    if (b < 768) {
        int which = b / 256;
        const float* s; bf16 *h, *l;
        if (which == 0)      { s = g_Afp; h = gA_h;  l = gA_l;  }
        else if (which == 1) { s = g_Rtf; h = gRt_h; l = gRt_l; }
        else                 { s = g_R2f; h = gR2_h; l = gR2_l; }
        int i = (b % 256)*256 + tid;
        float v = s[i];
        bf16 hh = __float2bfloat16(v);
        h[i] = hh;
        l[i] = __float2bfloat16(v - __bfloat162float(hh));
    } else if (b < 768 + 51200) {
        size_t i = (size_t)(b - 768)*256 + tid;
        int col = (int)(i % NCH);
        int r   = (int)((i / NCH) % NP);
        int bb  = (int)(i / ((size_t)NP*NCH));
        float v = (r < Nn) ? x[((size_t)bb*Nn + r)*NCH + col] : 0.f;
        bf16 hh = __float2bfloat16(v);
        gX_h[i] = hh;
        gX_l[i] = __float2bfloat16(v - __bfloat162float(hh));
    } else {
        int i = (b - 768 - 51200)*256 + tid;
        int k = i / GW, n = i % GW;
        float v = 0.f;
        if (k < 96) {
            int k1 = k / 32, c = k & 31;
            int k2 = n / 64, o = n & 63;
            v = w[o*288 + (k1*3 + k2)*32 + c];
        }
        bf16 hh = __float2bfloat16(v);
        gW_h[i] = hh;
        gW_l[i] = __float2bfloat16(v - __bfloat162float(hh));
    }
}

// ---------------- mma/async helpers ----------------
static __device__ __forceinline__ unsigned sptr(const void* p) {
    return (unsigned)__cvta_generic_to_shared(p);
}
static __device__ __forceinline__ void mma_bf16(float* c, const unsigned* a, const unsigned* b) {
    asm volatile("mma.sync.aligned.m16n8k16.row.col.f32.bf16.bf16.f32 "
        "{%0,%1,%2,%3},{%4,%5,%6,%7},{%8,%9},{%0,%1,%2,%3};\n"
        : "+f"(c[0]), "+f"(c[1]), "+f"(c[2]), "+f"(c[3])
        : "r"(a[0]), "r"(a[1]), "r"(a[2]), "r"(a[3]), "r"(b[0]), "r"(b[1]));
}
static __device__ __forceinline__ void mma_bf16_k8(float* c, const unsigned* a, unsigned b) {
    asm volatile("mma.sync.aligned.m16n8k8.row.col.f32.bf16.bf16.f32 "
        "{%0,%1,%2,%3},{%4,%5},{%6},{%0,%1,%2,%3};\n"
        : "+f"(c[0]), "+f"(c[1]), "+f"(c[2]), "+f"(c[3])
        : "r"(a[0]), "r"(a[1]), "r"(b));
}
#define LDB2(bq, addr) asm volatile( \
    "ldmatrix.sync.aligned.m8n8.x2.trans.shared.b16 {%0,%1},[%2];" \
    : "=r"((bq)[0]), "=r"((bq)[1]) : "r"(addr))
#define LDB1(b, addr) asm volatile( \
    "ldmatrix.sync.aligned.m8n8.x1.trans.shared.b16 {%0},[%1];" \
    : "=r"(b) : "r"(addr))
#define LDA4(aq, addr) asm volatile( \
    "ldmatrix.sync.aligned.m8n8.x4.shared.b16 {%0,%1,%2,%3},[%4];" \
    : "=r"((aq)[0]), "=r"((aq)[1]), "=r"((aq)[2]), "=r"((aq)[3]) : "r"(addr))
#define LDA2(aq, addr) asm volatile( \
    "ldmatrix.sync.aligned.m8n8.x2.shared.b16 {%0,%1},[%2];" \
    : "=r"((aq)[0]), "=r"((aq)[1]) : "r"(addr))

#define SM_STRIDE 72

#define CPA(dst, src, sz) asm volatile( \
    "cp.async.cg.shared.global [%0], [%1], 16, %2;" :: "r"(dst), "l"(src), "r"(sz))
#define CPA_COMMIT() asm volatile("cp.async.commit_group;")
template<int N>
static __device__ __forceinline__ void cpa_wait() {
    asm volatile("cp.async.wait_group %0;" :: "n"(N));
}

// MTx16(M) x 64(N) x KSN*16(K), 3-pass split; A via ldmatrix.x4
template<int MT, int KSN, int AS, int BS>
static __device__ __forceinline__ void mma_stageG(float (*acc)[4][4],
        const bf16* Ah, const bf16* Al, const bf16* Bh, const bf16* Bl,
        int wm0, int wn0) {
    int lane = threadIdx.x & 31;
    int arow = lane & 15;
    int acol = (lane >> 4) * 8;
    #pragma unroll
    for (int kk = 0; kk < KSN; kk++) {
        int kb = kk*16;
        unsigned aH[MT][4], aL[MT][4], bH[4][2], bL[4][2];
        #pragma unroll
        for (int mt = 0; mt < MT; mt++) {
            int r = wm0 + mt*16 + arow;
            LDA4(aH[mt], sptr(Ah + r*AS + kb + acol));
            LDA4(aL[mt], sptr(Al + r*AS + kb + acol));
        }
        int rr = kb + (lane & 15);
        #pragma unroll
        for (int nt = 0; nt < 4; nt++) {
            LDB2(bH[nt], sptr(Bh + rr*BS + wn0 + nt*8));
            LDB2(bL[nt], sptr(Bl + rr*BS + wn0 + nt*8));
        }
        #pragma unroll
        for (int mt = 0; mt < MT; mt++)
            #pragma unroll
            for (int nt = 0; nt < 4; nt++) {
                mma_bf16(acc[mt][nt], aH[mt], bH[nt]);
                mma_bf16(acc[mt][nt], aH[mt], bL[nt]);
                mma_bf16(acc[mt][nt], aL[mt], bH[nt]);
            }
    }
}

// single k8 step (3-pass)
template<int MT, int AS, int BS>
static __device__ __forceinline__ void mma_k8stage(float (*acc)[4][4],
        const bf16* Ah, const bf16* Al, const bf16* Bh, const bf16* Bl,
        int wm0, int wn0) {
    int lane = threadIdx.x & 31;
    int arow = lane & 15;
    unsigned aH[MT][2], aL[MT][2], bH[4], bL[4];
    #pragma unroll
    for (int mt = 0; mt < MT; mt++) {
        int r = wm0 + mt*16 + arow;
        LDA2(aH[mt], sptr(Ah + r*AS));
        LDA2(aL[mt], sptr(Al + r*AS));
    }
    int rr = lane & 7;
    #pragma unroll
    for (int nt = 0; nt < 4; nt++) {
        LDB1(bH[nt], sptr(Bh + rr*BS + wn0 + nt*8));
        LDB1(bL[nt], sptr(Bl + rr*BS + wn0 + nt*8));
    }
    #pragma unroll
    for (int mt = 0; mt < MT; mt++)
        #pragma unroll
        for (int nt = 0; nt < 4; nt++) {
            mma_bf16_k8(acc[mt][nt], aH[mt], bH[nt]);
            mma_bf16_k8(acc[mt][nt], aH[mt], bL[nt]);
            mma_bf16_k8(acc[mt][nt], aL[mt], bH[nt]);
        }
}

// ---------------- left: Y1 = A@X (mode0) ; Y2 = 2*A@Y1 - X (mode1) ----------
// grid (100, 2, 8), 256 threads, 128(M)x64(N) tile, 2-stage, 1 sync/chunk.
#define LA_B  (128*SM_STRIDE*2)      // 18432
#define LB_B  (64*SM_STRIDE*2)       // 9216
#define LCH   (2*LA_B + 2*LB_B)      // 55296 per chunk buffer
#define LEFT_SMEM (2*LCH)            // 110592

__global__ __launch_bounds__(256) void k_left_mma(int mode, const float* __restrict__ xf32) {
    extern __shared__ __align__(128) char smem[];
    unsigned sb = sptr(smem);
    int n0 = blockIdx.x*64, e0 = blockIdx.y*128, b = blockIdx.z;
    const bf16* Bhs = mode ? gY1_h : gX_h;
    const bf16* Bls = mode ? gY1_l : gX_l;
    bf16* Oh = mode ? gY2_h : gY1_h;
    bf16* Ol = mode ? gY2_l : gY1_l;
    int tid = threadIdx.x;

    float acc[2][4][4];
    #pragma unroll
    for (int i = 0; i < 2; i++) for (int j = 0; j < 4; j++) for (int r = 0; r < 4; r++) acc[i][j][r] = 0.f;

    auto load_chunk = [&](int c, int st) {
        unsigned base = sb + st*LCH;
        #pragma unroll
        for (int i = 0; i < 4; i++) {
            int u = tid + i*256, r = u >> 3, s = u & 7;
            CPA(base + r*(SM_STRIDE*2) + s*16,          gA_h + (size_t)(e0 + r)*NP + c*64 + s*8, 16);
            CPA(base + LA_B + r*(SM_STRIDE*2) + s*16,   gA_l + (size_t)(e0 + r)*NP + c*64 + s*8, 16);
        }
        #pragma unroll
        for (int i = 0; i < 2; i++) {
            int u = tid + i*256, r = u >> 3, s = u & 7;
            CPA(base + 2*LA_B + r*(SM_STRIDE*2) + s*16,        Bhs + ((size_t)b*NP + c*64 + r)*NCH + n0 + s*8, 16);
            CPA(base + 2*LA_B + LB_B + r*(SM_STRIDE*2) + s*16, Bls + ((size_t)b*NP + c*64 + r)*NCH + n0 + s*8, 16);
        }
        CPA_COMMIT();
    };

    int warp = tid >> 5;
    int wm0 = (warp >> 1)*32, wn0 = (warp & 1)*32;

    load_chunk(0, 0);
    #pragma unroll
    for (int c = 0; c < 4; c++) {
        cpa_wait<0>();
        __syncthreads();
        if (c < 3) load_chunk(c+1, (c+1)&1);
        const char* base = smem + (c&1)*LCH;
        const bf16* Ah = (const bf16*)base;
        const bf16* Al = (const bf16*)(base + LA_B);
        const bf16* Bh = (const bf16*)(base + 2*LA_B);
        const bf16* Bl = (const bf16*)(base + 2*LA_B + LB_B);
        if (c == 3) mma_stageG<2,1,SM_STRIDE,SM_STRIDE>(acc, Ah, Al, Bh, Bl, wm0, wn0);
        else        mma_stageG<2,4,SM_STRIDE,SM_STRIDE>(acc, Ah, Al, Bh, Bl, wm0, wn0);
    }

    int lane = tid & 31;
    int g = lane >> 2, tig = lane & 3;
    #pragma unroll
    for (int mt = 0; mt < 2; mt++)
        #pragma unroll
        for (int nt = 0; nt < 4; nt++) {
            int col = n0 + wn0 + nt*8 + tig*2;
            #pragma unroll
            for (int rh = 0; rh < 2; rh++) {
                int row = e0 + wm0 + mt*16 + g + rh*8;
                float v0 = acc[mt][nt][rh*2+0], v1 = acc[mt][nt][rh*2+1];
                if (mode) {
                    if (row < Nn) {
                        const float* xp = xf32 + ((size_t)b*Nn + row)*NCH + col;
                        v0 = 2.f*v0 - xp[0];
                        v1 = 2.f*v1 - xp[1];
                    } else { v0 = 0.f; v1 = 0.f; }
                }
                bf16 h0 = __float2bfloat16(v0), h1 = __float2bfloat16(v1);
                bf16 l0 = __float2bfloat16(v0 - __bfloat162float(h0));
                bf16 l1 = __float2bfloat16(v1 - __bfloat162float(h1));
                size_t di = ((size_t)b*NP + row)*NCH + col;
                bf162 ph; ph.x = h0; ph.y = h1;
                bf162 pl; pl.x = l0; pl.y = l1;
                *(bf162*)(Oh + di) = ph;
                *(bf162*)(Ol + di) = pl;
            }
        }
}

// ---------------- fused mix+right, 256 threads ------------------------------
// Phase 1: 64-row q-chunks, single S buffer, 3-buffer W pipeline.
// Phase 2: 64-row j-tiles, 3-stage A pipeline, B = G smem.
#define GSTR     200
#define OFF_GH   0
#define OFF_GL   80000
#define OFF_POOL 160000
#define P1_S(hl)     (OFF_POOL + (hl)*13312)                 // 64 x 104 bf16
#define P1_W(buf,hl) (OFF_POOL + 26624 + (buf)*13824 + (hl)*6912)  // 48 x 72 bf16
#define P2_A(st,hl)  (OFF_POOL + (st)*18432 + (hl)*9216)     // 64 x 72 bf16
#define FUSED_SMEM   228096

__global__ __launch_bounds__(256) void k_fused(const float* __restrict__ bias,
                                               float* __restrict__ out) {
    extern __shared__ __align__(128) char smem[];
    unsigned sb = sptr(smem);
    int bi = blockIdx.x;
    int bb = bi / Nn, ii = bi % Nn;
    size_t abase = ((size_t)(bb*NP + ii))*NCH;
    int tid = threadIdx.x;
    int lane = tid & 31, warp = tid >> 5;
    int g = lane >> 2, tig = lane & 3;

    bf16* Ghp = (bf16*)(smem + OFF_GH);
    bf16* Glp = (bf16*)(smem + OFF_GL);

    auto loadW = [&](int st, int buf) {
        int nt3 = st >> 1, half = st & 1;
        #pragma unroll
        for (int i = 0; i < 3; i++) {
            int u = tid + i*256;
            int hl = u / 384, rem = u % 384;
            int r = rem >> 3, s = rem & 7;
            const bf16* wsrc = (hl ? gW_l : gW_h) + (size_t)(half*48 + r)*GW + nt3*64 + s*8;
            CPA(sb + P1_W(buf,hl) + r*144 + s*16, wsrc, 16);
        }
        CPA_COMMIT();
    };

    // ---- phase 1: M=64 per chunk, 8 warps -> 16 rows x 32 cols each ----
    int p1m0 = (warp >> 1)*16, p1n0 = (warp & 1)*32;

    for (int qp = 0; qp < 4; qp++) {
        int q0 = qp*64;
        __syncthreads();
        // S copies (group shared with W stage 0)
        #pragma unroll
        for (int i = 0; i < 3; i++) {
            int u = tid + i*256;
            int r = u / 12, s = u % 12;
            int q = q0 + r;
            int seg = s >> 2, cc = (s & 3)*8;
            int sz = (q < Nn) ? 16 : 0;
            int qq = (q < Nn) ? q : 0;
            size_t off = abase + (size_t)qq*32 + cc;
            const bf16 *ph, *pl;
            if (seg == 0)      { ph = gX_h  + off; pl = gX_l  + off; }
            else if (seg == 1) { ph = gY1_h + off; pl = gY1_l + off; }
            else               { ph = gY2_h + off; pl = gY2_l + off; }
            unsigned d = r*208 + s*16;
            CPA(sb + P1_S(0) + d, ph, sz);
            CPA(sb + P1_S(1) + d, pl, sz);
        }
        loadW(0, 0);   // commits {S, W0}
        loadW(1, 1);   // commits {W1}

        const bf16* Sh = (const bf16*)(smem + P1_S(0));
        const bf16* Sl = (const bf16*)(smem + P1_S(1));

        float acc1[1][4][4];
        #pragma unroll
        for (int st = 0; st < 6; st++) {
            if (st < 5) cpa_wait<1>(); else cpa_wait<0>();
            __syncthreads();
            if (st < 4) loadW(st+2, (st+2)%3);
            int nt3 = st >> 1, half = st & 1;
            const bf16* Wh = (const bf16*)(smem + P1_W(st%3,0));
            const bf16* Wl = (const bf16*)(smem + P1_W(st%3,1));
            if (half == 0) {
                #pragma unroll
                for (int j = 0; j < 4; j++) for (int r = 0; r < 4; r++) acc1[0][j][r] = 0.f;
            }
            mma_stageG<1,3,104,SM_STRIDE>(acc1, Sh + half*48, Sl + half*48, Wh, Wl, p1m0, p1n0);
            if (half == 1) {
                #pragma unroll
                for (int nt = 0; nt < 4; nt++) {
                    int col = nt3*64 + p1n0 + nt*8 + tig*2;
                    #pragma unroll
                    for (int rh = 0; rh < 2; rh++) {
                        int row = q0 + p1m0 + g + rh*8;
                        if (row < Nn) {
                            float v0 = acc1[0][nt][rh*2+0], v1 = acc1[0][nt][rh*2+1];
                            bf16 h0 = __float2bfloat16(v0), h1 = __float2bfloat16(v1);
                            bf16 l0 = __float2bfloat16(v0 - __bfloat162float(h0));
                            bf16 l1 = __float2bfloat16(v1 - __bfloat162float(h1));
                            bf162 ph; ph.x = h0; ph.y = h1;
                            bf162 pl; pl.x = l0; pl.y = l1;
                            *(bf162*)(Ghp + row*GSTR + col) = ph;
                            *(bf162*)(Glp + row*GSTR + col) = pl;
                        }
                    }
                }
            }
        }
    }

    // ---- phase 2: 64-row j-tiles, 3-stage A pipeline ----
    int mw = (warp >> 1)*16, nw = (warp & 1)*32;

    for (int jt = 0; jt < 4; jt++) {
        int j0 = jt*64;
        float acc[1][4][4];
        #pragma unroll
        for (int j = 0; j < 4; j++) for (int r = 0; r < 4; r++) acc[0][j][r] = 0.f;

        auto load_chunk = [&](int c, int st) {
            int phse = c >> 2, kq0 = (c & 3)*64;
            const bf16* Ahs = phse ? gR2_h : gRt_h;
            const bf16* Als = phse ? gR2_l : gRt_l;
            #pragma unroll
            for (int i = 0; i < 4; i++) {
                int u = tid + i*256;
                int hl = u >> 9, rem = u & 511;
                int r = rem >> 3, s = rem & 7;
                const bf16* src = (hl ? Als : Ahs) + (size_t)(j0 + r)*NP + kq0 + s*8;
                CPA(sb + P2_A(st,hl) + r*(SM_STRIDE*2) + s*16, src, 16);
            }
            CPA_COMMIT();
        };

        __syncthreads();
        load_chunk(0, 0);
        load_chunk(1, 1);
        #pragma unroll
        for (int c = 0; c < 8; c++) {
            if (c < 7) cpa_wait<1>(); else cpa_wait<0>();
            __syncthreads();
            if (c < 6) load_chunk(c+2, (c+2)%3);
            int phse = c >> 2, kc = c & 3;
            const bf16* Ah = (const bf16*)(smem + P2_A(c%3,0));
            const bf16* Al = (const bf16*)(smem + P2_A(c%3,1));
            int coff = phse ? 128 : 64;
            const bf16* Bh = Ghp + kc*64*GSTR + coff;
            const bf16* Bl = Glp + kc*64*GSTR + coff;
            if (kc == 3) mma_k8stage<1,SM_STRIDE,GSTR>(acc, Ah, Al, Bh, Bl, mw, nw);
            else         mma_stageG<1,4,SM_STRIDE,GSTR>(acc, Ah, Al, Bh, Bl, mw, nw);
        }

        #pragma unroll
        for (int nt = 0; nt < 4; nt++) {
            int o = nw + nt*8 + tig*2;
            #pragma unroll
            for (int rh = 0; rh < 2; rh++) {
                int j = j0 + mw + g + rh*8;
                if (j < Nn) {
                    float v0 = acc[0][nt][rh*2+0], v1 = acc[0][nt][rh*2+1];
                    int gr = j*GSTR;
                    float g0a = __bfloat162float(Ghp[gr + o])       + __bfloat162float(Glp[gr + o]);
                    float g0b = __bfloat162float(Ghp[gr + o + 1])   + __bfloat162float(Glp[gr + o + 1]);
                    float g2a = __bfloat162float(Ghp[gr + 128 + o]) + __bfloat162float(Glp[gr + 128 + o]);
                    float g2b = __bfloat162float(Ghp[gr + 128 + o + 1]) + __bfloat162float(Glp[gr + 128 + o + 1]);
                    size_t oi = ((size_t)bi*Nn + j)*64 + o;
                    out[oi]     = bias[o]     + g0a - g2a + v0;
                    out[oi + 1] = bias[o + 1] + g0b - g2b + v1;
                }
            }
        }
    }
}

// ---------------------------------------------------------------------------
extern "C" void kernel_launch(void* const* d_in, const int* in_sizes, int n_in,
                              void* d_out, int out_size) {
    const float* x    = (const float*)d_in[0];
    const float* adj  = (const float*)d_in[1];
    const float* w    = (const float*)d_in[2];
    const float* bias = (const float*)d_in[3];
    float* out = (float*)d_out;

    cudaFuncSetAttribute(k_left_mma, cudaFuncAttributeMaxDynamicSharedMemorySize, LEFT_SMEM);
    cudaFuncSetAttribute(k_fused,    cudaFuncAttributeMaxDynamicSharedMemorySize, FUSED_SMEM);

    k_deg<<<1, 256>>>(adj);
    k_buildA<<<(NP*NP + 255)/256, 256>>>(adj);
    k_R2<<<dim3(16, 16), dim3(16, 16)>>>();
    k_prepsplit<<<768 + 51200 + 96, 256>>>(x, w);

    dim3 gl(NCH/64, 2, Bx);                               // (100, 2, 8)
    k_left_mma<<<gl, 256, LEFT_SMEM>>>(0, x);
    k_left_mma<<<gl, 256, LEFT_SMEM>>>(1, x);             // <- ncu launch 5
    k_fused<<<1600, 256, FUSED_SMEM>>>(bias, out);
}

// round 12
// speedup vs baseline: 2.4728x; 1.0292x over previous
#include <cuda_runtime.h>
#include <cuda_bf16.h>
#include <cstdint>

#define Nn   200
#define NP   256
#define Bx   8
#define NCH  6400
#define GW   192

typedef __nv_bfloat16 bf16;
typedef __nv_bfloat162 bf162;

// ---------------- static scratch ----------------
__device__ float g_d0[NP];
__device__ float g_d1[NP];
__device__ float g_Afp[NP*NP];
__device__ float g_Rtf[NP*NP];
__device__ float g_R2f[NP*NP];
__device__ bf16  gA_h[NP*NP],  gA_l[NP*NP];
__device__ bf16  gRt_h[NP*NP], gRt_l[NP*NP];
__device__ bf16  gR2_h[NP*NP], gR2_l[NP*NP];
__device__ bf16  gX_h[(size_t)Bx*NP*NCH],  gX_l[(size_t)Bx*NP*NCH];
__device__ bf16  gY1_h[(size_t)Bx*NP*NCH], gY1_l[(size_t)Bx*NP*NCH];
__device__ bf16  gY2_h[(size_t)Bx*NP*NCH], gY2_l[(size_t)Bx*NP*NCH];
__device__ bf16  gW_h[128*GW], gW_l[128*GW];            // [k=128][n=192]

// ---------------- prep kernels ----------------
__global__ void k_deg(const float* __restrict__ adj) {
    int i = threadIdx.x;
    if (i < Nn) {
        float cs = 0.f, rs = 0.f;
        for (int b = 0; b < Nn; b++) if (b != i) cs += adj[b*Nn + i];
        for (int e = 0; e < Nn; e++) if (e != i) rs += adj[i*Nn + e];
        g_d0[i] = (cs > 0.f) ? rsqrtf(cs) : 0.f;
        g_d1[i] = (rs > 0.f) ? rsqrtf(rs) : 0.f;
    }
}
__global__ void k_buildA(const float* __restrict__ adj) {
    int idx = blockIdx.x * blockDim.x + threadIdx.x;
    if (idx < NP*NP) {
        int e = idx / NP, b = idx % NP;
        float v = 0.f;
        if (e < Nn && b < Nn && e != b) v = g_d0[b] * adj[b*Nn + e] * g_d1[e];
        g_Afp[e*NP + b] = v;
        g_Rtf[b*NP + e] = v;
    }
}
__global__ void k_R2() {
    __shared__ float a[16][17], b[16][17];
    int tx = threadIdx.x, ty = threadIdx.y;
    int j = blockIdx.y*16 + ty, q = blockIdx.x*16 + tx;
    float s = 0.f;
    for (int p0 = 0; p0 < NP; p0 += 16) {
        a[ty][tx] = g_Rtf[j*NP + p0 + tx];
        b[ty][tx] = g_Rtf[(p0+ty)*NP + q];
        __syncthreads();
        #pragma unroll
        for (int p = 0; p < 16; p++) s += a[ty][p]*b[p][tx];
        __syncthreads();
    }
    g_R2f[j*NP + q] = 2.f*s;
}
static __device__ __forceinline__ unsigned pack2(float a, float b) {
    bf162 t; t.x = __float2bfloat16(a); t.y = __float2bfloat16(b);
    return *reinterpret_cast<unsigned*>(&t);
}
__global__ void k_prepsplit(const float* __restrict__ x, const float* __restrict__ w) {
    int b = blockIdx.x;
    int tid = threadIdx.x;
    if (b < 768) {
        int which = b / 256;
        const float* s; bf16 *h, *l;
        if (which == 0)      { s = g_Afp; h = gA_h;  l = gA_l;  }
        else if (which == 1) { s = g_Rtf; h = gRt_h; l = gRt_l; }
        else                 { s = g_R2f; h = gR2_h; l = gR2_l; }
        int i = (b % 256)*256 + tid;
        float v = s[i];
        bf16 hh = __float2bfloat16(v);
        h[i] = hh;
        l[i] = __float2bfloat16(v - __bfloat162float(hh));
    } else if (b < 768 + 12800) {
        size_t i4 = ((size_t)(b - 768)*256 + tid) * 4;
        int col = (int)(i4 % NCH);
        int r   = (int)((i4 / NCH) % NP);
        int bb  = (int)(i4 / ((size_t)NP*NCH));
        float v0 = 0.f, v1 = 0.f, v2 = 0.f, v3 = 0.f;
        if (r < Nn) {
            const float4 xv = *reinterpret_cast<const float4*>(x + ((size_t)bb*Nn + r)*NCH + col);
            v0 = xv.x; v1 = xv.y; v2 = xv.z; v3 = xv.w;
        }
        bf16 h0 = __float2bfloat16(v0), h1 = __float2bfloat16(v1);
        bf16 h2 = __float2bfloat16(v2), h3 = __float2bfloat16(v3);
        float l0 = v0 - __bfloat162float(h0), l1 = v1 - __bfloat162float(h1);
        float l2 = v2 - __bfloat162float(h2), l3 = v3 - __bfloat162float(h3);
        bf162 ph0; ph0.x = h0; ph0.y = h1;
        bf162 ph1; ph1.x = h2; ph1.y = h3;
        uint2 hv = make_uint2(*reinterpret_cast<unsigned*>(&ph0), *reinterpret_cast<unsigned*>(&ph1));
        uint2 lv = make_uint2(pack2(l0, l1), pack2(l2, l3));
        *reinterpret_cast<uint2*>(gX_h + i4) = hv;
        *reinterpret_cast<uint2*>(gX_l + i4) = lv;
    } else {
        int i = (b - 768 - 12800)*256 + tid;
        int k = i / GW, n = i % GW;
        float v = 0.f;
        if (k < 96) {
            int k1 = k / 32, c = k & 31;
            int k2 = n / 64, o = n & 63;
            v = w[o*288 + (k1*3 + k2)*32 + c];
        }
        bf16 hh = __float2bfloat16(v);
        gW_h[i] = hh;
        gW_l[i] = __float2bfloat16(v - __bfloat162float(hh));
    }
}

// ---------------- mma/async helpers ----------------
static __device__ __forceinline__ unsigned sptr(const void* p) {
    return (unsigned)__cvta_generic_to_shared(p);
}
static __device__ __forceinline__ void mma_bf16(float* c, const unsigned* a, const unsigned* b) {
    asm volatile("mma.sync.aligned.m16n8k16.row.col.f32.bf16.bf16.f32 "
        "{%0,%1,%2,%3},{%4,%5,%6,%7},{%8,%9},{%0,%1,%2,%3};\n"
        : "+f"(c[0]), "+f"(c[1]), "+f"(c[2]), "+f"(c[3])
        : "r"(a[0]), "r"(a[1]), "r"(a[2]), "r"(a[3]), "r"(b[0]), "r"(b[1]));
}
static __device__ __forceinline__ void mma_bf16_k8(float* c, const unsigned* a, unsigned b) {
    asm volatile("mma.sync.aligned.m16n8k8.row.col.f32.bf16.bf16.f32 "
        "{%0,%1,%2,%3},{%4,%5},{%6},{%0,%1,%2,%3};\n"
        : "+f"(c[0]), "+f"(c[1]), "+f"(c[2]), "+f"(c[3])
        : "r"(a[0]), "r"(a[1]), "r"(b));
}
#define LDB2(bq, addr) asm volatile( \
    "ldmatrix.sync.aligned.m8n8.x2.trans.shared.b16 {%0,%1},[%2];" \
    : "=r"((bq)[0]), "=r"((bq)[1]) : "r"(addr))
#define LDB1(b, addr) asm volatile( \
    "ldmatrix.sync.aligned.m8n8.x1.trans.shared.b16 {%0},[%1];" \
    : "=r"(b) : "r"(addr))
#define LDA4(aq, addr) asm volatile( \
    "ldmatrix.sync.aligned.m8n8.x4.shared.b16 {%0,%1,%2,%3},[%4];" \
    : "=r"((aq)[0]), "=r"((aq)[1]), "=r"((aq)[2]), "=r"((aq)[3]) : "r"(addr))
#define LDA2(aq, addr) asm volatile( \
    "ldmatrix.sync.aligned.m8n8.x2.shared.b16 {%0,%1},[%2];" \
    : "=r"((aq)[0]), "=r"((aq)[1]) : "r"(addr))

#define SM_STRIDE 72

#define CPA(dst, src, sz) asm volatile( \
    "cp.async.cg.shared.global [%0], [%1], 16, %2;" :: "r"(dst), "l"(src), "r"(sz))
#define CPA_COMMIT() asm volatile("cp.async.commit_group;")
template<int N>
static __device__ __forceinline__ void cpa_wait() {
    asm volatile("cp.async.wait_group %0;" :: "n"(N));
}

// MTx16(M) x 64(N) x KSN*16(K), 3-pass split; A via ldmatrix.x4
template<int MT, int KSN, int AS, int BS>
static __device__ __forceinline__ void mma_stageG(float (*acc)[4][4],
        const bf16* Ah, const bf16* Al, const bf16* Bh, const bf16* Bl,
        int wm0, int wn0) {
    int lane = threadIdx.x & 31;
    int arow = lane & 15;
    int acol = (lane >> 4) * 8;
    #pragma unroll
    for (int kk = 0; kk < KSN; kk++) {
        int kb = kk*16;
        unsigned aH[MT][4], aL[MT][4], bH[4][2], bL[4][2];
        #pragma unroll
        for (int mt = 0; mt < MT; mt++) {
            int r = wm0 + mt*16 + arow;
            LDA4(aH[mt], sptr(Ah + r*AS + kb + acol));
            LDA4(aL[mt], sptr(Al + r*AS + kb + acol));
        }
        int rr = kb + (lane & 15);
        #pragma unroll
        for (int nt = 0; nt < 4; nt++) {
            LDB2(bH[nt], sptr(Bh + rr*BS + wn0 + nt*8));
            LDB2(bL[nt], sptr(Bl + rr*BS + wn0 + nt*8));
        }
        #pragma unroll
        for (int mt = 0; mt < MT; mt++)
            #pragma unroll
            for (int nt = 0; nt < 4; nt++) {
                mma_bf16(acc[mt][nt], aH[mt], bH[nt]);
                mma_bf16(acc[mt][nt], aH[mt], bL[nt]);
                mma_bf16(acc[mt][nt], aL[mt], bH[nt]);
            }
    }
}

// single k8 step (3-pass)
template<int MT, int AS, int BS>
static __device__ __forceinline__ void mma_k8stage(float (*acc)[4][4],
        const bf16* Ah, const bf16* Al, const bf16* Bh, const bf16* Bl,
        int wm0, int wn0) {
    int lane = threadIdx.x & 31;
    int arow = lane & 15;
    unsigned aH[MT][2], aL[MT][2], bH[4], bL[4];
    #pragma unroll
    for (int mt = 0; mt < MT; mt++) {
        int r = wm0 + mt*16 + arow;
        LDA2(aH[mt], sptr(Ah + r*AS));
        LDA2(aL[mt], sptr(Al + r*AS));
    }
    int rr = lane & 7;
    #pragma unroll
    for (int nt = 0; nt < 4; nt++) {
        LDB1(bH[nt], sptr(Bh + rr*BS + wn0 + nt*8));
        LDB1(bL[nt], sptr(Bl + rr*BS + wn0 + nt*8));
    }
    #pragma unroll
    for (int mt = 0; mt < MT; mt++)
        #pragma unroll
        for (int nt = 0; nt < 4; nt++) {
            mma_bf16_k8(acc[mt][nt], aH[mt], bH[nt]);
            mma_bf16_k8(acc[mt][nt], aH[mt], bL[nt]);
            mma_bf16_k8(acc[mt][nt], aL[mt], bH[nt]);
        }
}

// ---------------- fused left: Y1 = A@X, Y2 = 2*A@Y1 - X (one kernel) --------
// grid (100, 8), 256 threads. X block + Y1 block resident in smem.
#define XB_H   0
#define XB_L   36864
#define Y1S_H  73728
#define Y1S_L  110592
#define LA(st,hl) (147456 + (st)*40960 + (hl)*20480)   // 256 x 32 bf16, stride 40
#define LEFT_SMEM 229376

__global__ __launch_bounds__(256) void k_leftfused() {
    extern __shared__ __align__(128) char smem[];
    unsigned sb = sptr(smem);
    int n0 = blockIdx.x*64, b = blockIdx.y;
    int tid = threadIdx.x;
    int lane = tid & 31, warp = tid >> 5;
    int g = lane >> 2, tig = lane & 3;
    int wm0 = (warp >> 1)*64, wn0 = (warp & 1)*32;

    const bf16* XBh = (const bf16*)(smem + XB_H);
    const bf16* XBl = (const bf16*)(smem + XB_L);
    bf16* Y1h = (bf16*)(smem + Y1S_H);
    bf16* Y1l = (bf16*)(smem + Y1S_L);

    auto loadA = [&](int c, int st) {
        int k0 = c*32;
        #pragma unroll
        for (int i = 0; i < 8; i++) {
            int u = tid + i*256;
            int hl = u >> 10, rem = u & 1023;
            int r = rem >> 2, s = rem & 3;
            const bf16* src = (hl ? gA_l : gA_h) + (size_t)r*NP + k0 + s*8;
            CPA(sb + LA(st,hl) + r*80 + s*16, src, 16);
        }
        CPA_COMMIT();
    };

    // load X block (256 x 64 h/l) + first A chunk
    #pragma unroll
    for (int i = 0; i < 16; i++) {
        int u = tid + i*256;
        int hl = u >> 11, rem = u & 2047;
        int r = rem >> 3, s = rem & 7;
        const bf16* src = (hl ? gX_l : gX_h) + ((size_t)b*NP + r)*NCH + n0 + s*8;
        CPA(sb + (hl ? XB_L : XB_H) + r*144 + s*16, src, 16);
    }
    loadA(0, 0);   // commit covers X block + A0

    float acc[4][4][4];
    #pragma unroll
    for (int i = 0; i < 4; i++) for (int j = 0; j < 4; j++) for (int r = 0; r < 4; r++) acc[i][j][r] = 0.f;

    // ---- stage 1: Y1 = A @ X ----
    #pragma unroll
    for (int c = 0; c < 7; c++) {
        cpa_wait<0>();
        __syncthreads();
        if (c < 6) loadA(c+1, (c+1)&1);
        const bf16* Ah = (const bf16*)(smem + LA(c&1,0));
        const bf16* Al = (const bf16*)(smem + LA(c&1,1));
        if (c == 6) mma_k8stage<4,40,SM_STRIDE>(acc, Ah, Al, XBh + 192*SM_STRIDE, XBl + 192*SM_STRIDE, wm0, wn0);
        else        mma_stageG<4,2,40,SM_STRIDE>(acc, Ah, Al, XBh + c*32*SM_STRIDE, XBl + c*32*SM_STRIDE, wm0, wn0);
    }

    __syncthreads();          // all warps done with A buffers
    loadA(0, 0);              // prefetch stage-2 A chunk 0 (overlaps epilogue)

    // epilogue 1: split Y1 -> smem (all rows) + global (rows < Nn)
    #pragma unroll
    for (int mt = 0; mt < 4; mt++)
        #pragma unroll
        for (int nt = 0; nt < 4; nt++) {
            int col = wn0 + nt*8 + tig*2;
            #pragma unroll
            for (int rh = 0; rh < 2; rh++) {
                int row = wm0 + mt*16 + g + rh*8;
                float v0 = acc[mt][nt][rh*2+0], v1 = acc[mt][nt][rh*2+1];
                bf16 h0 = __float2bfloat16(v0), h1 = __float2bfloat16(v1);
                bf16 l0 = __float2bfloat16(v0 - __bfloat162float(h0));
                bf16 l1 = __float2bfloat16(v1 - __bfloat162float(h1));
                bf162 ph; ph.x = h0; ph.y = h1;
                bf162 pl; pl.x = l0; pl.y = l1;
                *(bf162*)(Y1h + row*SM_STRIDE + col) = ph;
                *(bf162*)(Y1l + row*SM_STRIDE + col) = pl;
                if (row < Nn) {
                    size_t di = ((size_t)b*NP + row)*NCH + n0 + col;
                    *(unsigned*)(gY1_h + di) = *reinterpret_cast<unsigned*>(&ph);
                    *(unsigned*)(gY1_l + di) = *reinterpret_cast<unsigned*>(&pl);
                }
            }
        }
    __syncthreads();          // Y1 smem visible to all; A0 load in flight

    #pragma unroll
    for (int i = 0; i < 4; i++) for (int j = 0; j < 4; j++) for (int r = 0; r < 4; r++) acc[i][j][r] = 0.f;

    // ---- stage 2: Y2 = 2*A @ Y1 - X ----
    #pragma unroll
    for (int c = 0; c < 7; c++) {
        cpa_wait<0>();
        __syncthreads();
        if (c < 6) loadA(c+1, (c+1)&1);
        const bf16* Ah = (const bf16*)(smem + LA(c&1,0));
        const bf16* Al = (const bf16*)(smem + LA(c&1,1));
        if (c == 6) mma_k8stage<4,40,SM_STRIDE>(acc, Ah, Al, Y1h + 192*SM_STRIDE, Y1l + 192*SM_STRIDE, wm0, wn0);
        else        mma_stageG<4,2,40,SM_STRIDE>(acc, Ah, Al, Y1h + c*32*SM_STRIDE, Y1l + c*32*SM_STRIDE, wm0, wn0);
    }

    // epilogue 2: Y2 = 2*acc - X (X from smem h+l), rows < Nn
    #pragma unroll
    for (int mt = 0; mt < 4; mt++)
        #pragma unroll
        for (int nt = 0; nt < 4; nt++) {
            int col = wn0 + nt*8 + tig*2;
            #pragma unroll
            for (int rh = 0; rh < 2; rh++) {
                int row = wm0 + mt*16 + g + rh*8;
                if (row < Nn) {
                    int xo = row*SM_STRIDE + col;
                    float x0 = __bfloat162float(XBh[xo])   + __bfloat162float(XBl[xo]);
                    float x1 = __bfloat162float(XBh[xo+1]) + __bfloat162float(XBl[xo+1]);
                    float v0 = 2.f*acc[mt][nt][rh*2+0] - x0;
                    float v1 = 2.f*acc[mt][nt][rh*2+1] - x1;
                    bf16 h0 = __float2bfloat16(v0), h1 = __float2bfloat16(v1);
                    bf16 l0 = __float2bfloat16(v0 - __bfloat162float(h0));
                    bf16 l1 = __float2bfloat16(v1 - __bfloat162float(h1));
                    bf162 ph; ph.x = h0; ph.y = h1;
                    bf162 pl; pl.x = l0; pl.y = l1;
                    size_t di = ((size_t)b*NP + row)*NCH + n0 + col;
                    *(unsigned*)(gY2_h + di) = *reinterpret_cast<unsigned*>(&ph);
                    *(unsigned*)(gY2_l + di) = *reinterpret_cast<unsigned*>(&pl);
                }
            }
        }
}

// ---------------- fused mix+right, 256 threads ------------------------------
#define GSTR     200
#define OFF_GH   0
#define OFF_GL   80000
#define OFF_POOL 160000
#define P1_S(hl)     (OFF_POOL + (hl)*13312)                 // 64 x 104 bf16
#define P1_W(buf,hl) (OFF_POOL + 26624 + (buf)*13824 + (hl)*6912)  // 48 x 72 bf16
#define P2_A(st,hl)  (OFF_POOL + (st)*18432 + (hl)*9216)     // 64 x 72 bf16
#define FUSED_SMEM   228096

__global__ __launch_bounds__(256) void k_fused(const float* __restrict__ bias,
                                               float* __restrict__ out) {
    extern __shared__ __align__(128) char smem[];
    unsigned sb = sptr(smem);
    int bi = blockIdx.x;
    int bb = bi / Nn, ii = bi % Nn;
    size_t abase = ((size_t)(bb*NP + ii))*NCH;
    int tid = threadIdx.x;
    int lane = tid & 31, warp = tid >> 5;
    int g = lane >> 2, tig = lane & 3;

    bf16* Ghp = (bf16*)(smem + OFF_GH);
    bf16* Glp = (bf16*)(smem + OFF_GL);

    auto loadW = [&](int st, int buf) {
        int nt3 = st >> 1, half = st & 1;
        #pragma unroll
        for (int i = 0; i < 3; i++) {
            int u = tid + i*256;
            int hl = u / 384, rem = u % 384;
            int r = rem >> 3, s = rem & 7;
            const bf16* wsrc = (hl ? gW_l : gW_h) + (size_t)(half*48 + r)*GW + nt3*64 + s*8;
            CPA(sb + P1_W(buf,hl) + r*144 + s*16, wsrc, 16);
        }
        CPA_COMMIT();
    };

    int p1m0 = (warp >> 1)*16, p1n0 = (warp & 1)*32;

    for (int qp = 0; qp < 4; qp++) {
        int q0 = qp*64;
        __syncthreads();
        #pragma unroll
        for (int i = 0; i < 3; i++) {
            int u = tid + i*256;
            int r = u / 12, s = u % 12;
            int q = q0 + r;
            int seg = s >> 2, cc = (s & 3)*8;
            int sz = (q < Nn) ? 16 : 0;
            int qq = (q < Nn) ? q : 0;
            size_t off = abase + (size_t)qq*32 + cc;
            const bf16 *ph, *pl;
            if (seg == 0)      { ph = gX_h  + off; pl = gX_l  + off; }
            else if (seg == 1) { ph = gY1_h + off; pl = gY1_l + off; }
            else               { ph = gY2_h + off; pl = gY2_l + off; }
            unsigned d = r*208 + s*16;
            CPA(sb + P1_S(0) + d, ph, sz);
            CPA(sb + P1_S(1) + d, pl, sz);
        }
        loadW(0, 0);
        loadW(1, 1);

        const bf16* Sh = (const bf16*)(smem + P1_S(0));
        const bf16* Sl = (const bf16*)(smem + P1_S(1));

        float acc1[1][4][4];
        #pragma unroll
        for (int st = 0; st < 6; st++) {
            if (st < 5) cpa_wait<1>(); else cpa_wait<0>();
            __syncthreads();
            if (st < 4) loadW(st+2, (st+2)%3);
            int nt3 = st >> 1, half = st & 1;
            const bf16* Wh = (const bf16*)(smem + P1_W(st%3,0));
            const bf16* Wl = (const bf16*)(smem + P1_W(st%3,1));
            if (half == 0) {
                #pragma unroll
                for (int j = 0; j < 4; j++) for (int r = 0; r < 4; r++) acc1[0][j][r] = 0.f;
            }
            mma_stageG<1,3,104,SM_STRIDE>(acc1, Sh + half*48, Sl + half*48, Wh, Wl, p1m0, p1n0);
            if (half == 1) {
                #pragma unroll
                for (int nt = 0; nt < 4; nt++) {
                    int col = nt3*64 + p1n0 + nt*8 + tig*2;
                    #pragma unroll
                    for (int rh = 0; rh < 2; rh++) {
                        int row = q0 + p1m0 + g + rh*8;
                        if (row < Nn) {
                            float v0 = acc1[0][nt][rh*2+0], v1 = acc1[0][nt][rh*2+1];
                            bf16 h0 = __float2bfloat16(v0), h1 = __float2bfloat16(v1);
                            bf16 l0 = __float2bfloat16(v0 - __bfloat162float(h0));
                            bf16 l1 = __float2bfloat16(v1 - __bfloat162float(h1));
                            bf162 ph; ph.x = h0; ph.y = h1;
                            bf162 pl; pl.x = l0; pl.y = l1;
                            *(bf162*)(Ghp + row*GSTR + col) = ph;
                            *(bf162*)(Glp + row*GSTR + col) = pl;
                        }
                    }
                }
            }
        }
    }

    int mw = (warp >> 1)*16, nw = (warp & 1)*32;

    for (int jt = 0; jt < 4; jt++) {
        int j0 = jt*64;
        float acc[1][4][4];
        #pragma unroll
        for (int j = 0; j < 4; j++) for (int r = 0; r < 4; r++) acc[0][j][r] = 0.f;

        auto load_chunk = [&](int c, int st) {
            int phse = c >> 2, kq0 = (c & 3)*64;
            const bf16* Ahs = phse ? gR2_h : gRt_h;
            const bf16* Als = phse ? gR2_l : gRt_l;
            #pragma unroll
            for (int i = 0; i < 4; i++) {
                int u = tid + i*256;
                int hl = u >> 9, rem = u & 511;
                int r = rem >> 3, s = rem & 7;
                const bf16* src = (hl ? Als : Ahs) + (size_t)(j0 + r)*NP + kq0 + s*8;
                CPA(sb + P2_A(st,hl) + r*(SM_STRIDE*2) + s*16, src, 16);
            }
            CPA_COMMIT();
        };

        __syncthreads();
        load_chunk(0, 0);
        load_chunk(1, 1);
        #pragma unroll
        for (int c = 0; c < 8; c++) {
            if (c < 7) cpa_wait<1>(); else cpa_wait<0>();
            __syncthreads();
            if (c < 6) load_chunk(c+2, (c+2)%3);
            int phse = c >> 2, kc = c & 3;
            const bf16* Ah = (const bf16*)(smem + P2_A(c%3,0));
            const bf16* Al = (const bf16*)(smem + P2_A(c%3,1));
            int coff = phse ? 128 : 64;
            const bf16* Bh = Ghp + kc*64*GSTR + coff;
            const bf16* Bl = Glp + kc*64*GSTR + coff;
            if (kc == 3) mma_k8stage<1,SM_STRIDE,GSTR>(acc, Ah, Al, Bh, Bl, mw, nw);
            else         mma_stageG<1,4,SM_STRIDE,GSTR>(acc, Ah, Al, Bh, Bl, mw, nw);
        }

        #pragma unroll
        for (int nt = 0; nt < 4; nt++) {
            int o = nw + nt*8 + tig*2;
            #pragma unroll
            for (int rh = 0; rh < 2; rh++) {
                int j = j0 + mw + g + rh*8;
                if (j < Nn) {
                    float v0 = acc[0][nt][rh*2+0], v1 = acc[0][nt][rh*2+1];
                    int gr = j*GSTR;
                    float g0a = __bfloat162float(Ghp[gr + o])       + __bfloat162float(Glp[gr + o]);
                    float g0b = __bfloat162float(Ghp[gr + o + 1])   + __bfloat162float(Glp[gr + o + 1]);
                    float g2a = __bfloat162float(Ghp[gr + 128 + o]) + __bfloat162float(Glp[gr + 128 + o]);
                    float g2b = __bfloat162float(Ghp[gr + 128 + o + 1]) + __bfloat162float(Glp[gr + 128 + o + 1]);
                    size_t oi = ((size_t)bi*Nn + j)*64 + o;
                    out[oi]     = bias[o]     + g0a - g2a + v0;
                    out[oi + 1] = bias[o + 1] + g0b - g2b + v1;
                }
            }
        }
    }
}

// ---------------------------------------------------------------------------
extern "C" void kernel_launch(void* const* d_in, const int* in_sizes, int n_in,
                              void* d_out, int out_size) {
    const float* x    = (const float*)d_in[0];
    const float* adj  = (const float*)d_in[1];
    const float* w    = (const float*)d_in[2];
    const float* bias = (const float*)d_in[3];
    float* out = (float*)d_out;

    cudaFuncSetAttribute(k_leftfused, cudaFuncAttributeMaxDynamicSharedMemorySize, LEFT_SMEM);
    cudaFuncSetAttribute(k_fused,     cudaFuncAttributeMaxDynamicSharedMemorySize, FUSED_SMEM);

    k_deg<<<1, 256>>>(adj);
    k_buildA<<<(NP*NP + 255)/256, 256>>>(adj);
    k_R2<<<dim3(16, 16), dim3(16, 16)>>>();
    k_prepsplit<<<768 + 12800 + 96, 256>>>(x, w);

    k_leftfused<<<dim3(100, Bx), 256, LEFT_SMEM>>>();        // Y1 + Y2 in one pass
    k_fused<<<1600, 256, FUSED_SMEM>>>(bias, out);           // mix + right fused
}

// round 13
// speedup vs baseline: 2.5620x; 1.0360x over previous
#include <cuda_runtime.h>
#include <cuda_bf16.h>
#include <cstdint>

#define Nn   200
#define NP   256
#define Bx   8
#define NCH  6400
#define GW   192

typedef __nv_bfloat16 bf16;
typedef __nv_bfloat162 bf162;

// ---------------- static scratch ----------------
__device__ float g_d0[NP];
__device__ float g_d1[NP];
__device__ float g_Afp[NP*NP];
__device__ float g_Rtf[NP*NP];
__device__ float g_R2f[NP*NP];
__device__ bf16  gA_h[NP*NP],  gA_l[NP*NP];
__device__ bf16  gRt_h[NP*NP], gRt_l[NP*NP];
__device__ bf16  gR2_h[NP*NP], gR2_l[NP*NP];
__device__ bf16  gX_h[(size_t)Bx*NP*NCH],  gX_l[(size_t)Bx*NP*NCH];
__device__ bf16  gY1_h[(size_t)Bx*NP*NCH], gY1_l[(size_t)Bx*NP*NCH];
__device__ bf16  gY2_h[(size_t)Bx*NP*NCH], gY2_l[(size_t)Bx*NP*NCH];
__device__ bf16  gW_h[128*GW], gW_l[128*GW];            // [k=128][n=192]

// ---------------- prep kernels ----------------
__global__ void k_deg(const float* __restrict__ adj) {
    int i = threadIdx.x;
    if (i < Nn) {
        float cs = 0.f, rs = 0.f;
        for (int b = 0; b < Nn; b++) if (b != i) cs += adj[b*Nn + i];
        for (int e = 0; e < Nn; e++) if (e != i) rs += adj[i*Nn + e];
        g_d0[i] = (cs > 0.f) ? rsqrtf(cs) : 0.f;
        g_d1[i] = (rs > 0.f) ? rsqrtf(rs) : 0.f;
    }
}
__global__ void k_buildA(const float* __restrict__ adj) {
    int idx = blockIdx.x * blockDim.x + threadIdx.x;
    if (idx < NP*NP) {
        int e = idx / NP, b = idx % NP;
        float v = 0.f;
        if (e < Nn && b < Nn && e != b) v = g_d0[b] * adj[b*Nn + e] * g_d1[e];
        g_Afp[e*NP + b] = v;
        g_Rtf[b*NP + e] = v;
    }
}
__global__ void k_R2() {
    __shared__ float a[16][17], b[16][17];
    int tx = threadIdx.x, ty = threadIdx.y;
    int j = blockIdx.y*16 + ty, q = blockIdx.x*16 + tx;
    float s = 0.f;
    for (int p0 = 0; p0 < NP; p0 += 16) {
        a[ty][tx] = g_Rtf[j*NP + p0 + tx];
        b[ty][tx] = g_Rtf[(p0+ty)*NP + q];
        __syncthreads();
        #pragma unroll
        for (int p = 0; p < 16; p++) s += a[ty][p]*b[p][tx];
        __syncthreads();
    }
    g_R2f[j*NP + q] = 2.f*s;
}
static __device__ __forceinline__ unsigned pack2(float a, float b) {
    bf162 t; t.x = __float2bfloat16(a); t.y = __float2bfloat16(b);
    return *reinterpret_cast<unsigned*>(&t);
}
__global__ void k_prepsplit(const float* __restrict__ x, const float* __restrict__ w) {
    int b = blockIdx.x;
    int tid = threadIdx.x;
    if (b < 768) {
        int which = b / 256;
        const float* s; bf16 *h, *l;
        if (which == 0)      { s = g_Afp; h = gA_h;  l = gA_l;  }
        else if (which == 1) { s = g_Rtf; h = gRt_h; l = gRt_l; }
        else                 { s = g_R2f; h = gR2_h; l = gR2_l; }
        int i = (b % 256)*256 + tid;
        float v = s[i];
        bf16 hh = __float2bfloat16(v);
        h[i] = hh;
        l[i] = __float2bfloat16(v - __bfloat162float(hh));
    } else if (b < 768 + 12800) {
        size_t i4 = ((size_t)(b - 768)*256 + tid) * 4;
        int col = (int)(i4 % NCH);
        int r   = (int)((i4 / NCH) % NP);
        int bb  = (int)(i4 / ((size_t)NP*NCH));
        float v0 = 0.f, v1 = 0.f, v2 = 0.f, v3 = 0.f;
        if (r < Nn) {
            const float4 xv = *reinterpret_cast<const float4*>(x + ((size_t)bb*Nn + r)*NCH + col);
            v0 = xv.x; v1 = xv.y; v2 = xv.z; v3 = xv.w;
        }
        bf16 h0 = __float2bfloat16(v0), h1 = __float2bfloat16(v1);
        bf16 h2 = __float2bfloat16(v2), h3 = __float2bfloat16(v3);
        float l0 = v0 - __bfloat162float(h0), l1 = v1 - __bfloat162float(h1);
        float l2 = v2 - __bfloat162float(h2), l3 = v3 - __bfloat162float(h3);
        bf162 ph0; ph0.x = h0; ph0.y = h1;
        bf162 ph1; ph1.x = h2; ph1.y = h3;
        uint2 hv = make_uint2(*reinterpret_cast<unsigned*>(&ph0), *reinterpret_cast<unsigned*>(&ph1));
        uint2 lv = make_uint2(pack2(l0, l1), pack2(l2, l3));
        *reinterpret_cast<uint2*>(gX_h + i4) = hv;
        *reinterpret_cast<uint2*>(gX_l + i4) = lv;
    } else {
        int i = (b - 768 - 12800)*256 + tid;
        int k = i / GW, n = i % GW;
        float v = 0.f;
        if (k < 96) {
            int k1 = k / 32, c = k & 31;
            int k2 = n / 64, o = n & 63;
            v = w[o*288 + (k1*3 + k2)*32 + c];
        }
        bf16 hh = __float2bfloat16(v);
        gW_h[i] = hh;
        gW_l[i] = __float2bfloat16(v - __bfloat162float(hh));
    }
}

// ---------------- mma/async helpers ----------------
static __device__ __forceinline__ unsigned sptr(const void* p) {
    return (unsigned)__cvta_generic_to_shared(p);
}
static __device__ __forceinline__ void mma_bf16(float* c, const unsigned* a, const unsigned* b) {
    asm volatile("mma.sync.aligned.m16n8k16.row.col.f32.bf16.bf16.f32 "
        "{%0,%1,%2,%3},{%4,%5,%6,%7},{%8,%9},{%0,%1,%2,%3};\n"
        : "+f"(c[0]), "+f"(c[1]), "+f"(c[2]), "+f"(c[3])
        : "r"(a[0]), "r"(a[1]), "r"(a[2]), "r"(a[3]), "r"(b[0]), "r"(b[1]));
}
static __device__ __forceinline__ void mma_bf16_k8(float* c, const unsigned* a, unsigned b) {
    asm volatile("mma.sync.aligned.m16n8k8.row.col.f32.bf16.bf16.f32 "
        "{%0,%1,%2,%3},{%4,%5},{%6},{%0,%1,%2,%3};\n"
        : "+f"(c[0]), "+f"(c[1]), "+f"(c[2]), "+f"(c[3])
        : "r"(a[0]), "r"(a[1]), "r"(b));
}
#define LDB2(bq, addr) asm volatile( \
    "ldmatrix.sync.aligned.m8n8.x2.trans.shared.b16 {%0,%1},[%2];" \
    : "=r"((bq)[0]), "=r"((bq)[1]) : "r"(addr))
#define LDB1(b, addr) asm volatile( \
    "ldmatrix.sync.aligned.m8n8.x1.trans.shared.b16 {%0},[%1];" \
    : "=r"(b) : "r"(addr))
#define LDA4(aq, addr) asm volatile( \
    "ldmatrix.sync.aligned.m8n8.x4.shared.b16 {%0,%1,%2,%3},[%4];" \
    : "=r"((aq)[0]), "=r"((aq)[1]), "=r"((aq)[2]), "=r"((aq)[3]) : "r"(addr))
#define LDA2(aq, addr) asm volatile( \
    "ldmatrix.sync.aligned.m8n8.x2.shared.b16 {%0,%1},[%2];" \
    : "=r"((aq)[0]), "=r"((aq)[1]) : "r"(addr))

#define SM_STRIDE 72

#define CPA(dst, src, sz) asm volatile( \
    "cp.async.cg.shared.global [%0], [%1], 16, %2;" :: "r"(dst), "l"(src), "r"(sz))
#define CPA_COMMIT() asm volatile("cp.async.commit_group;")
template<int N>
static __device__ __forceinline__ void cpa_wait() {
    asm volatile("cp.async.wait_group %0;" :: "n"(N));
}

// MTx16(M) x 64(N) x KSN*16(K), 3-pass split; A via ldmatrix.x4
template<int MT, int KSN, int AS, int BS>
static __device__ __forceinline__ void mma_stageG(float (*acc)[4][4],
        const bf16* Ah, const bf16* Al, const bf16* Bh, const bf16* Bl,
        int wm0, int wn0) {
    int lane = threadIdx.x & 31;
    int arow = lane & 15;
    int acol = (lane >> 4) * 8;
    #pragma unroll
    for (int kk = 0; kk < KSN; kk++) {
        int kb = kk*16;
        unsigned aH[MT][4], aL[MT][4], bH[4][2], bL[4][2];
        #pragma unroll
        for (int mt = 0; mt < MT; mt++) {
            int r = wm0 + mt*16 + arow;
            LDA4(aH[mt], sptr(Ah + r*AS + kb + acol));
            LDA4(aL[mt], sptr(Al + r*AS + kb + acol));
        }
        int rr = kb + (lane & 15);
        #pragma unroll
        for (int nt = 0; nt < 4; nt++) {
            LDB2(bH[nt], sptr(Bh + rr*BS + wn0 + nt*8));
            LDB2(bL[nt], sptr(Bl + rr*BS + wn0 + nt*8));
        }
        #pragma unroll
        for (int mt = 0; mt < MT; mt++)
            #pragma unroll
            for (int nt = 0; nt < 4; nt++) {
                mma_bf16(acc[mt][nt], aH[mt], bH[nt]);
                mma_bf16(acc[mt][nt], aH[mt], bL[nt]);
                mma_bf16(acc[mt][nt], aL[mt], bH[nt]);
            }
    }
}

// single k8 step (3-pass)
template<int MT, int AS, int BS>
static __device__ __forceinline__ void mma_k8stage(float (*acc)[4][4],
        const bf16* Ah, const bf16* Al, const bf16* Bh, const bf16* Bl,
        int wm0, int wn0) {
    int lane = threadIdx.x & 31;
    int arow = lane & 15;
    unsigned aH[MT][2], aL[MT][2], bH[4], bL[4];
    #pragma unroll
    for (int mt = 0; mt < MT; mt++) {
        int r = wm0 + mt*16 + arow;
        LDA2(aH[mt], sptr(Ah + r*AS));
        LDA2(aL[mt], sptr(Al + r*AS));
    }
    int rr = lane & 7;
    #pragma unroll
    for (int nt = 0; nt < 4; nt++) {
        LDB1(bH[nt], sptr(Bh + rr*BS + wn0 + nt*8));
        LDB1(bL[nt], sptr(Bl + rr*BS + wn0 + nt*8));
    }
    #pragma unroll
    for (int mt = 0; mt < MT; mt++)
        #pragma unroll
        for (int nt = 0; nt < 4; nt++) {
            mma_bf16_k8(acc[mt][nt], aH[mt], bH[nt]);
            mma_bf16_k8(acc[mt][nt], aH[mt], bL[nt]);
            mma_bf16_k8(acc[mt][nt], aL[mt], bH[nt]);
        }
}

// ---------------- fused left: Y1 = A@X, Y2 = 2*A@Y1 - X (one kernel) --------
#define XB_H   0
#define XB_L   36864
#define Y1S_H  73728
#define Y1S_L  110592
#define LA(st,hl) (147456 + (st)*40960 + (hl)*20480)   // 256 x 32 bf16, stride 40
#define LEFT_SMEM 229376

__global__ __launch_bounds__(256) void k_leftfused() {
    extern __shared__ __align__(128) char smem[];
    unsigned sb = sptr(smem);
    int n0 = blockIdx.x*64, b = blockIdx.y;
    int tid = threadIdx.x;
    int lane = tid & 31, warp = tid >> 5;
    int g = lane >> 2, tig = lane & 3;
    int wm0 = (warp >> 1)*64, wn0 = (warp & 1)*32;

    const bf16* XBh = (const bf16*)(smem + XB_H);
    const bf16* XBl = (const bf16*)(smem + XB_L);
    bf16* Y1h = (bf16*)(smem + Y1S_H);
    bf16* Y1l = (bf16*)(smem + Y1S_L);

    auto loadA = [&](int c, int st) {
        int k0 = c*32;
        #pragma unroll
        for (int i = 0; i < 8; i++) {
            int u = tid + i*256;
            int hl = u >> 10, rem = u & 1023;
            int r = rem >> 2, s = rem & 3;
            const bf16* src = (hl ? gA_l : gA_h) + (size_t)r*NP + k0 + s*8;
            CPA(sb + LA(st,hl) + r*80 + s*16, src, 16);
        }
        CPA_COMMIT();
    };

    #pragma unroll
    for (int i = 0; i < 16; i++) {
        int u = tid + i*256;
        int hl = u >> 11, rem = u & 2047;
        int r = rem >> 3, s = rem & 7;
        const bf16* src = (hl ? gX_l : gX_h) + ((size_t)b*NP + r)*NCH + n0 + s*8;
        CPA(sb + (hl ? XB_L : XB_H) + r*144 + s*16, src, 16);
    }
    loadA(0, 0);

    float acc[4][4][4];
    #pragma unroll
    for (int i = 0; i < 4; i++) for (int j = 0; j < 4; j++) for (int r = 0; r < 4; r++) acc[i][j][r] = 0.f;

    #pragma unroll
    for (int c = 0; c < 7; c++) {
        cpa_wait<0>();
        __syncthreads();
        if (c < 6) loadA(c+1, (c+1)&1);
        const bf16* Ah = (const bf16*)(smem + LA(c&1,0));
        const bf16* Al = (const bf16*)(smem + LA(c&1,1));
        if (c == 6) mma_k8stage<4,40,SM_STRIDE>(acc, Ah, Al, XBh + 192*SM_STRIDE, XBl + 192*SM_STRIDE, wm0, wn0);
        else        mma_stageG<4,2,40,SM_STRIDE>(acc, Ah, Al, XBh + c*32*SM_STRIDE, XBl + c*32*SM_STRIDE, wm0, wn0);
    }

    __syncthreads();
    loadA(0, 0);

    #pragma unroll
    for (int mt = 0; mt < 4; mt++)
        #pragma unroll
        for (int nt = 0; nt < 4; nt++) {
            int col = wn0 + nt*8 + tig*2;
            #pragma unroll
            for (int rh = 0; rh < 2; rh++) {
                int row = wm0 + mt*16 + g + rh*8;
                float v0 = acc[mt][nt][rh*2+0], v1 = acc[mt][nt][rh*2+1];
                bf16 h0 = __float2bfloat16(v0), h1 = __float2bfloat16(v1);
                bf16 l0 = __float2bfloat16(v0 - __bfloat162float(h0));
                bf16 l1 = __float2bfloat16(v1 - __bfloat162float(h1));
                bf162 ph; ph.x = h0; ph.y = h1;
                bf162 pl; pl.x = l0; pl.y = l1;
                *(bf162*)(Y1h + row*SM_STRIDE + col) = ph;
                *(bf162*)(Y1l + row*SM_STRIDE + col) = pl;
                if (row < Nn) {
                    size_t di = ((size_t)b*NP + row)*NCH + n0 + col;
                    *(unsigned*)(gY1_h + di) = *reinterpret_cast<unsigned*>(&ph);
                    *(unsigned*)(gY1_l + di) = *reinterpret_cast<unsigned*>(&pl);
                }
            }
        }
    __syncthreads();

    #pragma unroll
    for (int i = 0; i < 4; i++) for (int j = 0; j < 4; j++) for (int r = 0; r < 4; r++) acc[i][j][r] = 0.f;

    #pragma unroll
    for (int c = 0; c < 7; c++) {
        cpa_wait<0>();
        __syncthreads();
        if (c < 6) loadA(c+1, (c+1)&1);
        const bf16* Ah = (const bf16*)(smem + LA(c&1,0));
        const bf16* Al = (const bf16*)(smem + LA(c&1,1));
        if (c == 6) mma_k8stage<4,40,SM_STRIDE>(acc, Ah, Al, Y1h + 192*SM_STRIDE, Y1l + 192*SM_STRIDE, wm0, wn0);
        else        mma_stageG<4,2,40,SM_STRIDE>(acc, Ah, Al, Y1h + c*32*SM_STRIDE, Y1l + c*32*SM_STRIDE, wm0, wn0);
    }

    #pragma unroll
    for (int mt = 0; mt < 4; mt++)
        #pragma unroll
        for (int nt = 0; nt < 4; nt++) {
            int col = wn0 + nt*8 + tig*2;
            #pragma unroll
            for (int rh = 0; rh < 2; rh++) {
                int row = wm0 + mt*16 + g + rh*8;
                if (row < Nn) {
                    int xo = row*SM_STRIDE + col;
                    float x0 = __bfloat162float(XBh[xo])   + __bfloat162float(XBl[xo]);
                    float x1 = __bfloat162float(XBh[xo+1]) + __bfloat162float(XBl[xo+1]);
                    float v0 = 2.f*acc[mt][nt][rh*2+0] - x0;
                    float v1 = 2.f*acc[mt][nt][rh*2+1] - x1;
                    bf16 h0 = __float2bfloat16(v0), h1 = __float2bfloat16(v1);
                    bf16 l0 = __float2bfloat16(v0 - __bfloat162float(h0));
                    bf16 l1 = __float2bfloat16(v1 - __bfloat162float(h1));
                    bf162 ph; ph.x = h0; ph.y = h1;
                    bf162 pl; pl.x = l0; pl.y = l1;
                    size_t di = ((size_t)b*NP + row)*NCH + n0 + col;
                    *(unsigned*)(gY2_h + di) = *reinterpret_cast<unsigned*>(&ph);
                    *(unsigned*)(gY2_l + di) = *reinterpret_cast<unsigned*>(&pl);
                }
            }
        }
}

// ---------------- fused mix+right, 256 threads ------------------------------
#define GSTR     200
#define OFF_GH   0
#define OFF_GL   80000
#define OFF_POOL 160000
#define P1_S(hl)     (OFF_POOL + (hl)*13312)                 // 64 x 104 bf16
#define P1_W(buf,hl) (OFF_POOL + 26624 + (buf)*13824 + (hl)*6912)  // 48 x 72 bf16
#define FUSED_SMEM   228096

__global__ __launch_bounds__(256) void k_fused(const float* __restrict__ bias,
                                               float* __restrict__ out) {
    extern __shared__ __align__(128) char smem[];
    unsigned sb = sptr(smem);
    int bi = blockIdx.x;
    int bb = bi / Nn, ii = bi % Nn;
    size_t abase = ((size_t)(bb*NP + ii))*NCH;
    int tid = threadIdx.x;
    int lane = tid & 31, warp = tid >> 5;
    int g = lane >> 2, tig = lane & 3;

    bf16* Ghp = (bf16*)(smem + OFF_GH);
    bf16* Glp = (bf16*)(smem + OFF_GL);

    auto loadW = [&](int st, int buf) {
        int nt3 = st >> 1, half = st & 1;
        #pragma unroll
        for (int i = 0; i < 3; i++) {
            int u = tid + i*256;
            int hl = u / 384, rem = u % 384;
            int r = rem >> 3, s = rem & 7;
            const bf16* wsrc = (hl ? gW_l : gW_h) + (size_t)(half*48 + r)*GW + nt3*64 + s*8;
            CPA(sb + P1_W(buf,hl) + r*144 + s*16, wsrc, 16);
        }
        CPA_COMMIT();
    };

    int p1m0 = (warp >> 1)*16, p1n0 = (warp & 1)*32;

    // ---- phase 1: build G in smem ----
    for (int qp = 0; qp < 4; qp++) {
        int q0 = qp*64;
        __syncthreads();
        #pragma unroll
        for (int i = 0; i < 3; i++) {
            int u = tid + i*256;
            int r = u / 12, s = u % 12;
            int q = q0 + r;
            int seg = s >> 2, cc = (s & 3)*8;
            int sz = (q < Nn) ? 16 : 0;
            int qq = (q < Nn) ? q : 0;
            size_t off = abase + (size_t)qq*32 + cc;
            const bf16 *ph, *pl;
            if (seg == 0)      { ph = gX_h  + off; pl = gX_l  + off; }
            else if (seg == 1) { ph = gY1_h + off; pl = gY1_l + off; }
            else               { ph = gY2_h + off; pl = gY2_l + off; }
            unsigned d = r*208 + s*16;
            CPA(sb + P1_S(0) + d, ph, sz);
            CPA(sb + P1_S(1) + d, pl, sz);
        }
        loadW(0, 0);
        loadW(1, 1);

        const bf16* Sh = (const bf16*)(smem + P1_S(0));
        const bf16* Sl = (const bf16*)(smem + P1_S(1));

        float acc1[1][4][4];
        #pragma unroll
        for (int st = 0; st < 6; st++) {
            if (st < 5) cpa_wait<1>(); else cpa_wait<0>();
            __syncthreads();
            if (st < 4) loadW(st+2, (st+2)%3);
            int nt3 = st >> 1, half = st & 1;
            const bf16* Wh = (const bf16*)(smem + P1_W(st%3,0));
            const bf16* Wl = (const bf16*)(smem + P1_W(st%3,1));
            if (half == 0) {
                #pragma unroll
                for (int j = 0; j < 4; j++) for (int r = 0; r < 4; r++) acc1[0][j][r] = 0.f;
            }
            mma_stageG<1,3,104,SM_STRIDE>(acc1, Sh + half*48, Sl + half*48, Wh, Wl, p1m0, p1n0);
            if (half == 1) {
                #pragma unroll
                for (int nt = 0; nt < 4; nt++) {
                    int col = nt3*64 + p1n0 + nt*8 + tig*2;
                    #pragma unroll
                    for (int rh = 0; rh < 2; rh++) {
                        int row = q0 + p1m0 + g + rh*8;
                        if (row < Nn) {
                            float v0 = acc1[0][nt][rh*2+0], v1 = acc1[0][nt][rh*2+1];
                            bf16 h0 = __float2bfloat16(v0), h1 = __float2bfloat16(v1);
                            bf16 l0 = __float2bfloat16(v0 - __bfloat162float(h0));
                            bf16 l1 = __float2bfloat16(v1 - __bfloat162float(h1));
                            bf162 ph; ph.x = h0; ph.y = h1;
                            bf162 pl; pl.x = l0; pl.y = l1;
                            *(bf162*)(Ghp + row*GSTR + col) = ph;
                            *(bf162*)(Glp + row*GSTR + col) = pl;
                        }
                    }
                }
            }
        }
    }

    __syncthreads();   // G complete; no block barriers below

    // ---- phase 2: warp-private A pipeline, 128-row j-tiles ----
    // per-warp smem: Ah stage0/1 (2304 B each), Al (2304 B)
    unsigned PA = sb + OFF_POOL + warp*6912;

    for (int jt = 0; jt < 2; jt++) {
        int jr = jt*128 + warp*16;
        float acc[8][4];
        #pragma unroll
        for (int j = 0; j < 8; j++) for (int r = 0; r < 4; r++) acc[j][r] = 0.f;

        auto issueA = [&](int c, int isL) {
            int phse = c >> 2, kc = c & 3;
            const bf16* src = isL ? (phse ? gR2_l : gRt_l) : (phse ? gR2_h : gRt_h);
            unsigned dst = PA + (isL ? 4608 : (c & 1)*2304);
            if (kc < 3) {
                int kq = kc*64;
                #pragma unroll
                for (int i = 0; i < 4; i++) {
                    int idx = lane + i*32, r = idx >> 3, s = idx & 7;
                    CPA(dst + r*144 + s*16, src + (size_t)(jr + r)*NP + kq + s*8, 16);
                }
            } else {
                if (lane < 16) CPA(dst + lane*144, src + (size_t)(jr + lane)*NP + 192, 16);
            }
            CPA_COMMIT();
        };

        issueA(0, 0); issueA(0, 1); issueA(1, 0);

        #pragma unroll
        for (int c = 0; c < 8; c++) {
            int phse = c >> 2, kc = c & 3;
            int coff = phse ? 128 : 64;
            const bf16* Ah = (const bf16*)(smem + OFF_POOL + warp*6912 + (c & 1)*2304);
            const bf16* Al = (const bf16*)(smem + OFF_POOL + warp*6912 + 4608);

            if (c == 7) cpa_wait<1>(); else cpa_wait<2>();
            __syncwarp();
            if (kc < 3) {
                #pragma unroll
                for (int ks = 0; ks < 4; ks++) {
                    unsigned a4[4];
                    LDA4(a4, sptr(Ah + (lane & 15)*72 + ks*16 + (lane >> 4)*8));
                    int rr = kc*64 + ks*16 + (lane & 15);
                    #pragma unroll
                    for (int nt = 0; nt < 8; nt++) {
                        unsigned bh[2], bl[2];
                        LDB2(bh, sptr(Ghp + rr*GSTR + coff + nt*8));
                        LDB2(bl, sptr(Glp + rr*GSTR + coff + nt*8));
                        mma_bf16(acc[nt], a4, bh);
                        mma_bf16(acc[nt], a4, bl);
                    }
                }
            } else {
                unsigned a2[2];
                LDA2(a2, sptr(Ah + (lane & 15)*72));
                int rr = 192 + (lane & 7);
                #pragma unroll
                for (int nt = 0; nt < 8; nt++) {
                    unsigned bh, bl;
                    LDB1(bh, sptr(Ghp + rr*GSTR + coff + nt*8));
                    LDB1(bl, sptr(Glp + rr*GSTR + coff + nt*8));
                    mma_bf16_k8(acc[nt], a2, bh);
                    mma_bf16_k8(acc[nt], a2, bl);
                }
            }

            if (c == 7) cpa_wait<0>(); else cpa_wait<1>();
            __syncwarp();
            if (kc < 3) {
                #pragma unroll
                for (int ks = 0; ks < 4; ks++) {
                    unsigned a4[4];
                    LDA4(a4, sptr(Al + (lane & 15)*72 + ks*16 + (lane >> 4)*8));
                    int rr = kc*64 + ks*16 + (lane & 15);
                    #pragma unroll
                    for (int nt = 0; nt < 8; nt++) {
                        unsigned bh[2];
                        LDB2(bh, sptr(Ghp + rr*GSTR + coff + nt*8));
                        mma_bf16(acc[nt], a4, bh);
                    }
                }
            } else {
                unsigned a2[2];
                LDA2(a2, sptr(Al + (lane & 15)*72));
                int rr = 192 + (lane & 7);
                #pragma unroll
                for (int nt = 0; nt < 8; nt++) {
                    unsigned bh;
                    LDB1(bh, sptr(Ghp + rr*GSTR + coff + nt*8));
                    mma_bf16_k8(acc[nt], a2, bh);
                }
            }
            if (c < 7) { issueA(c+1, 1); if (c < 6) issueA(c+2, 0); }
        }

        // epilogue: warp rows jr..jr+15
        #pragma unroll
        for (int nt = 0; nt < 8; nt++) {
            int o = nt*8 + tig*2;
            #pragma unroll
            for (int rh = 0; rh < 2; rh++) {
                int j = jr + g + rh*8;
                if (j < Nn) {
                    float v0 = acc[nt][rh*2+0], v1 = acc[nt][rh*2+1];
                    int gr = j*GSTR;
                    float g0a = __bfloat162float(Ghp[gr + o])       + __bfloat162float(Glp[gr + o]);
                    float g0b = __bfloat162float(Ghp[gr + o + 1])   + __bfloat162float(Glp[gr + o + 1]);
                    float g2a = __bfloat162float(Ghp[gr + 128 + o]) + __bfloat162float(Glp[gr + 128 + o]);
                    float g2b = __bfloat162float(Ghp[gr + 128 + o + 1]) + __bfloat162float(Glp[gr + 128 + o + 1]);
                    size_t oi = ((size_t)bi*Nn + j)*64 + o;
                    out[oi]     = bias[o]     + g0a - g2a + v0;
                    out[oi + 1] = bias[o + 1] + g0b - g2b + v1;
                }
            }
        }
    }
}

// ---------------------------------------------------------------------------
extern "C" void kernel_launch(void* const* d_in, const int* in_sizes, int n_in,
                              void* d_out, int out_size) {
    const float* x    = (const float*)d_in[0];
    const float* adj  = (const float*)d_in[1];
    const float* w    = (const float*)d_in[2];
    const float* bias = (const float*)d_in[3];
    float* out = (float*)d_out;

    cudaFuncSetAttribute(k_leftfused, cudaFuncAttributeMaxDynamicSharedMemorySize, LEFT_SMEM);
    cudaFuncSetAttribute(k_fused,     cudaFuncAttributeMaxDynamicSharedMemorySize, FUSED_SMEM);

    k_deg<<<1, 256>>>(adj);
    k_buildA<<<(NP*NP + 255)/256, 256>>>(adj);
    k_R2<<<dim3(16, 16), dim3(16, 16)>>>();
    k_prepsplit<<<768 + 12800 + 96, 256>>>(x, w);

    k_leftfused<<<dim3(100, Bx), 256, LEFT_SMEM>>>();
    k_fused<<<1600, 256, FUSED_SMEM>>>(bias, out);
}